// round 4
// baseline (speedup 1.0000x reference)
#include <cuda_runtime.h>
#include <cuda_bf16.h>
#include <cstdint>
#include <math.h>

// ---------------- problem constants ----------------
#define BATCH   8192
#define D0      1024
#define D1      768
#define DIB     1024
#define KCAT    2816        // D0 + D1 + DIB
#define DOUT    1536
#define H1C     512
#define H2C     100
#define NEXP    7

#define KA_BIG  (2*KCAT)    // A stored dedup'd: [ah | al]
#define KB_BIG  (2*KCAT)    // B stored dedup'd: [bh | bl]
#define NC_BIG  (KCAT/64)   // 44 chunks per segment
#define NCH_BIG (3*NC_BIG)  // 132 total chunks (3 terms)

// ---------------- device scratch (no allocations allowed) ----------------
__device__ __nv_bfloat16 g_A [(size_t)BATCH * KA_BIG];   // 92 MB
__device__ __nv_bfloat16 g_B [(size_t)DOUT  * KB_BIG];   // 17.3 MB  [n][k] K-major
__device__ __nv_bfloat16 g_A1[(size_t)BATCH * D0];       // 16.8 MB  plain bf16
__device__ __nv_bfloat16 g_B1[(size_t)H1C   * D0];       // 1 MB
__device__ float g_h1   [BATCH * H1C];
__device__ float g_h2   [BATCH * H2C];
__device__ float g_stats1[2 * H1C];
__device__ float g_stats2[2 * H2C];
__device__ float g_w    [BATCH * 3];
__device__ float g_bavg [3 * DOUT];

// ---------------- PTX helpers (base-target safe: sm_80+ ISA only) ------------
__device__ __forceinline__ uint32_t smem_u32(const void* p) {
    uint32_t a;
    asm("{ .reg .u64 t; cvta.to.shared.u64 t, %1; cvt.u32.u64 %0, t; }"
        : "=r"(a) : "l"(p));
    return a;
}
__device__ __forceinline__ void cp16(uint32_t saddr, const void* g) {
    asm volatile("cp.async.cg.shared.global [%0], [%1], 16;"
                 :: "r"(saddr), "l"(g));
}
__device__ __forceinline__ void ldsm4(uint32_t* r, uint32_t addr) {
    asm volatile("ldmatrix.sync.aligned.m8n8.x4.shared.b16 {%0,%1,%2,%3}, [%4];"
                 : "=r"(r[0]), "=r"(r[1]), "=r"(r[2]), "=r"(r[3]) : "r"(addr));
}
__device__ __forceinline__ void mma_bf16(float* c, const uint32_t* a,
                                         uint32_t b0, uint32_t b1) {
    asm volatile(
        "mma.sync.aligned.m16n8k16.row.col.f32.bf16.bf16.f32 "
        "{%0,%1,%2,%3}, {%4,%5,%6,%7}, {%8,%9}, {%0,%1,%2,%3};"
        : "+f"(c[0]), "+f"(c[1]), "+f"(c[2]), "+f"(c[3])
        : "r"(a[0]), "r"(a[1]), "r"(a[2]), "r"(a[3]), "r"(b0), "r"(b1));
}

// ---------------- HMMA bf16 GEMM: C[M,N] = A[M,KA] @ B[N,KB]^T ---------------
// CTA 128(M) x 256(N), BK=64, 4-stage cp.async pipeline, 8 warps 2(m)x4(n),
// warp tile 64x64, mma.sync.m16n8k16.
// Split-bf16 chunk remap: chunk c -> seg = c/ncseg, cc = c%ncseg;
//   A k-chunk = cc + (seg==1 ? ncseg : 0)   (seg1 uses al)
//   B k-chunk = cc + (seg==2 ? ncseg : 0)   (seg2 uses bl)
#define A_STG 16384
#define B_STG 32768
#define STAGE_BYTES (A_STG + B_STG)         // 48 KB
#define HM_SMEM     (4 * STAGE_BYTES)       // 192 KB

__global__ void __launch_bounds__(256, 1)
hmma_gemm_kernel(const __nv_bfloat16* __restrict__ A,
                 const __nv_bfloat16* __restrict__ B,
                 float* __restrict__ C,
                 int ldA, int ldB, int ldC, int nchunks, int ncseg) {
    extern __shared__ char smem[];
    const uint32_t sbase = smem_u32(smem);
    const int tid  = threadIdx.x;
    const int lane = tid & 31;
    const int wid  = tid >> 5;
    const int wm   = wid & 1;           // 0..1  (64-row m slice)
    const int wn   = wid >> 1;          // 0..3  (64-col n slice)
    const int bm   = blockIdx.y * 128;
    const int bn   = blockIdx.x * 256;

    // cp.async store slot (covers rows srow+32i)
    const int srow = tid >> 3;          // 0..31
    const int scol = tid & 7;           // 16B unit
    const uint32_t stoff = (uint32_t)srow * 128 +
                           (uint32_t)((scol ^ (srow & 7)) << 4);
    const __nv_bfloat16* gA0 = A + (size_t)(bm + srow) * ldA + scol * 8;
    const __nv_bfloat16* gB0 = B + (size_t)(bn + srow) * ldB + scol * 8;

    float acc[4][8][4];
    #pragma unroll
    for (int i = 0; i < 4; i++)
        #pragma unroll
        for (int j = 0; j < 8; j++)
            #pragma unroll
            for (int r = 0; r < 4; r++) acc[i][j][r] = 0.f;

    // ldmatrix lane geometry
    const int g  = lane >> 3;
    const int lr = lane & 7;
    const int rA  = wm * 64 + lr + (g & 1) * 8;
    const int chA = g >> 1;
    const int sA7 = rA & 7;
    const int rB  = wn * 64 + lr + (g >> 1) * 8;
    const int chB = g & 1;
    const int sB7 = rB & 7;

#define LOAD_STAGE(s, c_)                                                      \
    do {                                                                       \
        int cc_ = (c_);                                                        \
        int seg_ = cc_ / ncseg;                                                \
        int rem_ = cc_ - seg_ * ncseg;                                         \
        int ka_ = (rem_ + ((seg_ == 1) ? ncseg : 0)) * 64;                     \
        int kb_ = (rem_ + ((seg_ == 2) ? ncseg : 0)) * 64;                     \
        uint32_t dA = sbase + (s) * STAGE_BYTES + stoff;                       \
        const __nv_bfloat16* ga = gA0 + ka_;                                   \
        _Pragma("unroll")                                                      \
        for (int i = 0; i < 4; i++)                                            \
            cp16(dA + i * 4096, ga + (size_t)i * 32 * ldA);                    \
        uint32_t dB = sbase + (s) * STAGE_BYTES + A_STG + stoff;               \
        const __nv_bfloat16* gb = gB0 + kb_;                                   \
        _Pragma("unroll")                                                      \
        for (int i = 0; i < 8; i++)                                            \
            cp16(dB + i * 4096, gb + (size_t)i * 32 * ldB);                    \
        asm volatile("cp.async.commit_group;" ::: "memory");                   \
    } while (0)

    LOAD_STAGE(0, 0);
    LOAD_STAGE(1, 1);
    LOAD_STAGE(2, 2);

    for (int c = 0; c < nchunks; c++) {
        if (c + 3 < nchunks) {
            asm volatile("cp.async.wait_group 2;" ::: "memory");
        } else {
            asm volatile("cp.async.wait_group 0;" ::: "memory");
        }
        __syncthreads();
        if (c + 3 < nchunks)
            LOAD_STAGE((c + 3) & 3, c + 3);

        const uint32_t aB = sbase + (c & 3) * STAGE_BYTES;
        const uint32_t bB = aB + A_STG;
        #pragma unroll
        for (int ks = 0; ks < 4; ks++) {
            uint32_t a[4][4];
            #pragma unroll
            for (int mi = 0; mi < 4; mi++) {
                uint32_t addr = aB + (uint32_t)(rA + mi * 16) * 128 +
                                (uint32_t)(((2 * ks + chA) ^ sA7) << 4);
                ldsm4(a[mi], addr);
            }
            uint32_t b[4][4];
            #pragma unroll
            for (int ng = 0; ng < 4; ng++) {
                uint32_t addr = bB + (uint32_t)(rB + ng * 16) * 128 +
                                (uint32_t)(((2 * ks + chB) ^ sB7) << 4);
                ldsm4(b[ng], addr);
            }
            #pragma unroll
            for (int mi = 0; mi < 4; mi++)
                #pragma unroll
                for (int ni = 0; ni < 8; ni++)
                    mma_bf16(acc[mi][ni], a[mi],
                             b[ni >> 1][(ni & 1) * 2],
                             b[ni >> 1][(ni & 1) * 2 + 1]);
        }
        __syncthreads();
    }
#undef LOAD_STAGE

    // epilogue: write fp32 accumulators
    const int erow = lane >> 2;
    const int ecol = (lane & 3) * 2;
    #pragma unroll
    for (int mi = 0; mi < 4; mi++) {
        int row = bm + wm * 64 + mi * 16 + erow;
        #pragma unroll
        for (int ni = 0; ni < 8; ni++) {
            int col = bn + wn * 64 + ni * 8 + ecol;
            float2 v0 = make_float2(acc[mi][ni][0], acc[mi][ni][1]);
            float2 v1 = make_float2(acc[mi][ni][2], acc[mi][ni][3]);
            *reinterpret_cast<float2*>(C + (size_t)row * ldC + col) = v0;
            *reinterpret_cast<float2*>(C + (size_t)(row + 8) * ldC + col) = v1;
        }
    }
}

// ---------------- conversions: fp32 -> split bf16 (hi, lo) ----------------
__device__ __forceinline__ void split_bf16(float v, __nv_bfloat16& h, __nv_bfloat16& l) {
    h = __float2bfloat16(v);
    l = __float2bfloat16(v - __bfloat162float(h));
}
__device__ __forceinline__ void store4bf(__nv_bfloat16* p,
                                         __nv_bfloat16 a, __nv_bfloat16 b,
                                         __nv_bfloat16 c, __nv_bfloat16 d) {
    __nv_bfloat162 v0, v1;
    v0.x = a; v0.y = b; v1.x = c; v1.y = d;
    uint2 u;
    u.x = *reinterpret_cast<uint32_t*>(&v0);
    u.y = *reinterpret_cast<uint32_t*>(&v1);
    *reinterpret_cast<uint2*>(p) = u;
}

// A for big GEMM: rows scaled by router weight; layout [ah | al]
__global__ void convert_A_kernel(const float* __restrict__ x0,
                                 const float* __restrict__ x1,
                                 const float* __restrict__ xib) {
    const int K4 = KCAT / 4;   // 704
    const int total = BATCH * K4;
    for (int idx = blockIdx.x * blockDim.x + threadIdx.x; idx < total;
         idx += gridDim.x * blockDim.x) {
        int b = idx / K4;
        int c = (idx - b * K4) * 4;
        float w; float4 v;
        if (c < D0) {
            w = g_w[b * 3 + 0];
            v = *reinterpret_cast<const float4*>(x0 + (size_t)b * D0 + c);
        } else if (c < D0 + D1) {
            w = g_w[b * 3 + 1];
            v = *reinterpret_cast<const float4*>(x1 + (size_t)b * D1 + (c - D0));
        } else {
            w = g_w[b * 3 + 2];
            v = *reinterpret_cast<const float4*>(xib + (size_t)b * DIB + (c - D0 - D1));
        }
        v.x *= w; v.y *= w; v.z *= w; v.w *= w;
        __nv_bfloat16 h[4], l[4];
        split_bf16(v.x, h[0], l[0]); split_bf16(v.y, h[1], l[1]);
        split_bf16(v.z, h[2], l[2]); split_bf16(v.w, h[3], l[3]);
        __nv_bfloat16* p = g_A + (size_t)b * KA_BIG + c;
        store4bf(p,        h[0], h[1], h[2], h[3]);
        store4bf(p + KCAT, l[0], l[1], l[2], l[3]);
    }
}

// A1 for router GEMM1: plain bf16 of x0
__global__ void convert_A1_kernel(const float* __restrict__ x0) {
    const int total = BATCH * D0 / 4;
    for (int idx = blockIdx.x * blockDim.x + threadIdx.x; idx < total;
         idx += gridDim.x * blockDim.x) {
        float4 v = *reinterpret_cast<const float4*>(x0 + (size_t)idx * 4);
        __nv_bfloat16* p = g_A1 + (size_t)idx * 4;
        store4bf(p, __float2bfloat16(v.x), __float2bfloat16(v.y),
                    __float2bfloat16(v.z), __float2bfloat16(v.w));
    }
}

// B for big GEMM: average 7 experts, transpose to [n][k]; layout [bh | bl]
__global__ void convert_B_kernel(const float* __restrict__ pW0,
                                 const float* __restrict__ pW1,
                                 const float* __restrict__ pWib) {
    __shared__ float t[32][33];
    const int k0 = blockIdx.x * 32;
    const int n0 = blockIdx.y * 32;
    const int tx = threadIdx.x, ty = threadIdx.y;
    for (int kl = ty; kl < 32; kl += 8) {
        int k = k0 + kl;
        const float* src; int lr, ld;
        if (k < D0)            { src = pW0;  lr = k;            ld = D0;  }
        else if (k < D0 + D1)  { src = pW1;  lr = k - D0;       ld = D1;  }
        else                   { src = pWib; lr = k - D0 - D1;  ld = DIB; }
        const float* p = src + (size_t)lr * DOUT + n0 + tx;
        const size_t es = (size_t)ld * DOUT;
        float s = 0.f;
        #pragma unroll
        for (int e = 0; e < NEXP; e++) s += p[(size_t)e * es];
        t[kl][tx] = s * (1.0f / 7.0f);
    }
    __syncthreads();
    for (int nl = ty; nl < 32; nl += 8) {
        float v = t[tx][nl];
        __nv_bfloat16 h, l;
        split_bf16(v, h, l);
        size_t o = (size_t)(n0 + nl) * KB_BIG + k0 + tx;
        g_B[o]        = h;
        g_B[o + KCAT] = l;
    }
}

// B1 for router GEMM1: transpose rw1[1024,512] to [n][k], plain bf16
__global__ void convert_B1_kernel(const float* __restrict__ rw1) {
    __shared__ float t[32][33];
    const int k0 = blockIdx.x * 32;
    const int n0 = blockIdx.y * 32;
    const int tx = threadIdx.x, ty = threadIdx.y;
    for (int kl = ty; kl < 32; kl += 8)
        t[kl][tx] = rw1[(size_t)(k0 + kl) * H1C + n0 + tx];
    __syncthreads();
    for (int nl = ty; nl < 32; nl += 8)
        g_B1[(size_t)(n0 + nl) * D0 + k0 + tx] = __float2bfloat16(t[tx][nl]);
}

// ---------------- misc small kernels ----------------
__global__ void zero_stats_kernel() {
    int i = blockIdx.x * blockDim.x + threadIdx.x;
    if (i < 2 * H1C) g_stats1[i] = 0.0f;
    if (i < 2 * H2C) g_stats2[i] = 0.0f;
}

__global__ void avg_bias_kernel(const float* __restrict__ pb0,
                                const float* __restrict__ pb1,
                                const float* __restrict__ pbib) {
    int i = blockIdx.x * blockDim.x + threadIdx.x;
    if (i >= 3 * DOUT) return;
    int s = i / DOUT, n = i - s * DOUT;
    const float* pb = (s == 0) ? pb0 : (s == 1) ? pb1 : pbib;
    float a = 0.f;
    #pragma unroll
    for (int e = 0; e < NEXP; e++) a += pb[e * DOUT + n];
    g_bavg[i] = a * (1.0f / 7.0f);
}

// fp32 SGEMM kept for router layer 2 (N=100)
template<bool NGUARD>
__global__ void __launch_bounds__(256, 2)
sgemm_kernel(const float* __restrict__ A, const float* __restrict__ Bm,
             const float* __restrict__ bias, float* __restrict__ C,
             int M, int N, int K) {
    __shared__ float As[8][128];
    __shared__ float Bs[8][128];
    const int bm = blockIdx.y * 128;
    const int bn = blockIdx.x * 128;
    const int tid  = threadIdx.x;
    const int arow = tid >> 1;
    const int acol = (tid & 1) << 2;
    const int brow = tid >> 5;
    const int bcol = (tid & 31) << 2;
    const int tx = tid & 15;
    const int ty = tid >> 4;

    float acc[8][8];
    #pragma unroll
    for (int i = 0; i < 8; i++)
        #pragma unroll
        for (int j = 0; j < 8; j++) acc[i][j] = 0.f;

    for (int k0 = 0; k0 < K; k0 += 8) {
        float4 av = *reinterpret_cast<const float4*>(
            A + (size_t)(bm + arow) * K + k0 + acol);
        As[acol + 0][arow] = av.x;
        As[acol + 1][arow] = av.y;
        As[acol + 2][arow] = av.z;
        As[acol + 3][arow] = av.w;
        if (!NGUARD) {
            float4 bv = *reinterpret_cast<const float4*>(
                Bm + (size_t)(k0 + brow) * N + bn + bcol);
            *reinterpret_cast<float4*>(&Bs[brow][bcol]) = bv;
        } else {
            #pragma unroll
            for (int j = 0; j < 4; j++) {
                int n = bn + bcol + j;
                Bs[brow][bcol + j] = (n < N) ? Bm[(size_t)(k0 + brow) * N + n] : 0.f;
            }
        }
        __syncthreads();
        #pragma unroll
        for (int kk = 0; kk < 8; kk++) {
            float4 a0 = *reinterpret_cast<const float4*>(&As[kk][ty * 4]);
            float4 a1 = *reinterpret_cast<const float4*>(&As[kk][64 + ty * 4]);
            float4 b0 = *reinterpret_cast<const float4*>(&Bs[kk][tx * 4]);
            float4 b1 = *reinterpret_cast<const float4*>(&Bs[kk][64 + tx * 4]);
            float a[8] = {a0.x, a0.y, a0.z, a0.w, a1.x, a1.y, a1.z, a1.w};
            float b[8] = {b0.x, b0.y, b0.z, b0.w, b1.x, b1.y, b1.z, b1.w};
            #pragma unroll
            for (int i = 0; i < 8; i++)
                #pragma unroll
                for (int j = 0; j < 8; j++)
                    acc[i][j] = fmaf(a[i], b[j], acc[i][j]);
        }
        __syncthreads();
    }

    #pragma unroll
    for (int i = 0; i < 8; i++) {
        int m = bm + ((i < 4) ? (ty * 4 + i) : (64 + ty * 4 + (i - 4)));
        #pragma unroll
        for (int j = 0; j < 8; j++) {
            int n = bn + ((j < 4) ? (tx * 4 + j) : (64 + tx * 4 + (j - 4)));
            if (!NGUARD || n < N) {
                float v = acc[i][j];
                if (bias) v += bias[n];
                C[(size_t)m * N + n] = v;
            }
        }
    }
}

__global__ void col_stats_kernel(const float* __restrict__ H,
                                 float* __restrict__ stats, int Brows, int C) {
    int c = blockIdx.x * 32 + threadIdx.x;
    int chunk = (Brows + gridDim.y - 1) / gridDim.y;
    int r0 = blockIdx.y * chunk;
    int r1 = min(Brows, r0 + chunk);
    float s = 0.f, s2 = 0.f;
    if (c < C) {
        for (int r = r0 + threadIdx.y; r < r1; r += 8) {
            float v = H[(size_t)r * C + c];
            s += v;
            s2 = fmaf(v, v, s2);
        }
    }
    __shared__ float sh[8][2][32];
    sh[threadIdx.y][0][threadIdx.x] = s;
    sh[threadIdx.y][1][threadIdx.x] = s2;
    __syncthreads();
    if (threadIdx.y == 0 && c < C) {
        float ts = 0.f, ts2 = 0.f;
        #pragma unroll
        for (int y = 0; y < 8; y++) { ts += sh[y][0][threadIdx.x]; ts2 += sh[y][1][threadIdx.x]; }
        atomicAdd(&stats[c], ts);
        atomicAdd(&stats[C + c], ts2);
    }
}

__global__ void bn_relu_h1_kernel(const float* __restrict__ gamma,
                                  const float* __restrict__ beta) {
    const int total = BATCH * H1C;
    const float invB = 1.0f / (float)BATCH;
    for (int i = blockIdx.x * blockDim.x + threadIdx.x; i < total;
         i += gridDim.x * blockDim.x) {
        int c = i & (H1C - 1);
        float mean = g_stats1[c] * invB;
        float var  = g_stats1[H1C + c] * invB - mean * mean;
        float inv  = rsqrtf(var + 1e-5f);
        float v = g_h1[i];
        v = gamma[c] * (v - mean) * inv + beta[c];
        g_h1[i] = fmaxf(v, 0.f);
    }
}

__global__ void router_final_kernel(const float* __restrict__ rg2,
                                    const float* __restrict__ rbt2,
                                    const float* __restrict__ rw3,
                                    const float* __restrict__ rb3) {
    int warp = (blockIdx.x * blockDim.x + threadIdx.x) >> 5;
    int lane = threadIdx.x & 31;
    if (warp >= BATCH) return;
    const float invB = 1.0f / (float)BATCH;
    float d0 = 0.f, d1 = 0.f, d2 = 0.f;
    for (int c = lane; c < H2C; c += 32) {
        float mean = g_stats2[c] * invB;
        float var  = g_stats2[H2C + c] * invB - mean * mean;
        float v = g_h2[(size_t)warp * H2C + c];
        v = rg2[c] * (v - mean) * rsqrtf(var + 1e-5f) + rbt2[c];
        v = tanhf(v);
        d0 = fmaf(v, rw3[c * 3 + 0], d0);
        d1 = fmaf(v, rw3[c * 3 + 1], d1);
        d2 = fmaf(v, rw3[c * 3 + 2], d2);
    }
    #pragma unroll
    for (int o = 16; o > 0; o >>= 1) {
        d0 += __shfl_down_sync(0xffffffffu, d0, o);
        d1 += __shfl_down_sync(0xffffffffu, d1, o);
        d2 += __shfl_down_sync(0xffffffffu, d2, o);
    }
    if (lane == 0) {
        float l0 = 1.f / (1.f + __expf(-(d0 + rb3[0])));
        float l1 = 1.f / (1.f + __expf(-(d1 + rb3[1])));
        float l2 = 1.f / (1.f + __expf(-(d2 + rb3[2])));
        float mx = fmaxf(l0, fmaxf(l1, l2));
        float e0 = __expf(l0 - mx), e1 = __expf(l1 - mx), e2 = __expf(l2 - mx);
        float inv = 1.f / (e0 + e1 + e2);
        g_w[warp * 3 + 0] = e0 * inv;
        g_w[warp * 3 + 1] = e1 * inv;
        g_w[warp * 3 + 2] = e2 * inv;
    }
}

__global__ void normalize_rows_kernel(float* __restrict__ out) {
    int b = blockIdx.x;
    int t = threadIdx.x;
    float w0 = g_w[b * 3 + 0], w1 = g_w[b * 3 + 1], w2 = g_w[b * 3 + 2];
    float vals[6];
    float ss = 0.f;
    #pragma unroll
    for (int j = 0; j < 6; j++) {
        int n = t + j * 256;
        float v = out[(size_t)b * DOUT + n];
        v += w0 * g_bavg[n] + w1 * g_bavg[DOUT + n] + w2 * g_bavg[2 * DOUT + n];
        vals[j] = v;
        ss = fmaf(v, v, ss);
    }
    __shared__ float red[256];
    red[t] = ss;
    __syncthreads();
    #pragma unroll
    for (int s2 = 128; s2 > 0; s2 >>= 1) {
        if (t < s2) red[t] += red[t + s2];
        __syncthreads();
    }
    float inv = 1.f / fmaxf(sqrtf(red[0]), 1e-12f);
    #pragma unroll
    for (int j = 0; j < 6; j++)
        out[(size_t)b * DOUT + t + j * 256] = vals[j] * inv;
}

// ---------------- launch ----------------
extern "C" void kernel_launch(void* const* d_in, const int* in_sizes, int n_in,
                              void* d_out, int out_size) {
    const float* x0   = (const float*)d_in[0];
    const float* x1   = (const float*)d_in[1];
    const float* xib  = (const float*)d_in[2];
    const float* pW0  = (const float*)d_in[3];
    const float* pb0  = (const float*)d_in[4];
    const float* pW1  = (const float*)d_in[5];
    const float* pb1  = (const float*)d_in[6];
    const float* pWib = (const float*)d_in[7];
    const float* pbib = (const float*)d_in[8];
    const float* rw1  = (const float*)d_in[9];
    // rb1 (d_in[10]) cancels exactly under batch-norm — skipped
    const float* rg1  = (const float*)d_in[11];
    const float* rbt1 = (const float*)d_in[12];
    const float* rw2  = (const float*)d_in[13];
    const float* rb2  = (const float*)d_in[14];
    const float* rg2  = (const float*)d_in[15];
    const float* rbt2 = (const float*)d_in[16];
    const float* rw3  = (const float*)d_in[17];
    const float* rb3  = (const float*)d_in[18];
    float* out = (float*)d_out;
    (void)in_sizes; (void)n_in; (void)out_size;

    void *a_p, *b_p, *a1_p, *b1_p, *h1_p, *h2_p, *s1_p, *s2_p;
    cudaGetSymbolAddress(&a_p,  g_A);
    cudaGetSymbolAddress(&b_p,  g_B);
    cudaGetSymbolAddress(&a1_p, g_A1);
    cudaGetSymbolAddress(&b1_p, g_B1);
    cudaGetSymbolAddress(&h1_p, g_h1);
    cudaGetSymbolAddress(&h2_p, g_h2);
    cudaGetSymbolAddress(&s1_p, g_stats1);
    cudaGetSymbolAddress(&s2_p, g_stats2);
    const __nv_bfloat16* Ab  = (const __nv_bfloat16*)a_p;
    const __nv_bfloat16* Bb  = (const __nv_bfloat16*)b_p;
    const __nv_bfloat16* A1b = (const __nv_bfloat16*)a1_p;
    const __nv_bfloat16* B1b = (const __nv_bfloat16*)b1_p;
    float* h1  = (float*)h1_p;
    float* h2  = (float*)h2_p;
    float* st1 = (float*)s1_p;
    float* st2 = (float*)s2_p;

    cudaFuncSetAttribute(hmma_gemm_kernel,
                         cudaFuncAttributeMaxDynamicSharedMemorySize, HM_SMEM);

    zero_stats_kernel<<<4, 256>>>();
    avg_bias_kernel<<<(3 * DOUT + 255) / 256, 256>>>(pb0, pb1, pbib);

    // weight-side conversions (independent of router)
    convert_B_kernel <<<dim3(KCAT / 32, DOUT / 32), dim3(32, 8)>>>(pW0, pW1, pWib);
    convert_B1_kernel<<<dim3(D0 / 32, H1C / 32),   dim3(32, 8)>>>(rw1);
    convert_A1_kernel<<<4096, 256>>>(x0);

    // router layer 1 on HMMA (plain bf16): h1 = x0 @ rw1  (bias cancels in BN)
    hmma_gemm_kernel<<<dim3(H1C / 256, BATCH / 128), 256, HM_SMEM>>>(
        A1b, B1b, h1, D0, D0, H1C, D0 / 64, D0 / 64);
    col_stats_kernel<<<dim3(H1C / 32, 16), dim3(32, 8)>>>(h1, st1, BATCH, H1C);
    bn_relu_h1_kernel<<<4096, 256>>>(rg1, rbt1);

    // router layer 2 (small, fp32): h2 = h1 @ rw2 + rb2
    sgemm_kernel<true><<<dim3(1, BATCH / 128), 256>>>(
        h1, rw2, rb2, h2, BATCH, H2C, H1C);
    col_stats_kernel<<<dim3((H2C + 31) / 32, 16), dim3(32, 8)>>>(h2, st2, BATCH, H2C);
    router_final_kernel<<<BATCH * 32 / 256, 256>>>(rg2, rbt2, rw3, rb3);

    // big GEMM on HMMA, split-bf16 3-term with dedup'd operands
    convert_A_kernel<<<8192, 256>>>(x0, x1, xib);
    hmma_gemm_kernel<<<dim3(DOUT / 256, BATCH / 128), 256, HM_SMEM>>>(
        Ab, Bb, out, KA_BIG, KB_BIG, DOUT, NCH_BIG, NC_BIG);

    normalize_rows_kernel<<<BATCH, 256>>>(out);
}

// round 5
// speedup vs baseline: 1.1242x; 1.1242x over previous
#include <cuda_runtime.h>
#include <cuda_bf16.h>
#include <cuda_fp16.h>
#include <cstdint>
#include <math.h>

// ---------------- problem constants ----------------
#define BATCH   8192
#define D0      1024
#define D1      768
#define DIB     1024
#define KCAT    2816        // D0 + D1 + DIB
#define DOUT    1536
#define H1C     512
#define H2C     100
#define H2P     128         // padded N for layer-2 GEMM
#define NEXP    7

#define KA_BIG  (2*KCAT)    // A stored dedup'd: [ah | al]
#define KB_BIG  (2*KCAT)    // B stored dedup'd: [bh | bl]
#define NC_BIG  (KCAT/64)   // 44 chunks per segment
#define NCH_BIG (3*NC_BIG)  // 132 total chunks (3 split-bf16 terms)

// ---------------- device scratch (no allocations allowed) ----------------
__device__ __nv_bfloat16 g_A  [(size_t)BATCH * KA_BIG];  // 92 MB
__device__ __nv_bfloat16 g_B  [(size_t)DOUT  * KB_BIG];  // 17.3 MB  [n][k] K-major
__device__ __half        g_A1 [(size_t)BATCH * D0];      // 16.8 MB  fp16 x0
__device__ __half        g_B1 [(size_t)H1C   * D0];      // 1 MB     rw1^T fp16
__device__ __half        g_B2 [(size_t)H2P   * H1C];     // 128 KB   rw2^T fp16 (padded)
__device__ float  g_h1 [BATCH * H1C];
__device__ __half g_h1h[BATCH * H1C];
__device__ float  g_h2 [BATCH * H2P];
__device__ float  g_stats1[2 * H1C];
__device__ float  g_stats2[2 * H2C];
__device__ float  g_w   [BATCH * 3];
__device__ float  g_bavg[3 * DOUT];

// ---------------- PTX helpers (base-target safe: sm_80+ ISA only) ------------
__device__ __forceinline__ uint32_t smem_u32(const void* p) {
    uint32_t a;
    asm("{ .reg .u64 t; cvta.to.shared.u64 t, %1; cvt.u32.u64 %0, t; }"
        : "=r"(a) : "l"(p));
    return a;
}
__device__ __forceinline__ void cp16(uint32_t saddr, const void* g) {
    asm volatile("cp.async.cg.shared.global [%0], [%1], 16;"
                 :: "r"(saddr), "l"(g));
}
__device__ __forceinline__ void ldsm4(uint32_t* r, uint32_t addr) {
    asm volatile("ldmatrix.sync.aligned.m8n8.x4.shared.b16 {%0,%1,%2,%3}, [%4];"
                 : "=r"(r[0]), "=r"(r[1]), "=r"(r[2]), "=r"(r[3]) : "r"(addr));
}
template<bool F16>
__device__ __forceinline__ void mma_any(float* c, const uint32_t* a,
                                        uint32_t b0, uint32_t b1) {
    if (F16) {
        asm volatile(
            "mma.sync.aligned.m16n8k16.row.col.f32.f16.f16.f32 "
            "{%0,%1,%2,%3}, {%4,%5,%6,%7}, {%8,%9}, {%0,%1,%2,%3};"
            : "+f"(c[0]), "+f"(c[1]), "+f"(c[2]), "+f"(c[3])
            : "r"(a[0]), "r"(a[1]), "r"(a[2]), "r"(a[3]), "r"(b0), "r"(b1));
    } else {
        asm volatile(
            "mma.sync.aligned.m16n8k16.row.col.f32.bf16.bf16.f32 "
            "{%0,%1,%2,%3}, {%4,%5,%6,%7}, {%8,%9}, {%0,%1,%2,%3};"
            : "+f"(c[0]), "+f"(c[1]), "+f"(c[2]), "+f"(c[3])
            : "r"(a[0]), "r"(a[1]), "r"(a[2]), "r"(a[3]), "r"(b0), "r"(b1));
    }
}

// ---------------- HMMA 16-bit GEMM: C[M,N] = A[M,KA] @ B[N,KB]^T -------------
// CTA 128x128, BK=64, 3-stage cp.async pipeline (96 KB smem, 2 CTA/SM),
// 8 warps 2(m) x 4(n), warp tile 64x32, mma.sync.m16n8k16, one sync per chunk.
// Split chunk remap: chunk c -> seg = c/ncseg, cc = c%ncseg;
//   A k-chunk = cc + (seg==1 ? ncseg : 0)   (seg1 uses a_lo)
//   B k-chunk = cc + (seg==2 ? ncseg : 0)   (seg2 uses b_lo)
#define STAGE_BYTES 32768               // A 16KB + B 16KB
#define HM_SMEM     (3 * STAGE_BYTES)   // 98304

template<bool F16>
__global__ void __launch_bounds__(256, 2)
hmma_gemm_kernel(const uint16_t* __restrict__ A,
                 const uint16_t* __restrict__ B,
                 float* __restrict__ C,
                 int ldA, int ldB, int ldC, int nchunks, int ncseg) {
    extern __shared__ char smem[];
    const uint32_t sbase = smem_u32(smem);
    const int tid  = threadIdx.x;
    const int lane = tid & 31;
    const int wid  = tid >> 5;
    const int wm   = wid & 1;
    const int wn   = wid >> 1;
    const int bm   = blockIdx.y * 128;
    const int bn   = blockIdx.x * 128;

    const int srow = tid >> 3;          // 0..31
    const int scol = tid & 7;           // 16B unit
    const uint32_t stoff = (uint32_t)srow * 128 +
                           (uint32_t)((scol ^ (srow & 7)) << 4);
    const uint16_t* gA0 = A + (size_t)(bm + srow) * ldA + scol * 8;
    const uint16_t* gB0 = B + (size_t)(bn + srow) * ldB + scol * 8;

    float acc[4][4][4];
    #pragma unroll
    for (int i = 0; i < 4; i++)
        #pragma unroll
        for (int j = 0; j < 4; j++)
            #pragma unroll
            for (int r = 0; r < 4; r++) acc[i][j][r] = 0.f;

    const int g  = lane >> 3;
    const int lr = lane & 7;
    const int rA  = wm * 64 + lr + (g & 1) * 8;
    const int chA = g >> 1;
    const int sA7 = rA & 7;
    const int rB  = wn * 32 + lr + (g >> 1) * 8;
    const int chB = g & 1;
    const int sB7 = rB & 7;

#define LOAD_STAGE(s, c_)                                                      \
    do {                                                                       \
        int cc_ = (c_);                                                        \
        int seg_ = cc_ / ncseg;                                                \
        int rem_ = cc_ - seg_ * ncseg;                                         \
        int ka_ = (rem_ + ((seg_ == 1) ? ncseg : 0)) * 64;                     \
        int kb_ = (rem_ + ((seg_ == 2) ? ncseg : 0)) * 64;                     \
        uint32_t dA = sbase + (s) * STAGE_BYTES + stoff;                       \
        const uint16_t* ga = gA0 + ka_;                                        \
        _Pragma("unroll")                                                      \
        for (int i = 0; i < 4; i++)                                            \
            cp16(dA + i * 4096, ga + (size_t)i * 32 * ldA);                    \
        uint32_t dB = sbase + (s) * STAGE_BYTES + 16384 + stoff;               \
        const uint16_t* gb = gB0 + kb_;                                        \
        _Pragma("unroll")                                                      \
        for (int i = 0; i < 4; i++)                                            \
            cp16(dB + i * 4096, gb + (size_t)i * 32 * ldB);                    \
        asm volatile("cp.async.commit_group;" ::: "memory");                   \
    } while (0)

    LOAD_STAGE(0, 0);
    LOAD_STAGE(1, 1);

    for (int c = 0; c < nchunks; c++) {
        if (c + 2 < nchunks) {
            asm volatile("cp.async.wait_group 1;" ::: "memory");
        } else {
            asm volatile("cp.async.wait_group 0;" ::: "memory");
        }
        __syncthreads();
        if (c + 2 < nchunks) {
            int s2 = (c + 2) % 3;
            LOAD_STAGE(s2, c + 2);
        }

        const uint32_t aB = sbase + (c % 3) * STAGE_BYTES;
        const uint32_t bB = aB + 16384;
        #pragma unroll
        for (int ks = 0; ks < 4; ks++) {
            uint32_t a[4][4];
            #pragma unroll
            for (int mi = 0; mi < 4; mi++) {
                uint32_t addr = aB + (uint32_t)(rA + mi * 16) * 128 +
                                (uint32_t)(((2 * ks + chA) ^ sA7) << 4);
                ldsm4(a[mi], addr);
            }
            uint32_t b[2][4];
            #pragma unroll
            for (int ng = 0; ng < 2; ng++) {
                uint32_t addr = bB + (uint32_t)(rB + ng * 16) * 128 +
                                (uint32_t)(((2 * ks + chB) ^ sB7) << 4);
                ldsm4(b[ng], addr);
            }
            #pragma unroll
            for (int mi = 0; mi < 4; mi++)
                #pragma unroll
                for (int ni = 0; ni < 4; ni++)
                    mma_any<F16>(acc[mi][ni], a[mi],
                                 b[ni >> 1][(ni & 1) * 2],
                                 b[ni >> 1][(ni & 1) * 2 + 1]);
        }
        // no trailing sync: slot (c+2)%3 overwritten only after next-iter sync
    }
#undef LOAD_STAGE

    const int erow = lane >> 2;
    const int ecol = (lane & 3) * 2;
    #pragma unroll
    for (int mi = 0; mi < 4; mi++) {
        int row = bm + wm * 64 + mi * 16 + erow;
        #pragma unroll
        for (int ni = 0; ni < 4; ni++) {
            int col = bn + wn * 32 + ni * 8 + ecol;
            float2 v0 = make_float2(acc[mi][ni][0], acc[mi][ni][1]);
            float2 v1 = make_float2(acc[mi][ni][2], acc[mi][ni][3]);
            *reinterpret_cast<float2*>(C + (size_t)row * ldC + col) = v0;
            *reinterpret_cast<float2*>(C + (size_t)(row + 8) * ldC + col) = v1;
        }
    }
}

// ---------------- conversions ----------------
__device__ __forceinline__ void split_bf16(float v, __nv_bfloat16& h, __nv_bfloat16& l) {
    h = __float2bfloat16(v);
    l = __float2bfloat16(v - __bfloat162float(h));
}
__device__ __forceinline__ void store4bf(__nv_bfloat16* p,
                                         __nv_bfloat16 a, __nv_bfloat16 b,
                                         __nv_bfloat16 c, __nv_bfloat16 d) {
    __nv_bfloat162 v0, v1;
    v0.x = a; v0.y = b; v1.x = c; v1.y = d;
    uint2 u;
    u.x = *reinterpret_cast<uint32_t*>(&v0);
    u.y = *reinterpret_cast<uint32_t*>(&v1);
    *reinterpret_cast<uint2*>(p) = u;
}

// A for big GEMM: rows scaled by router weight; layout [ah | al]
__global__ void convert_A_kernel(const float* __restrict__ x0,
                                 const float* __restrict__ x1,
                                 const float* __restrict__ xib) {
    const int K4 = KCAT / 4;   // 704
    const int total = BATCH * K4;
    for (int idx = blockIdx.x * blockDim.x + threadIdx.x; idx < total;
         idx += gridDim.x * blockDim.x) {
        int b = idx / K4;
        int c = (idx - b * K4) * 4;
        float w; float4 v;
        if (c < D0) {
            w = g_w[b * 3 + 0];
            v = *reinterpret_cast<const float4*>(x0 + (size_t)b * D0 + c);
        } else if (c < D0 + D1) {
            w = g_w[b * 3 + 1];
            v = *reinterpret_cast<const float4*>(x1 + (size_t)b * D1 + (c - D0));
        } else {
            w = g_w[b * 3 + 2];
            v = *reinterpret_cast<const float4*>(xib + (size_t)b * DIB + (c - D0 - D1));
        }
        v.x *= w; v.y *= w; v.z *= w; v.w *= w;
        __nv_bfloat16 h[4], l[4];
        split_bf16(v.x, h[0], l[0]); split_bf16(v.y, h[1], l[1]);
        split_bf16(v.z, h[2], l[2]); split_bf16(v.w, h[3], l[3]);
        __nv_bfloat16* p = g_A + (size_t)b * KA_BIG + c;
        store4bf(p,        h[0], h[1], h[2], h[3]);
        store4bf(p + KCAT, l[0], l[1], l[2], l[3]);
    }
}

// A1 for router GEMM1: fp16 of x0
__global__ void convert_A1_kernel(const float* __restrict__ x0) {
    const int total = BATCH * D0 / 4;
    for (int idx = blockIdx.x * blockDim.x + threadIdx.x; idx < total;
         idx += gridDim.x * blockDim.x) {
        float4 v = *reinterpret_cast<const float4*>(x0 + (size_t)idx * 4);
        __half2 h0 = __floats2half2_rn(v.x, v.y);
        __half2 h1 = __floats2half2_rn(v.z, v.w);
        uint2 u;
        u.x = *reinterpret_cast<uint32_t*>(&h0);
        u.y = *reinterpret_cast<uint32_t*>(&h1);
        *reinterpret_cast<uint2*>(g_A1 + (size_t)idx * 4) = u;
    }
}

// B for big GEMM: average 7 experts, transpose to [n][k]; layout [bh | bl]
__global__ void convert_B_kernel(const float* __restrict__ pW0,
                                 const float* __restrict__ pW1,
                                 const float* __restrict__ pWib) {
    __shared__ float t[32][33];
    const int k0 = blockIdx.x * 32;
    const int n0 = blockIdx.y * 32;
    const int tx = threadIdx.x, ty = threadIdx.y;
    for (int kl = ty; kl < 32; kl += 8) {
        int k = k0 + kl;
        const float* src; int lr, ld;
        if (k < D0)            { src = pW0;  lr = k;            ld = D0;  }
        else if (k < D0 + D1)  { src = pW1;  lr = k - D0;       ld = D1;  }
        else                   { src = pWib; lr = k - D0 - D1;  ld = DIB; }
        const float* p = src + (size_t)lr * DOUT + n0 + tx;
        const size_t es = (size_t)ld * DOUT;
        float s = 0.f;
        #pragma unroll
        for (int e = 0; e < NEXP; e++) s += p[(size_t)e * es];
        t[kl][tx] = s * (1.0f / 7.0f);
    }
    __syncthreads();
    for (int nl = ty; nl < 32; nl += 8) {
        float v = t[tx][nl];
        __nv_bfloat16 h, l;
        split_bf16(v, h, l);
        size_t o = (size_t)(n0 + nl) * KB_BIG + k0 + tx;
        g_B[o]        = h;
        g_B[o + KCAT] = l;
    }
}

// B1: transpose rw1[1024,512] to [n][k], fp16
__global__ void convert_B1_kernel(const float* __restrict__ rw1) {
    __shared__ float t[32][33];
    const int k0 = blockIdx.x * 32;
    const int n0 = blockIdx.y * 32;
    const int tx = threadIdx.x, ty = threadIdx.y;
    for (int kl = ty; kl < 32; kl += 8)
        t[kl][tx] = rw1[(size_t)(k0 + kl) * H1C + n0 + tx];
    __syncthreads();
    for (int nl = ty; nl < 32; nl += 8)
        g_B1[(size_t)(n0 + nl) * D0 + k0 + tx] = __float2half(t[tx][nl]);
}

// B2: transpose rw2[512,100] to [n][k] fp16, padded to 128 rows (zeros)
__global__ void convert_B2_kernel(const float* __restrict__ rw2) {
    __shared__ float t[32][33];
    const int k0 = blockIdx.x * 32;
    const int n0 = blockIdx.y * 32;
    const int tx = threadIdx.x, ty = threadIdx.y;
    for (int kl = ty; kl < 32; kl += 8) {
        int n = n0 + tx;
        t[kl][tx] = (n < H2C) ? rw2[(size_t)(k0 + kl) * H2C + n] : 0.f;
    }
    __syncthreads();
    for (int nl = ty; nl < 32; nl += 8)
        g_B2[(size_t)(n0 + nl) * H1C + k0 + tx] = __float2half(t[tx][nl]);
}

// ---------------- misc small kernels ----------------
__global__ void zero_stats_kernel() {
    int i = blockIdx.x * blockDim.x + threadIdx.x;
    if (i < 2 * H1C) g_stats1[i] = 0.0f;
    if (i < 2 * H2C) g_stats2[i] = 0.0f;
}

__global__ void avg_bias_kernel(const float* __restrict__ pb0,
                                const float* __restrict__ pb1,
                                const float* __restrict__ pbib) {
    int i = blockIdx.x * blockDim.x + threadIdx.x;
    if (i >= 3 * DOUT) return;
    int s = i / DOUT, n = i - s * DOUT;
    const float* pb = (s == 0) ? pb0 : (s == 1) ? pb1 : pbib;
    float a = 0.f;
    #pragma unroll
    for (int e = 0; e < NEXP; e++) a += pb[e * DOUT + n];
    g_bavg[i] = a * (1.0f / 7.0f);
}

__global__ void col_stats_kernel(const float* __restrict__ H,
                                 float* __restrict__ stats,
                                 int Brows, int C, int ld) {
    int c = blockIdx.x * 32 + threadIdx.x;
    int chunk = (Brows + gridDim.y - 1) / gridDim.y;
    int r0 = blockIdx.y * chunk;
    int r1 = min(Brows, r0 + chunk);
    float s = 0.f, s2 = 0.f;
    if (c < C) {
        for (int r = r0 + threadIdx.y; r < r1; r += 8) {
            float v = H[(size_t)r * ld + c];
            s += v;
            s2 = fmaf(v, v, s2);
        }
    }
    __shared__ float sh[8][2][32];
    sh[threadIdx.y][0][threadIdx.x] = s;
    sh[threadIdx.y][1][threadIdx.x] = s2;
    __syncthreads();
    if (threadIdx.y == 0 && c < C) {
        float ts = 0.f, ts2 = 0.f;
        #pragma unroll
        for (int y = 0; y < 8; y++) { ts += sh[y][0][threadIdx.x]; ts2 += sh[y][1][threadIdx.x]; }
        atomicAdd(&stats[c], ts);
        atomicAdd(&stats[C + c], ts2);
    }
}

// BN + ReLU on h1 (fp32 in) -> fp16 out
__global__ void bn_relu_h1_kernel(const float* __restrict__ gamma,
                                  const float* __restrict__ beta) {
    const int total = BATCH * H1C;
    const float invB = 1.0f / (float)BATCH;
    for (int i = blockIdx.x * blockDim.x + threadIdx.x; i < total;
         i += gridDim.x * blockDim.x) {
        int c = i & (H1C - 1);
        float mean = g_stats1[c] * invB;
        float var  = g_stats1[H1C + c] * invB - mean * mean;
        float inv  = rsqrtf(var + 1e-5f);
        float v = g_h1[i];
        v = gamma[c] * (v - mean) * inv + beta[c];
        g_h1h[i] = __float2half(fmaxf(v, 0.f));
    }
}

__global__ void router_final_kernel(const float* __restrict__ rg2,
                                    const float* __restrict__ rbt2,
                                    const float* __restrict__ rw3,
                                    const float* __restrict__ rb3) {
    int warp = (blockIdx.x * blockDim.x + threadIdx.x) >> 5;
    int lane = threadIdx.x & 31;
    if (warp >= BATCH) return;
    const float invB = 1.0f / (float)BATCH;
    float d0 = 0.f, d1 = 0.f, d2 = 0.f;
    for (int c = lane; c < H2C; c += 32) {
        float mean = g_stats2[c] * invB;
        float var  = g_stats2[H2C + c] * invB - mean * mean;
        float v = g_h2[(size_t)warp * H2P + c];
        v = rg2[c] * (v - mean) * rsqrtf(var + 1e-5f) + rbt2[c];
        v = tanhf(v);
        d0 = fmaf(v, rw3[c * 3 + 0], d0);
        d1 = fmaf(v, rw3[c * 3 + 1], d1);
        d2 = fmaf(v, rw3[c * 3 + 2], d2);
    }
    #pragma unroll
    for (int o = 16; o > 0; o >>= 1) {
        d0 += __shfl_down_sync(0xffffffffu, d0, o);
        d1 += __shfl_down_sync(0xffffffffu, d1, o);
        d2 += __shfl_down_sync(0xffffffffu, d2, o);
    }
    if (lane == 0) {
        float l0 = 1.f / (1.f + __expf(-(d0 + rb3[0])));
        float l1 = 1.f / (1.f + __expf(-(d1 + rb3[1])));
        float l2 = 1.f / (1.f + __expf(-(d2 + rb3[2])));
        float mx = fmaxf(l0, fmaxf(l1, l2));
        float e0 = __expf(l0 - mx), e1 = __expf(l1 - mx), e2 = __expf(l2 - mx);
        float inv = 1.f / (e0 + e1 + e2);
        g_w[warp * 3 + 0] = e0 * inv;
        g_w[warp * 3 + 1] = e1 * inv;
        g_w[warp * 3 + 2] = e2 * inv;
    }
}

__global__ void normalize_rows_kernel(float* __restrict__ out) {
    int b = blockIdx.x;
    int t = threadIdx.x;
    float w0 = g_w[b * 3 + 0], w1 = g_w[b * 3 + 1], w2 = g_w[b * 3 + 2];
    float vals[6];
    float ss = 0.f;
    #pragma unroll
    for (int j = 0; j < 6; j++) {
        int n = t + j * 256;
        float v = out[(size_t)b * DOUT + n];
        v += w0 * g_bavg[n] + w1 * g_bavg[DOUT + n] + w2 * g_bavg[2 * DOUT + n];
        vals[j] = v;
        ss = fmaf(v, v, ss);
    }
    __shared__ float red[256];
    red[t] = ss;
    __syncthreads();
    #pragma unroll
    for (int s2 = 128; s2 > 0; s2 >>= 1) {
        if (t < s2) red[t] += red[t + s2];
        __syncthreads();
    }
    float inv = 1.f / fmaxf(sqrtf(red[0]), 1e-12f);
    #pragma unroll
    for (int j = 0; j < 6; j++)
        out[(size_t)b * DOUT + t + j * 256] = vals[j] * inv;
}

// ---------------- launch ----------------
extern "C" void kernel_launch(void* const* d_in, const int* in_sizes, int n_in,
                              void* d_out, int out_size) {
    const float* x0   = (const float*)d_in[0];
    const float* x1   = (const float*)d_in[1];
    const float* xib  = (const float*)d_in[2];
    const float* pW0  = (const float*)d_in[3];
    const float* pb0  = (const float*)d_in[4];
    const float* pW1  = (const float*)d_in[5];
    const float* pb1  = (const float*)d_in[6];
    const float* pWib = (const float*)d_in[7];
    const float* pbib = (const float*)d_in[8];
    const float* rw1  = (const float*)d_in[9];
    // rb1 (d_in[10]) cancels exactly under batch-norm — skipped
    const float* rg1  = (const float*)d_in[11];
    const float* rbt1 = (const float*)d_in[12];
    const float* rw2  = (const float*)d_in[13];
    // rb2 (d_in[14]) also cancels under batch-norm — skipped
    const float* rg2  = (const float*)d_in[15];
    const float* rbt2 = (const float*)d_in[16];
    const float* rw3  = (const float*)d_in[17];
    const float* rb3  = (const float*)d_in[18];
    float* out = (float*)d_out;
    (void)in_sizes; (void)n_in; (void)out_size;

    void *a_p, *b_p, *a1_p, *b1_p, *b2_p, *h1_p, *h1h_p, *h2_p, *s1_p, *s2_p;
    cudaGetSymbolAddress(&a_p,   g_A);
    cudaGetSymbolAddress(&b_p,   g_B);
    cudaGetSymbolAddress(&a1_p,  g_A1);
    cudaGetSymbolAddress(&b1_p,  g_B1);
    cudaGetSymbolAddress(&b2_p,  g_B2);
    cudaGetSymbolAddress(&h1_p,  g_h1);
    cudaGetSymbolAddress(&h1h_p, g_h1h);
    cudaGetSymbolAddress(&h2_p,  g_h2);
    cudaGetSymbolAddress(&s1_p,  g_stats1);
    cudaGetSymbolAddress(&s2_p,  g_stats2);
    const uint16_t* Ab  = (const uint16_t*)a_p;
    const uint16_t* Bb  = (const uint16_t*)b_p;
    const uint16_t* A1h = (const uint16_t*)a1_p;
    const uint16_t* B1h = (const uint16_t*)b1_p;
    const uint16_t* B2h = (const uint16_t*)b2_p;
    const uint16_t* H1h = (const uint16_t*)h1h_p;
    float* h1  = (float*)h1_p;
    float* h2  = (float*)h2_p;
    float* st1 = (float*)s1_p;
    float* st2 = (float*)s2_p;

    cudaFuncSetAttribute(hmma_gemm_kernel<true>,
                         cudaFuncAttributeMaxDynamicSharedMemorySize, HM_SMEM);
    cudaFuncSetAttribute(hmma_gemm_kernel<false>,
                         cudaFuncAttributeMaxDynamicSharedMemorySize, HM_SMEM);

    zero_stats_kernel<<<4, 256>>>();
    avg_bias_kernel<<<(3 * DOUT + 255) / 256, 256>>>(pb0, pb1, pbib);

    // weight-side conversions (independent of router)
    convert_B_kernel <<<dim3(KCAT / 32, DOUT / 32), dim3(32, 8)>>>(pW0, pW1, pWib);
    convert_B1_kernel<<<dim3(D0 / 32, H1C / 32),   dim3(32, 8)>>>(rw1);
    convert_B2_kernel<<<dim3(H1C / 32, H2P / 32),  dim3(32, 8)>>>(rw2);
    convert_A1_kernel<<<4096, 256>>>(x0);

    // router layer 1 (fp16 HMMA): h1 = x0 @ rw1
    hmma_gemm_kernel<true><<<dim3(H1C / 128, BATCH / 128), 256, HM_SMEM>>>(
        A1h, B1h, h1, D0, D0, H1C, D0 / 64, D0 / 64);
    col_stats_kernel<<<dim3(H1C / 32, 16), dim3(32, 8)>>>(h1, st1, BATCH, H1C, H1C);
    bn_relu_h1_kernel<<<4096, 256>>>(rg1, rbt1);

    // router layer 2 (fp16 HMMA, N padded to 128): h2 = relu(bn(h1)) @ rw2
    hmma_gemm_kernel<true><<<dim3(H2P / 128, BATCH / 128), 256, HM_SMEM>>>(
        H1h, B2h, h2, H1C, H1C, H2P, H1C / 64, H1C / 64);
    col_stats_kernel<<<dim3((H2C + 31) / 32, 16), dim3(32, 8)>>>(h2, st2, BATCH, H2C, H2P);
    router_final_kernel<<<BATCH * 32 / 256, 256>>>(rg2, rbt2, rw3, rb3);

    // big GEMM (bf16 3-term split, dedup'd operands)
    convert_A_kernel<<<8192, 256>>>(x0, x1, xib);
    hmma_gemm_kernel<false><<<dim3(DOUT / 128, BATCH / 128), 256, HM_SMEM>>>(
        Ab, Bb, out, KA_BIG, KB_BIG, DOUT, NCH_BIG, NC_BIG);

    normalize_rows_kernel<<<BATCH, 256>>>(out);
}

// round 6
// speedup vs baseline: 1.5258x; 1.3573x over previous
#include <cuda_runtime.h>
#include <cuda_bf16.h>
#include <cuda_fp16.h>
#include <cstdint>
#include <math.h>

// ---------------- problem constants ----------------
#define BATCH   8192
#define D0      1024
#define D1      768
#define DIB     1024
#define KCAT    2816        // D0 + D1 + DIB
#define DOUT    1536
#define H1C     512
#define H2C     100
#define H2P     128         // padded N for layer-2 GEMM
#define NEXP    7

#define KA_BIG  (2*KCAT)    // A stored split fp16: [ah | al]
#define NC_BIG  (KCAT/64)   // 44 chunks per segment
#define NCH_BIG (2*NC_BIG)  // 88 total chunks (2 fp16 terms: ah*bh + al*bh)

// ---------------- device scratch (no allocations allowed) ----------------
__device__ __half g_A  [(size_t)BATCH * KA_BIG];  // 92 MB   [b][ah|al]
__device__ __half g_B  [(size_t)DOUT  * KCAT];    // 8.7 MB  [n][k] K-major, fp16
__device__ __half g_A1 [(size_t)BATCH * D0];      // 16.8 MB fp16 x0
__device__ __half g_B1 [(size_t)H1C   * D0];      // 1 MB    rw1^T fp16
__device__ __half g_B2 [(size_t)H2P   * H1C];     // 128 KB  rw2^T fp16 (padded)
__device__ float  g_h1 [BATCH * H1C];
__device__ __half g_h1h[BATCH * H1C];
__device__ float  g_h2 [BATCH * H2P];
__device__ float  g_stats1[2 * H1C];
__device__ float  g_stats2[2 * H2C];
__device__ float  g_w   [BATCH * 3];
__device__ float  g_bavg[3 * DOUT];

// ---------------- PTX helpers (base-target safe: sm_80+ ISA only) ------------
__device__ __forceinline__ uint32_t smem_u32(const void* p) {
    uint32_t a;
    asm("{ .reg .u64 t; cvta.to.shared.u64 t, %1; cvt.u32.u64 %0, t; }"
        : "=r"(a) : "l"(p));
    return a;
}
__device__ __forceinline__ void cp16(uint32_t saddr, const void* g) {
    asm volatile("cp.async.cg.shared.global [%0], [%1], 16;"
                 :: "r"(saddr), "l"(g));
}
__device__ __forceinline__ void ldsm4(uint32_t* r, uint32_t addr) {
    asm volatile("ldmatrix.sync.aligned.m8n8.x4.shared.b16 {%0,%1,%2,%3}, [%4];"
                 : "=r"(r[0]), "=r"(r[1]), "=r"(r[2]), "=r"(r[3]) : "r"(addr));
}
__device__ __forceinline__ void mma_f16(float* c, const uint32_t* a,
                                        uint32_t b0, uint32_t b1) {
    asm volatile(
        "mma.sync.aligned.m16n8k16.row.col.f32.f16.f16.f32 "
        "{%0,%1,%2,%3}, {%4,%5,%6,%7}, {%8,%9}, {%0,%1,%2,%3};"
        : "+f"(c[0]), "+f"(c[1]), "+f"(c[2]), "+f"(c[3])
        : "r"(a[0]), "r"(a[1]), "r"(a[2]), "r"(a[3]), "r"(b0), "r"(b1));
}

// ---------------- HMMA fp16 GEMM: C[M,N] = A[M,KA] @ B[N,KB]^T ---------------
// CTA 128x128, BK=64, 3-stage cp.async pipeline (96 KB smem, 2 CTA/SM),
// 8 warps 2(m) x 4(n), warp tile 64x32, mma.sync.m16n8k16, one sync per chunk.
// Split chunk remap: chunk c -> seg = c/ncseg, cc = c%ncseg;
//   A k-chunk = cc + (seg==1 ? ncseg : 0)   -> contiguous over [ah|al]
//   B k-chunk = cc                          -> bh reused by both terms
#define STAGE_BYTES 32768               // A 16KB + B 16KB
#define HM_SMEM     (3 * STAGE_BYTES)   // 98304

__global__ void __launch_bounds__(256, 2)
hmma_gemm_kernel(const uint16_t* __restrict__ A,
                 const uint16_t* __restrict__ B,
                 float* __restrict__ C,
                 int ldA, int ldB, int ldC, int nchunks, int ncseg) {
    extern __shared__ char smem[];
    const uint32_t sbase = smem_u32(smem);
    const int tid  = threadIdx.x;
    const int lane = tid & 31;
    const int wid  = tid >> 5;
    const int wm   = wid & 1;
    const int wn   = wid >> 1;
    const int bm   = blockIdx.y * 128;
    const int bn   = blockIdx.x * 128;

    const int srow = tid >> 3;          // 0..31
    const int scol = tid & 7;           // 16B unit
    const uint32_t stoff = (uint32_t)srow * 128 +
                           (uint32_t)((scol ^ (srow & 7)) << 4);
    const uint16_t* gA0 = A + (size_t)(bm + srow) * ldA + scol * 8;
    const uint16_t* gB0 = B + (size_t)(bn + srow) * ldB + scol * 8;

    float acc[4][4][4];
    #pragma unroll
    for (int i = 0; i < 4; i++)
        #pragma unroll
        for (int j = 0; j < 4; j++)
            #pragma unroll
            for (int r = 0; r < 4; r++) acc[i][j][r] = 0.f;

    const int g  = lane >> 3;
    const int lr = lane & 7;
    const int rA  = wm * 64 + lr + (g & 1) * 8;
    const int chA = g >> 1;
    const int sA7 = rA & 7;
    const int rB  = wn * 32 + lr + (g >> 1) * 8;
    const int chB = g & 1;
    const int sB7 = rB & 7;

#define LOAD_STAGE(s, c_)                                                      \
    do {                                                                       \
        int cc_ = (c_);                                                        \
        int seg_ = cc_ / ncseg;                                                \
        int rem_ = cc_ - seg_ * ncseg;                                         \
        int ka_ = (rem_ + ((seg_ == 1) ? ncseg : 0)) * 64;                     \
        int kb_ = rem_ * 64;                                                   \
        uint32_t dA = sbase + (s) * STAGE_BYTES + stoff;                       \
        const uint16_t* ga = gA0 + ka_;                                        \
        _Pragma("unroll")                                                      \
        for (int i = 0; i < 4; i++)                                            \
            cp16(dA + i * 4096, ga + (size_t)i * 32 * ldA);                    \
        uint32_t dB = sbase + (s) * STAGE_BYTES + 16384 + stoff;               \
        const uint16_t* gb = gB0 + kb_;                                        \
        _Pragma("unroll")                                                      \
        for (int i = 0; i < 4; i++)                                            \
            cp16(dB + i * 4096, gb + (size_t)i * 32 * ldB);                    \
        asm volatile("cp.async.commit_group;" ::: "memory");                   \
    } while (0)

    LOAD_STAGE(0, 0);
    LOAD_STAGE(1, 1);

    for (int c = 0; c < nchunks; c++) {
        if (c + 2 < nchunks) {
            asm volatile("cp.async.wait_group 1;" ::: "memory");
        } else {
            asm volatile("cp.async.wait_group 0;" ::: "memory");
        }
        __syncthreads();
        if (c + 2 < nchunks) {
            int s2 = (c + 2) % 3;
            LOAD_STAGE(s2, c + 2);
        }

        const uint32_t aB = sbase + (c % 3) * STAGE_BYTES;
        const uint32_t bB = aB + 16384;
        #pragma unroll
        for (int ks = 0; ks < 4; ks++) {
            uint32_t a[4][4];
            #pragma unroll
            for (int mi = 0; mi < 4; mi++) {
                uint32_t addr = aB + (uint32_t)(rA + mi * 16) * 128 +
                                (uint32_t)(((2 * ks + chA) ^ sA7) << 4);
                ldsm4(a[mi], addr);
            }
            uint32_t b[2][4];
            #pragma unroll
            for (int ng = 0; ng < 2; ng++) {
                uint32_t addr = bB + (uint32_t)(rB + ng * 16) * 128 +
                                (uint32_t)(((2 * ks + chB) ^ sB7) << 4);
                ldsm4(b[ng], addr);
            }
            #pragma unroll
            for (int mi = 0; mi < 4; mi++)
                #pragma unroll
                for (int ni = 0; ni < 4; ni++)
                    mma_f16(acc[mi][ni], a[mi],
                            b[ni >> 1][(ni & 1) * 2],
                            b[ni >> 1][(ni & 1) * 2 + 1]);
        }
        // no trailing sync: slot (c+2)%3 overwritten only after next-iter sync
    }
#undef LOAD_STAGE

    const int erow = lane >> 2;
    const int ecol = (lane & 3) * 2;
    #pragma unroll
    for (int mi = 0; mi < 4; mi++) {
        int row = bm + wm * 64 + mi * 16 + erow;
        #pragma unroll
        for (int ni = 0; ni < 4; ni++) {
            int col = bn + wn * 32 + ni * 8 + ecol;
            float2 v0 = make_float2(acc[mi][ni][0], acc[mi][ni][1]);
            float2 v1 = make_float2(acc[mi][ni][2], acc[mi][ni][3]);
            *reinterpret_cast<float2*>(C + (size_t)row * ldC + col) = v0;
            *reinterpret_cast<float2*>(C + (size_t)(row + 8) * ldC + col) = v1;
        }
    }
}

// ---------------- conversions ----------------
__device__ __forceinline__ void split_f16(float v, __half& h, __half& l) {
    h = __float2half(v);
    l = __float2half(v - __half2float(h));
}
__device__ __forceinline__ void store4h(__half* p, __half a, __half b,
                                        __half c, __half d) {
    __half2 v0, v1;
    v0.x = a; v0.y = b; v1.x = c; v1.y = d;
    uint2 u;
    u.x = *reinterpret_cast<uint32_t*>(&v0);
    u.y = *reinterpret_cast<uint32_t*>(&v1);
    *reinterpret_cast<uint2*>(p) = u;
}

// A for big GEMM: rows scaled by router weight; layout [ah | al] fp16
__global__ void convert_A_kernel(const float* __restrict__ x0,
                                 const float* __restrict__ x1,
                                 const float* __restrict__ xib) {
    const int K4 = KCAT / 4;   // 704
    const int total = BATCH * K4;
    for (int idx = blockIdx.x * blockDim.x + threadIdx.x; idx < total;
         idx += gridDim.x * blockDim.x) {
        int b = idx / K4;
        int c = (idx - b * K4) * 4;
        float w; float4 v;
        if (c < D0) {
            w = g_w[b * 3 + 0];
            v = *reinterpret_cast<const float4*>(x0 + (size_t)b * D0 + c);
        } else if (c < D0 + D1) {
            w = g_w[b * 3 + 1];
            v = *reinterpret_cast<const float4*>(x1 + (size_t)b * D1 + (c - D0));
        } else {
            w = g_w[b * 3 + 2];
            v = *reinterpret_cast<const float4*>(xib + (size_t)b * DIB + (c - D0 - D1));
        }
        v.x *= w; v.y *= w; v.z *= w; v.w *= w;
        __half h[4], l[4];
        split_f16(v.x, h[0], l[0]); split_f16(v.y, h[1], l[1]);
        split_f16(v.z, h[2], l[2]); split_f16(v.w, h[3], l[3]);
        __half* p = g_A + (size_t)b * KA_BIG + c;
        store4h(p,        h[0], h[1], h[2], h[3]);
        store4h(p + KCAT, l[0], l[1], l[2], l[3]);
    }
}

// A1 for router GEMM1: fp16 of x0
__global__ void convert_A1_kernel(const float* __restrict__ x0) {
    const int total = BATCH * D0 / 4;
    for (int idx = blockIdx.x * blockDim.x + threadIdx.x; idx < total;
         idx += gridDim.x * blockDim.x) {
        float4 v = *reinterpret_cast<const float4*>(x0 + (size_t)idx * 4);
        __half2 h0 = __floats2half2_rn(v.x, v.y);
        __half2 h1 = __floats2half2_rn(v.z, v.w);
        uint2 u;
        u.x = *reinterpret_cast<uint32_t*>(&h0);
        u.y = *reinterpret_cast<uint32_t*>(&h1);
        *reinterpret_cast<uint2*>(g_A1 + (size_t)idx * 4) = u;
    }
}

// B for big GEMM: average 7 experts, transpose to [n][k], single fp16
__global__ void convert_B_kernel(const float* __restrict__ pW0,
                                 const float* __restrict__ pW1,
                                 const float* __restrict__ pWib) {
    __shared__ float t[32][33];
    const int k0 = blockIdx.x * 32;
    const int n0 = blockIdx.y * 32;
    const int tx = threadIdx.x, ty = threadIdx.y;
    for (int kl = ty; kl < 32; kl += 8) {
        int k = k0 + kl;
        const float* src; int lr, ld;
        if (k < D0)            { src = pW0;  lr = k;            ld = D0;  }
        else if (k < D0 + D1)  { src = pW1;  lr = k - D0;       ld = D1;  }
        else                   { src = pWib; lr = k - D0 - D1;  ld = DIB; }
        const float* p = src + (size_t)lr * DOUT + n0 + tx;
        const size_t es = (size_t)ld * DOUT;
        float s = 0.f;
        #pragma unroll
        for (int e = 0; e < NEXP; e++) s += p[(size_t)e * es];
        t[kl][tx] = s * (1.0f / 7.0f);
    }
    __syncthreads();
    for (int nl = ty; nl < 32; nl += 8)
        g_B[(size_t)(n0 + nl) * KCAT + k0 + tx] = __float2half(t[tx][nl]);
}

// B1: transpose rw1[1024,512] to [n][k], fp16
__global__ void convert_B1_kernel(const float* __restrict__ rw1) {
    __shared__ float t[32][33];
    const int k0 = blockIdx.x * 32;
    const int n0 = blockIdx.y * 32;
    const int tx = threadIdx.x, ty = threadIdx.y;
    for (int kl = ty; kl < 32; kl += 8)
        t[kl][tx] = rw1[(size_t)(k0 + kl) * H1C + n0 + tx];
    __syncthreads();
    for (int nl = ty; nl < 32; nl += 8)
        g_B1[(size_t)(n0 + nl) * D0 + k0 + tx] = __float2half(t[tx][nl]);
}

// B2: transpose rw2[512,100] to [n][k] fp16, padded to 128 rows (zeros)
__global__ void convert_B2_kernel(const float* __restrict__ rw2) {
    __shared__ float t[32][33];
    const int k0 = blockIdx.x * 32;
    const int n0 = blockIdx.y * 32;
    const int tx = threadIdx.x, ty = threadIdx.y;
    for (int kl = ty; kl < 32; kl += 8) {
        int n = n0 + tx;
        t[kl][tx] = (n < H2C) ? rw2[(size_t)(k0 + kl) * H2C + n] : 0.f;
    }
    __syncthreads();
    for (int nl = ty; nl < 32; nl += 8)
        g_B2[(size_t)(n0 + nl) * H1C + k0 + tx] = __float2half(t[tx][nl]);
}

// ---------------- misc small kernels ----------------
__global__ void zero_stats_kernel() {
    int i = blockIdx.x * blockDim.x + threadIdx.x;
    if (i < 2 * H1C) g_stats1[i] = 0.0f;
    if (i < 2 * H2C) g_stats2[i] = 0.0f;
}

__global__ void avg_bias_kernel(const float* __restrict__ pb0,
                                const float* __restrict__ pb1,
                                const float* __restrict__ pbib) {
    int i = blockIdx.x * blockDim.x + threadIdx.x;
    if (i >= 3 * DOUT) return;
    int s = i / DOUT, n = i - s * DOUT;
    const float* pb = (s == 0) ? pb0 : (s == 1) ? pb1 : pbib;
    float a = 0.f;
    #pragma unroll
    for (int e = 0; e < NEXP; e++) a += pb[e * DOUT + n];
    g_bavg[i] = a * (1.0f / 7.0f);
}

__global__ void col_stats_kernel(const float* __restrict__ H,
                                 float* __restrict__ stats,
                                 int Brows, int C, int ld) {
    int c = blockIdx.x * 32 + threadIdx.x;
    int chunk = (Brows + gridDim.y - 1) / gridDim.y;
    int r0 = blockIdx.y * chunk;
    int r1 = min(Brows, r0 + chunk);
    float s = 0.f, s2 = 0.f;
    if (c < C) {
        for (int r = r0 + threadIdx.y; r < r1; r += 8) {
            float v = H[(size_t)r * ld + c];
            s += v;
            s2 = fmaf(v, v, s2);
        }
    }
    __shared__ float sh[8][2][32];
    sh[threadIdx.y][0][threadIdx.x] = s;
    sh[threadIdx.y][1][threadIdx.x] = s2;
    __syncthreads();
    if (threadIdx.y == 0 && c < C) {
        float ts = 0.f, ts2 = 0.f;
        #pragma unroll
        for (int y = 0; y < 8; y++) { ts += sh[y][0][threadIdx.x]; ts2 += sh[y][1][threadIdx.x]; }
        atomicAdd(&stats[c], ts);
        atomicAdd(&stats[C + c], ts2);
    }
}

// BN + ReLU on h1 (fp32 in) -> fp16 out
__global__ void bn_relu_h1_kernel(const float* __restrict__ gamma,
                                  const float* __restrict__ beta) {
    const int total = BATCH * H1C;
    const float invB = 1.0f / (float)BATCH;
    for (int i = blockIdx.x * blockDim.x + threadIdx.x; i < total;
         i += gridDim.x * blockDim.x) {
        int c = i & (H1C - 1);
        float mean = g_stats1[c] * invB;
        float var  = g_stats1[H1C + c] * invB - mean * mean;
        float inv  = rsqrtf(var + 1e-5f);
        float v = g_h1[i];
        v = gamma[c] * (v - mean) * inv + beta[c];
        g_h1h[i] = __float2half(fmaxf(v, 0.f));
    }
}

__global__ void router_final_kernel(const float* __restrict__ rg2,
                                    const float* __restrict__ rbt2,
                                    const float* __restrict__ rw3,
                                    const float* __restrict__ rb3) {
    int warp = (blockIdx.x * blockDim.x + threadIdx.x) >> 5;
    int lane = threadIdx.x & 31;
    if (warp >= BATCH) return;
    const float invB = 1.0f / (float)BATCH;
    float d0 = 0.f, d1 = 0.f, d2 = 0.f;
    for (int c = lane; c < H2C; c += 32) {
        float mean = g_stats2[c] * invB;
        float var  = g_stats2[H2C + c] * invB - mean * mean;
        float v = g_h2[(size_t)warp * H2P + c];
        v = rg2[c] * (v - mean) * rsqrtf(var + 1e-5f) + rbt2[c];
        v = tanhf(v);
        d0 = fmaf(v, rw3[c * 3 + 0], d0);
        d1 = fmaf(v, rw3[c * 3 + 1], d1);
        d2 = fmaf(v, rw3[c * 3 + 2], d2);
    }
    #pragma unroll
    for (int o = 16; o > 0; o >>= 1) {
        d0 += __shfl_down_sync(0xffffffffu, d0, o);
        d1 += __shfl_down_sync(0xffffffffu, d1, o);
        d2 += __shfl_down_sync(0xffffffffu, d2, o);
    }
    if (lane == 0) {
        float l0 = 1.f / (1.f + __expf(-(d0 + rb3[0])));
        float l1 = 1.f / (1.f + __expf(-(d1 + rb3[1])));
        float l2 = 1.f / (1.f + __expf(-(d2 + rb3[2])));
        float mx = fmaxf(l0, fmaxf(l1, l2));
        float e0 = __expf(l0 - mx), e1 = __expf(l1 - mx), e2 = __expf(l2 - mx);
        float inv = 1.f / (e0 + e1 + e2);
        g_w[warp * 3 + 0] = e0 * inv;
        g_w[warp * 3 + 1] = e1 * inv;
        g_w[warp * 3 + 2] = e2 * inv;
    }
}

__global__ void normalize_rows_kernel(float* __restrict__ out) {
    int b = blockIdx.x;
    int t = threadIdx.x;
    float w0 = g_w[b * 3 + 0], w1 = g_w[b * 3 + 1], w2 = g_w[b * 3 + 2];
    float vals[6];
    float ss = 0.f;
    #pragma unroll
    for (int j = 0; j < 6; j++) {
        int n = t + j * 256;
        float v = out[(size_t)b * DOUT + n];
        v += w0 * g_bavg[n] + w1 * g_bavg[DOUT + n] + w2 * g_bavg[2 * DOUT + n];
        vals[j] = v;
        ss = fmaf(v, v, ss);
    }
    __shared__ float red[256];
    red[t] = ss;
    __syncthreads();
    #pragma unroll
    for (int s2 = 128; s2 > 0; s2 >>= 1) {
        if (t < s2) red[t] += red[t + s2];
        __syncthreads();
    }
    float inv = 1.f / fmaxf(sqrtf(red[0]), 1e-12f);
    #pragma unroll
    for (int j = 0; j < 6; j++)
        out[(size_t)b * DOUT + t + j * 256] = vals[j] * inv;
}

// ---------------- launch ----------------
extern "C" void kernel_launch(void* const* d_in, const int* in_sizes, int n_in,
                              void* d_out, int out_size) {
    const float* x0   = (const float*)d_in[0];
    const float* x1   = (const float*)d_in[1];
    const float* xib  = (const float*)d_in[2];
    const float* pW0  = (const float*)d_in[3];
    const float* pb0  = (const float*)d_in[4];
    const float* pW1  = (const float*)d_in[5];
    const float* pb1  = (const float*)d_in[6];
    const float* pWib = (const float*)d_in[7];
    const float* pbib = (const float*)d_in[8];
    const float* rw1  = (const float*)d_in[9];
    // rb1 (d_in[10]) cancels exactly under batch-norm — skipped
    const float* rg1  = (const float*)d_in[11];
    const float* rbt1 = (const float*)d_in[12];
    const float* rw2  = (const float*)d_in[13];
    // rb2 (d_in[14]) also cancels under batch-norm — skipped
    const float* rg2  = (const float*)d_in[15];
    const float* rbt2 = (const float*)d_in[16];
    const float* rw3  = (const float*)d_in[17];
    const float* rb3  = (const float*)d_in[18];
    float* out = (float*)d_out;
    (void)in_sizes; (void)n_in; (void)out_size;

    void *a_p, *b_p, *a1_p, *b1_p, *b2_p, *h1_p, *h1h_p, *h2_p, *s1_p, *s2_p;
    cudaGetSymbolAddress(&a_p,   g_A);
    cudaGetSymbolAddress(&b_p,   g_B);
    cudaGetSymbolAddress(&a1_p,  g_A1);
    cudaGetSymbolAddress(&b1_p,  g_B1);
    cudaGetSymbolAddress(&b2_p,  g_B2);
    cudaGetSymbolAddress(&h1_p,  g_h1);
    cudaGetSymbolAddress(&h1h_p, g_h1h);
    cudaGetSymbolAddress(&h2_p,  g_h2);
    cudaGetSymbolAddress(&s1_p,  g_stats1);
    cudaGetSymbolAddress(&s2_p,  g_stats2);
    const uint16_t* Ab  = (const uint16_t*)a_p;
    const uint16_t* Bb  = (const uint16_t*)b_p;
    const uint16_t* A1h = (const uint16_t*)a1_p;
    const uint16_t* B1h = (const uint16_t*)b1_p;
    const uint16_t* B2h = (const uint16_t*)b2_p;
    const uint16_t* H1h = (const uint16_t*)h1h_p;
    float* h1  = (float*)h1_p;
    float* h2  = (float*)h2_p;
    float* st1 = (float*)s1_p;
    float* st2 = (float*)s2_p;

    cudaFuncSetAttribute(hmma_gemm_kernel,
                         cudaFuncAttributeMaxDynamicSharedMemorySize, HM_SMEM);

    zero_stats_kernel<<<4, 256>>>();
    avg_bias_kernel<<<(3 * DOUT + 255) / 256, 256>>>(pb0, pb1, pbib);

    // weight-side conversions (independent of router)
    convert_B_kernel <<<dim3(KCAT / 32, DOUT / 32), dim3(32, 8)>>>(pW0, pW1, pWib);
    convert_B1_kernel<<<dim3(D0 / 32, H1C / 32),   dim3(32, 8)>>>(rw1);
    convert_B2_kernel<<<dim3(H1C / 32, H2P / 32),  dim3(32, 8)>>>(rw2);
    convert_A1_kernel<<<4096, 256>>>(x0);

    // router layer 1 (fp16 HMMA): h1 = x0 @ rw1
    hmma_gemm_kernel<<<dim3(H1C / 128, BATCH / 128), 256, HM_SMEM>>>(
        A1h, B1h, h1, D0, D0, H1C, D0 / 64, D0 / 64);
    col_stats_kernel<<<dim3(H1C / 32, 16), dim3(32, 8)>>>(h1, st1, BATCH, H1C, H1C);
    bn_relu_h1_kernel<<<4096, 256>>>(rg1, rbt1);

    // router layer 2 (fp16 HMMA, N padded to 128): h2 = relu(bn(h1)) @ rw2
    hmma_gemm_kernel<<<dim3(H2P / 128, BATCH / 128), 256, HM_SMEM>>>(
        H1h, B2h, h2, H1C, H1C, H2P, H1C / 64, H1C / 64);
    col_stats_kernel<<<dim3((H2C + 31) / 32, 16), dim3(32, 8)>>>(h2, st2, BATCH, H2C, H2P);
    router_final_kernel<<<BATCH * 32 / 256, 256>>>(rg2, rbt2, rw3, rb3);

    // big GEMM (fp16 2-term split: ah*bh + al*bh)
    convert_A_kernel<<<8192, 256>>>(x0, x1, xib);
    hmma_gemm_kernel<<<dim3(DOUT / 128, BATCH / 128), 256, HM_SMEM>>>(
        Ab, Bb, out, KA_BIG, KCAT, DOUT, NCH_BIG, NC_BIG);

    normalize_rows_kernel<<<BATCH, 256>>>(out);
}

// round 7
// speedup vs baseline: 2.3728x; 1.5551x over previous
#include <cuda_runtime.h>
#include <cuda_bf16.h>
#include <cuda_fp16.h>
#include <cstdint>
#include <math.h>

// ---------------- problem constants ----------------
#define BATCH   8192
#define D0      1024
#define D1      768
#define DIB     1024
#define KCAT    2816        // D0 + D1 + DIB
#define DOUT    1536
#define H1C     512
#define H2C     100
#define H2P     128         // padded N for layer-2 GEMM
#define NEXP    7

#define NC_BIG  (KCAT/64)   // 44 chunks

// ---------------- device scratch (no allocations allowed) ----------------
__device__ __half g_A  [(size_t)BATCH * KCAT];    // 46 MB   fp16 w-scaled concat
__device__ __half g_B  [(size_t)DOUT  * KCAT];    // 8.7 MB  [n][k] K-major, fp16
__device__ __half g_A1 [(size_t)BATCH * D0];      // 16.8 MB fp16 x0
__device__ __half g_B1 [(size_t)H1C   * D0];      // 1 MB    rw1^T fp16
__device__ __half g_B2 [(size_t)H2P   * H1C];     // 128 KB  rw2^T fp16 (padded)
__device__ float  g_h1 [BATCH * H1C];
__device__ __half g_h1h[BATCH * H1C];
__device__ float  g_h2 [BATCH * H2P];
__device__ float  g_stats1[2 * H1C];
__device__ float  g_stats2[2 * H2C];
__device__ float  g_w   [BATCH * 3];
__device__ float  g_bavg[3 * DOUT];

// ---------------- PTX helpers (base-target safe: sm_80+ ISA only) ------------
__device__ __forceinline__ uint32_t smem_u32(const void* p) {
    uint32_t a;
    asm("{ .reg .u64 t; cvta.to.shared.u64 t, %1; cvt.u32.u64 %0, t; }"
        : "=r"(a) : "l"(p));
    return a;
}
__device__ __forceinline__ void cp16(uint32_t saddr, const void* g) {
    asm volatile("cp.async.cg.shared.global [%0], [%1], 16;"
                 :: "r"(saddr), "l"(g));
}
__device__ __forceinline__ void ldsm4(uint32_t* r, uint32_t addr) {
    asm volatile("ldmatrix.sync.aligned.m8n8.x4.shared.b16 {%0,%1,%2,%3}, [%4];"
                 : "=r"(r[0]), "=r"(r[1]), "=r"(r[2]), "=r"(r[3]) : "r"(addr));
}
__device__ __forceinline__ void mma_f16(float* c, const uint32_t* a,
                                        uint32_t b0, uint32_t b1) {
    asm volatile(
        "mma.sync.aligned.m16n8k16.row.col.f32.f16.f16.f32 "
        "{%0,%1,%2,%3}, {%4,%5,%6,%7}, {%8,%9}, {%0,%1,%2,%3};"
        : "+f"(c[0]), "+f"(c[1]), "+f"(c[2]), "+f"(c[3])
        : "r"(a[0]), "r"(a[1]), "r"(a[2]), "r"(a[3]), "r"(b0), "r"(b1));
}

// ---------------- HMMA fp16 GEMM: C[M,N] = A[M,KA] @ B[N,KB]^T ---------------
// CTA 128x128, BK=64, 3-stage cp.async pipeline (96 KB smem, 2 CTA/SM),
// 8 warps 2(m) x 4(n), warp tile 64x32, mma.sync.m16n8k16, one sync per chunk.
// Optional split chunk remap (unused when nchunks == ncseg).
#define STAGE_BYTES 32768               // A 16KB + B 16KB
#define HM_SMEM     (3 * STAGE_BYTES)   // 98304

__global__ void __launch_bounds__(256, 2)
hmma_gemm_kernel(const uint16_t* __restrict__ A,
                 const uint16_t* __restrict__ B,
                 float* __restrict__ C,
                 int ldA, int ldB, int ldC, int nchunks, int ncseg) {
    extern __shared__ char smem[];
    const uint32_t sbase = smem_u32(smem);
    const int tid  = threadIdx.x;
    const int lane = tid & 31;
    const int wid  = tid >> 5;
    const int wm   = wid & 1;
    const int wn   = wid >> 1;
    const int bm   = blockIdx.y * 128;
    const int bn   = blockIdx.x * 128;

    const int srow = tid >> 3;          // 0..31
    const int scol = tid & 7;           // 16B unit
    const uint32_t stoff = (uint32_t)srow * 128 +
                           (uint32_t)((scol ^ (srow & 7)) << 4);
    const uint16_t* gA0 = A + (size_t)(bm + srow) * ldA + scol * 8;
    const uint16_t* gB0 = B + (size_t)(bn + srow) * ldB + scol * 8;

    float acc[4][4][4];
    #pragma unroll
    for (int i = 0; i < 4; i++)
        #pragma unroll
        for (int j = 0; j < 4; j++)
            #pragma unroll
            for (int r = 0; r < 4; r++) acc[i][j][r] = 0.f;

    const int g  = lane >> 3;
    const int lr = lane & 7;
    const int rA  = wm * 64 + lr + (g & 1) * 8;
    const int chA = g >> 1;
    const int sA7 = rA & 7;
    const int rB  = wn * 32 + lr + (g >> 1) * 8;
    const int chB = g & 1;
    const int sB7 = rB & 7;

#define LOAD_STAGE(s, c_)                                                      \
    do {                                                                       \
        int cc_ = (c_);                                                        \
        int seg_ = cc_ / ncseg;                                                \
        int rem_ = cc_ - seg_ * ncseg;                                         \
        int ka_ = (rem_ + ((seg_ == 1) ? ncseg : 0)) * 64;                     \
        int kb_ = rem_ * 64;                                                   \
        uint32_t dA = sbase + (s) * STAGE_BYTES + stoff;                       \
        const uint16_t* ga = gA0 + ka_;                                        \
        _Pragma("unroll")                                                      \
        for (int i = 0; i < 4; i++)                                            \
            cp16(dA + i * 4096, ga + (size_t)i * 32 * ldA);                    \
        uint32_t dB = sbase + (s) * STAGE_BYTES + 16384 + stoff;               \
        const uint16_t* gb = gB0 + kb_;                                        \
        _Pragma("unroll")                                                      \
        for (int i = 0; i < 4; i++)                                            \
            cp16(dB + i * 4096, gb + (size_t)i * 32 * ldB);                    \
        asm volatile("cp.async.commit_group;" ::: "memory");                   \
    } while (0)

    LOAD_STAGE(0, 0);
    LOAD_STAGE(1, 1);

    for (int c = 0; c < nchunks; c++) {
        if (c + 2 < nchunks) {
            asm volatile("cp.async.wait_group 1;" ::: "memory");
        } else {
            asm volatile("cp.async.wait_group 0;" ::: "memory");
        }
        __syncthreads();
        if (c + 2 < nchunks) {
            int s2 = (c + 2) % 3;
            LOAD_STAGE(s2, c + 2);
        }

        const uint32_t aB = sbase + (c % 3) * STAGE_BYTES;
        const uint32_t bB = aB + 16384;
        #pragma unroll
        for (int ks = 0; ks < 4; ks++) {
            uint32_t a[4][4];
            #pragma unroll
            for (int mi = 0; mi < 4; mi++) {
                uint32_t addr = aB + (uint32_t)(rA + mi * 16) * 128 +
                                (uint32_t)(((2 * ks + chA) ^ sA7) << 4);
                ldsm4(a[mi], addr);
            }
            uint32_t b[2][4];
            #pragma unroll
            for (int ng = 0; ng < 2; ng++) {
                uint32_t addr = bB + (uint32_t)(rB + ng * 16) * 128 +
                                (uint32_t)(((2 * ks + chB) ^ sB7) << 4);
                ldsm4(b[ng], addr);
            }
            #pragma unroll
            for (int mi = 0; mi < 4; mi++)
                #pragma unroll
                for (int ni = 0; ni < 4; ni++)
                    mma_f16(acc[mi][ni], a[mi],
                            b[ni >> 1][(ni & 1) * 2],
                            b[ni >> 1][(ni & 1) * 2 + 1]);
        }
        // no trailing sync: slot (c+2)%3 overwritten only after next-iter sync
    }
#undef LOAD_STAGE

    const int erow = lane >> 2;
    const int ecol = (lane & 3) * 2;
    #pragma unroll
    for (int mi = 0; mi < 4; mi++) {
        int row = bm + wm * 64 + mi * 16 + erow;
        #pragma unroll
        for (int ni = 0; ni < 4; ni++) {
            int col = bn + wn * 32 + ni * 8 + ecol;
            float2 v0 = make_float2(acc[mi][ni][0], acc[mi][ni][1]);
            float2 v1 = make_float2(acc[mi][ni][2], acc[mi][ni][3]);
            *reinterpret_cast<float2*>(C + (size_t)row * ldC + col) = v0;
            *reinterpret_cast<float2*>(C + (size_t)(row + 8) * ldC + col) = v1;
        }
    }
}

// ---------------- conversions ----------------
// A for big GEMM: rows scaled by router weight, plain fp16
__global__ void convert_A_kernel(const float* __restrict__ x0,
                                 const float* __restrict__ x1,
                                 const float* __restrict__ xib) {
    const int K4 = KCAT / 4;   // 704
    const int total = BATCH * K4;
    for (int idx = blockIdx.x * blockDim.x + threadIdx.x; idx < total;
         idx += gridDim.x * blockDim.x) {
        int b = idx / K4;
        int c = (idx - b * K4) * 4;
        float w; float4 v;
        if (c < D0) {
            w = g_w[b * 3 + 0];
            v = *reinterpret_cast<const float4*>(x0 + (size_t)b * D0 + c);
        } else if (c < D0 + D1) {
            w = g_w[b * 3 + 1];
            v = *reinterpret_cast<const float4*>(x1 + (size_t)b * D1 + (c - D0));
        } else {
            w = g_w[b * 3 + 2];
            v = *reinterpret_cast<const float4*>(xib + (size_t)b * DIB + (c - D0 - D1));
        }
        __half2 h0 = __floats2half2_rn(v.x * w, v.y * w);
        __half2 h1 = __floats2half2_rn(v.z * w, v.w * w);
        uint2 u;
        u.x = *reinterpret_cast<uint32_t*>(&h0);
        u.y = *reinterpret_cast<uint32_t*>(&h1);
        *reinterpret_cast<uint2*>(g_A + (size_t)b * KCAT + c) = u;
    }
}

// A1 for router GEMM1: fp16 of x0
__global__ void convert_A1_kernel(const float* __restrict__ x0) {
    const int total = BATCH * D0 / 4;
    for (int idx = blockIdx.x * blockDim.x + threadIdx.x; idx < total;
         idx += gridDim.x * blockDim.x) {
        float4 v = *reinterpret_cast<const float4*>(x0 + (size_t)idx * 4);
        __half2 h0 = __floats2half2_rn(v.x, v.y);
        __half2 h1 = __floats2half2_rn(v.z, v.w);
        uint2 u;
        u.x = *reinterpret_cast<uint32_t*>(&h0);
        u.y = *reinterpret_cast<uint32_t*>(&h1);
        *reinterpret_cast<uint2*>(g_A1 + (size_t)idx * 4) = u;
    }
}

// B for big GEMM: average 7 experts, transpose to [n][k], fp16
__global__ void convert_B_kernel(const float* __restrict__ pW0,
                                 const float* __restrict__ pW1,
                                 const float* __restrict__ pWib) {
    __shared__ float t[32][33];
    const int k0 = blockIdx.x * 32;
    const int n0 = blockIdx.y * 32;
    const int tx = threadIdx.x, ty = threadIdx.y;
    for (int kl = ty; kl < 32; kl += 8) {
        int k = k0 + kl;
        const float* src; int lr, ld;
        if (k < D0)            { src = pW0;  lr = k;            ld = D0;  }
        else if (k < D0 + D1)  { src = pW1;  lr = k - D0;       ld = D1;  }
        else                   { src = pWib; lr = k - D0 - D1;  ld = DIB; }
        const float* p = src + (size_t)lr * DOUT + n0 + tx;
        const size_t es = (size_t)ld * DOUT;
        float s = 0.f;
        #pragma unroll
        for (int e = 0; e < NEXP; e++) s += p[(size_t)e * es];
        t[kl][tx] = s * (1.0f / 7.0f);
    }
    __syncthreads();
    for (int nl = ty; nl < 32; nl += 8)
        g_B[(size_t)(n0 + nl) * KCAT + k0 + tx] = __float2half(t[tx][nl]);
}

// B1: transpose rw1[1024,512] to [n][k], fp16
__global__ void convert_B1_kernel(const float* __restrict__ rw1) {
    __shared__ float t[32][33];
    const int k0 = blockIdx.x * 32;
    const int n0 = blockIdx.y * 32;
    const int tx = threadIdx.x, ty = threadIdx.y;
    for (int kl = ty; kl < 32; kl += 8)
        t[kl][tx] = rw1[(size_t)(k0 + kl) * H1C + n0 + tx];
    __syncthreads();
    for (int nl = ty; nl < 32; nl += 8)
        g_B1[(size_t)(n0 + nl) * D0 + k0 + tx] = __float2half(t[tx][nl]);
}

// B2: transpose rw2[512,100] to [n][k] fp16, padded to 128 rows (zeros)
__global__ void convert_B2_kernel(const float* __restrict__ rw2) {
    __shared__ float t[32][33];
    const int k0 = blockIdx.x * 32;
    const int n0 = blockIdx.y * 32;
    const int tx = threadIdx.x, ty = threadIdx.y;
    for (int kl = ty; kl < 32; kl += 8) {
        int n = n0 + tx;
        t[kl][tx] = (n < H2C) ? rw2[(size_t)(k0 + kl) * H2C + n] : 0.f;
    }
    __syncthreads();
    for (int nl = ty; nl < 32; nl += 8)
        g_B2[(size_t)(n0 + nl) * H1C + k0 + tx] = __float2half(t[tx][nl]);
}

// ---------------- misc small kernels ----------------
__global__ void zero_stats_kernel() {
    int i = blockIdx.x * blockDim.x + threadIdx.x;
    if (i < 2 * H1C) g_stats1[i] = 0.0f;
    if (i < 2 * H2C) g_stats2[i] = 0.0f;
}

__global__ void avg_bias_kernel(const float* __restrict__ pb0,
                                const float* __restrict__ pb1,
                                const float* __restrict__ pbib) {
    int i = blockIdx.x * blockDim.x + threadIdx.x;
    if (i >= 3 * DOUT) return;
    int s = i / DOUT, n = i - s * DOUT;
    const float* pb = (s == 0) ? pb0 : (s == 1) ? pb1 : pbib;
    float a = 0.f;
    #pragma unroll
    for (int e = 0; e < NEXP; e++) a += pb[e * DOUT + n];
    g_bavg[i] = a * (1.0f / 7.0f);
}

__global__ void col_stats_kernel(const float* __restrict__ H,
                                 float* __restrict__ stats,
                                 int Brows, int C, int ld) {
    int c = blockIdx.x * 32 + threadIdx.x;
    int chunk = (Brows + gridDim.y - 1) / gridDim.y;
    int r0 = blockIdx.y * chunk;
    int r1 = min(Brows, r0 + chunk);
    float s = 0.f, s2 = 0.f;
    if (c < C) {
        for (int r = r0 + threadIdx.y; r < r1; r += 8) {
            float v = H[(size_t)r * ld + c];
            s += v;
            s2 = fmaf(v, v, s2);
        }
    }
    __shared__ float sh[8][2][32];
    sh[threadIdx.y][0][threadIdx.x] = s;
    sh[threadIdx.y][1][threadIdx.x] = s2;
    __syncthreads();
    if (threadIdx.y == 0 && c < C) {
        float ts = 0.f, ts2 = 0.f;
        #pragma unroll
        for (int y = 0; y < 8; y++) { ts += sh[y][0][threadIdx.x]; ts2 += sh[y][1][threadIdx.x]; }
        atomicAdd(&stats[c], ts);
        atomicAdd(&stats[C + c], ts2);
    }
}

// BN + ReLU on h1 (fp32 in) -> fp16 out
__global__ void bn_relu_h1_kernel(const float* __restrict__ gamma,
                                  const float* __restrict__ beta) {
    const int total = BATCH * H1C;
    const float invB = 1.0f / (float)BATCH;
    for (int i = blockIdx.x * blockDim.x + threadIdx.x; i < total;
         i += gridDim.x * blockDim.x) {
        int c = i & (H1C - 1);
        float mean = g_stats1[c] * invB;
        float var  = g_stats1[H1C + c] * invB - mean * mean;
        float inv  = rsqrtf(var + 1e-5f);
        float v = g_h1[i];
        v = gamma[c] * (v - mean) * inv + beta[c];
        g_h1h[i] = __float2half(fmaxf(v, 0.f));
    }
}

__global__ void router_final_kernel(const float* __restrict__ rg2,
                                    const float* __restrict__ rbt2,
                                    const float* __restrict__ rw3,
                                    const float* __restrict__ rb3) {
    int warp = (blockIdx.x * blockDim.x + threadIdx.x) >> 5;
    int lane = threadIdx.x & 31;
    if (warp >= BATCH) return;
    const float invB = 1.0f / (float)BATCH;
    float d0 = 0.f, d1 = 0.f, d2 = 0.f;
    for (int c = lane; c < H2C; c += 32) {
        float mean = g_stats2[c] * invB;
        float var  = g_stats2[H2C + c] * invB - mean * mean;
        float v = g_h2[(size_t)warp * H2P + c];
        v = rg2[c] * (v - mean) * rsqrtf(var + 1e-5f) + rbt2[c];
        v = tanhf(v);
        d0 = fmaf(v, rw3[c * 3 + 0], d0);
        d1 = fmaf(v, rw3[c * 3 + 1], d1);
        d2 = fmaf(v, rw3[c * 3 + 2], d2);
    }
    #pragma unroll
    for (int o = 16; o > 0; o >>= 1) {
        d0 += __shfl_down_sync(0xffffffffu, d0, o);
        d1 += __shfl_down_sync(0xffffffffu, d1, o);
        d2 += __shfl_down_sync(0xffffffffu, d2, o);
    }
    if (lane == 0) {
        float l0 = 1.f / (1.f + __expf(-(d0 + rb3[0])));
        float l1 = 1.f / (1.f + __expf(-(d1 + rb3[1])));
        float l2 = 1.f / (1.f + __expf(-(d2 + rb3[2])));
        float mx = fmaxf(l0, fmaxf(l1, l2));
        float e0 = __expf(l0 - mx), e1 = __expf(l1 - mx), e2 = __expf(l2 - mx);
        float inv = 1.f / (e0 + e1 + e2);
        g_w[warp * 3 + 0] = e0 * inv;
        g_w[warp * 3 + 1] = e1 * inv;
        g_w[warp * 3 + 2] = e2 * inv;
    }
}

__global__ void normalize_rows_kernel(float* __restrict__ out) {
    int b = blockIdx.x;
    int t = threadIdx.x;
    float w0 = g_w[b * 3 + 0], w1 = g_w[b * 3 + 1], w2 = g_w[b * 3 + 2];
    float vals[6];
    float ss = 0.f;
    #pragma unroll
    for (int j = 0; j < 6; j++) {
        int n = t + j * 256;
        float v = out[(size_t)b * DOUT + n];
        v += w0 * g_bavg[n] + w1 * g_bavg[DOUT + n] + w2 * g_bavg[2 * DOUT + n];
        vals[j] = v;
        ss = fmaf(v, v, ss);
    }
    __shared__ float red[256];
    red[t] = ss;
    __syncthreads();
    #pragma unroll
    for (int s2 = 128; s2 > 0; s2 >>= 1) {
        if (t < s2) red[t] += red[t + s2];
        __syncthreads();
    }
    float inv = 1.f / fmaxf(sqrtf(red[0]), 1e-12f);
    #pragma unroll
    for (int j = 0; j < 6; j++)
        out[(size_t)b * DOUT + t + j * 256] = vals[j] * inv;
}

// ---------------- launch ----------------
extern "C" void kernel_launch(void* const* d_in, const int* in_sizes, int n_in,
                              void* d_out, int out_size) {
    const float* x0   = (const float*)d_in[0];
    const float* x1   = (const float*)d_in[1];
    const float* xib  = (const float*)d_in[2];
    const float* pW0  = (const float*)d_in[3];
    const float* pb0  = (const float*)d_in[4];
    const float* pW1  = (const float*)d_in[5];
    const float* pb1  = (const float*)d_in[6];
    const float* pWib = (const float*)d_in[7];
    const float* pbib = (const float*)d_in[8];
    const float* rw1  = (const float*)d_in[9];
    // rb1 (d_in[10]) cancels exactly under batch-norm — skipped
    const float* rg1  = (const float*)d_in[11];
    const float* rbt1 = (const float*)d_in[12];
    const float* rw2  = (const float*)d_in[13];
    // rb2 (d_in[14]) also cancels under batch-norm — skipped
    const float* rg2  = (const float*)d_in[15];
    const float* rbt2 = (const float*)d_in[16];
    const float* rw3  = (const float*)d_in[17];
    const float* rb3  = (const float*)d_in[18];
    float* out = (float*)d_out;
    (void)in_sizes; (void)n_in; (void)out_size;

    void *a_p, *b_p, *a1_p, *b1_p, *b2_p, *h1_p, *h1h_p, *h2_p, *s1_p, *s2_p;
    cudaGetSymbolAddress(&a_p,   g_A);
    cudaGetSymbolAddress(&b_p,   g_B);
    cudaGetSymbolAddress(&a1_p,  g_A1);
    cudaGetSymbolAddress(&b1_p,  g_B1);
    cudaGetSymbolAddress(&b2_p,  g_B2);
    cudaGetSymbolAddress(&h1_p,  g_h1);
    cudaGetSymbolAddress(&h1h_p, g_h1h);
    cudaGetSymbolAddress(&h2_p,  g_h2);
    cudaGetSymbolAddress(&s1_p,  g_stats1);
    cudaGetSymbolAddress(&s2_p,  g_stats2);
    const uint16_t* Ab  = (const uint16_t*)a_p;
    const uint16_t* Bb  = (const uint16_t*)b_p;
    const uint16_t* A1h = (const uint16_t*)a1_p;
    const uint16_t* B1h = (const uint16_t*)b1_p;
    const uint16_t* B2h = (const uint16_t*)b2_p;
    const uint16_t* H1h = (const uint16_t*)h1h_p;
    float* h1  = (float*)h1_p;
    float* h2  = (float*)h2_p;
    float* st1 = (float*)s1_p;
    float* st2 = (float*)s2_p;

    cudaFuncSetAttribute(hmma_gemm_kernel,
                         cudaFuncAttributeMaxDynamicSharedMemorySize, HM_SMEM);

    zero_stats_kernel<<<4, 256>>>();
    avg_bias_kernel<<<(3 * DOUT + 255) / 256, 256>>>(pb0, pb1, pbib);

    // weight-side conversions (independent of router)
    convert_B_kernel <<<dim3(KCAT / 32, DOUT / 32), dim3(32, 8)>>>(pW0, pW1, pWib);
    convert_B1_kernel<<<dim3(D0 / 32, H1C / 32),   dim3(32, 8)>>>(rw1);
    convert_B2_kernel<<<dim3(H1C / 32, H2P / 32),  dim3(32, 8)>>>(rw2);
    convert_A1_kernel<<<4096, 256>>>(x0);

    // router layer 1 (fp16 HMMA): h1 = x0 @ rw1
    hmma_gemm_kernel<<<dim3(H1C / 128, BATCH / 128), 256, HM_SMEM>>>(
        A1h, B1h, h1, D0, D0, H1C, D0 / 64, D0 / 64);
    col_stats_kernel<<<dim3(H1C / 32, 16), dim3(32, 8)>>>(h1, st1, BATCH, H1C, H1C);
    bn_relu_h1_kernel<<<4096, 256>>>(rg1, rbt1);

    // router layer 2 (fp16 HMMA, N padded to 128): h2 = relu(bn(h1)) @ rw2
    hmma_gemm_kernel<<<dim3(H2P / 128, BATCH / 128), 256, HM_SMEM>>>(
        H1h, B2h, h2, H1C, H1C, H2P, H1C / 64, H1C / 64);
    col_stats_kernel<<<dim3((H2C + 31) / 32, 16), dim3(32, 8)>>>(h2, st2, BATCH, H2C, H2P);
    router_final_kernel<<<BATCH * 32 / 256, 256>>>(rg2, rbt2, rw3, rb3);

    // big GEMM (plain fp16, 1 term)
    convert_A_kernel<<<8192, 256>>>(x0, x1, xib);
    hmma_gemm_kernel<<<dim3(DOUT / 128, BATCH / 128), 256, HM_SMEM>>>(
        Ab, Bb, out, KCAT, KCAT, DOUT, NC_BIG, NC_BIG);

    normalize_rows_kernel<<<BATCH, 256>>>(out);
}

// round 8
// speedup vs baseline: 2.4223x; 1.0208x over previous
#include <cuda_runtime.h>
#include <cuda_bf16.h>
#include <cuda_fp16.h>
#include <cstdint>
#include <math.h>

// ---------------- problem constants ----------------
#define BATCH   8192
#define D0      1024
#define D1      768
#define DIB     1024
#define KCAT    2816        // D0 + D1 + DIB
#define DOUT    1536
#define H1C     512
#define H2C     100
#define H2P     128         // padded N for layer-2 GEMM
#define NEXP    7

#define NC_BIG  (KCAT/64)   // 44 chunks

// ---------------- device scratch (no allocations allowed) ----------------
__device__ __half g_A  [(size_t)BATCH * KCAT];    // 46 MB   fp16 w-scaled concat
__device__ __half g_B  [(size_t)DOUT  * KCAT];    // 8.7 MB  [n][k] K-major, fp16
__device__ __half g_A1 [(size_t)BATCH * D0];      // 16.8 MB fp16 x0
__device__ __half g_B1 [(size_t)H1C   * D0];      // 1 MB    rw1^T fp16
__device__ __half g_B2 [(size_t)H2P   * H1C];     // 128 KB  rw2^T fp16 (padded)
__device__ float  g_h1 [BATCH * H1C];
__device__ __half g_h1h[BATCH * H1C];
__device__ float  g_h2 [BATCH * H2P];
__device__ float  g_stats1[2 * H1C];
__device__ float  g_stats2[2 * H2C];
__device__ float  g_w   [BATCH * 3];
__device__ float  g_bavg[3 * DOUT];

// ---------------- PTX helpers (base-target safe: sm_80+ ISA only) ------------
__device__ __forceinline__ uint32_t smem_u32(const void* p) {
    uint32_t a;
    asm("{ .reg .u64 t; cvta.to.shared.u64 t, %1; cvt.u32.u64 %0, t; }"
        : "=r"(a) : "l"(p));
    return a;
}
__device__ __forceinline__ void cp16(uint32_t saddr, const void* g) {
    asm volatile("cp.async.cg.shared.global [%0], [%1], 16;"
                 :: "r"(saddr), "l"(g));
}
__device__ __forceinline__ void ldsm4(uint32_t* r, uint32_t addr) {
    asm volatile("ldmatrix.sync.aligned.m8n8.x4.shared.b16 {%0,%1,%2,%3}, [%4];"
                 : "=r"(r[0]), "=r"(r[1]), "=r"(r[2]), "=r"(r[3]) : "r"(addr));
}
__device__ __forceinline__ void mma_f16(float* c, const uint32_t* a,
                                        uint32_t b0, uint32_t b1) {
    asm volatile(
        "mma.sync.aligned.m16n8k16.row.col.f32.f16.f16.f32 "
        "{%0,%1,%2,%3}, {%4,%5,%6,%7}, {%8,%9}, {%0,%1,%2,%3};"
        : "+f"(c[0]), "+f"(c[1]), "+f"(c[2]), "+f"(c[3])
        : "r"(a[0]), "r"(a[1]), "r"(a[2]), "r"(a[3]), "r"(b0), "r"(b1));
}

// ---------------- HMMA fp16 GEMM: C[M,N] = A[M,KA] @ B[N,KB]^T ---------------
// CTA 128x128, BK=64, 3-stage cp.async pipeline (96 KB smem, 2 CTA/SM),
// 4 warps in 2(m) x 2(n), warp tile 64x64 (acc 128 regs; 256-reg budget at
// 128 thr x 2 CTA), mma.sync.m16n8k16. LDSM traffic per mma: 0.125 KB
// (vs 0.1875 at 64x32) — attacks the smem-crossbar bound.
#define STAGE_BYTES 32768               // A 16KB + B 16KB
#define HM_SMEM     (3 * STAGE_BYTES)   // 98304

__global__ void __launch_bounds__(128, 2)
hmma_gemm_kernel(const uint16_t* __restrict__ A,
                 const uint16_t* __restrict__ B,
                 float* __restrict__ C,
                 int ldA, int ldB, int ldC, int nchunks, int ncseg) {
    extern __shared__ char smem[];
    const uint32_t sbase = smem_u32(smem);
    const int tid  = threadIdx.x;
    const int lane = tid & 31;
    const int wid  = tid >> 5;          // 0..3
    const int wm   = wid & 1;           // m half
    const int wn   = wid >> 1;          // n half
    const int bm   = blockIdx.y * 128;
    const int bn   = blockIdx.x * 128;

    const int srow = tid >> 3;          // 0..15
    const int scol = tid & 7;           // 16B unit
    const uint32_t stoff = (uint32_t)srow * 128 +
                           (uint32_t)((scol ^ (srow & 7)) << 4);
    const uint16_t* gA0 = A + (size_t)(bm + srow) * ldA + scol * 8;
    const uint16_t* gB0 = B + (size_t)(bn + srow) * ldB + scol * 8;

    float acc[4][8][4];
    #pragma unroll
    for (int i = 0; i < 4; i++)
        #pragma unroll
        for (int j = 0; j < 8; j++)
            #pragma unroll
            for (int r = 0; r < 4; r++) acc[i][j][r] = 0.f;

    const int g  = lane >> 3;
    const int lr = lane & 7;
    const int rA  = wm * 64 + lr + (g & 1) * 8;
    const int chA = g >> 1;
    const int sA7 = rA & 7;
    const int rB  = wn * 64 + lr + (g >> 1) * 8;
    const int chB = g & 1;
    const int sB7 = rB & 7;

#define LOAD_STAGE(s, c_)                                                      \
    do {                                                                       \
        int cc_ = (c_);                                                        \
        int seg_ = cc_ / ncseg;                                                \
        int rem_ = cc_ - seg_ * ncseg;                                         \
        int ka_ = (rem_ + ((seg_ == 1) ? ncseg : 0)) * 64;                     \
        int kb_ = rem_ * 64;                                                   \
        uint32_t dA = sbase + (s) * STAGE_BYTES + stoff;                       \
        const uint16_t* ga = gA0 + ka_;                                        \
        _Pragma("unroll")                                                      \
        for (int i = 0; i < 8; i++)                                            \
            cp16(dA + i * 2048, ga + (size_t)i * 16 * ldA);                    \
        uint32_t dB = sbase + (s) * STAGE_BYTES + 16384 + stoff;               \
        const uint16_t* gb = gB0 + kb_;                                        \
        _Pragma("unroll")                                                      \
        for (int i = 0; i < 8; i++)                                            \
            cp16(dB + i * 2048, gb + (size_t)i * 16 * ldB);                    \
        asm volatile("cp.async.commit_group;" ::: "memory");                   \
    } while (0)

    LOAD_STAGE(0, 0);
    LOAD_STAGE(1, 1);

    for (int c = 0; c < nchunks; c++) {
        if (c + 2 < nchunks) {
            asm volatile("cp.async.wait_group 1;" ::: "memory");
        } else {
            asm volatile("cp.async.wait_group 0;" ::: "memory");
        }
        __syncthreads();
        if (c + 2 < nchunks) {
            int s2 = (c + 2) % 3;
            LOAD_STAGE(s2, c + 2);
        }

        const uint32_t aB = sbase + (c % 3) * STAGE_BYTES;
        const uint32_t bB = aB + 16384;
        #pragma unroll
        for (int ks = 0; ks < 4; ks++) {
            uint32_t a[4][4];
            #pragma unroll
            for (int mi = 0; mi < 4; mi++) {
                uint32_t addr = aB + (uint32_t)(rA + mi * 16) * 128 +
                                (uint32_t)(((2 * ks + chA) ^ sA7) << 4);
                ldsm4(a[mi], addr);
            }
            uint32_t b[4][4];
            #pragma unroll
            for (int ng = 0; ng < 4; ng++) {
                uint32_t addr = bB + (uint32_t)(rB + ng * 16) * 128 +
                                (uint32_t)(((2 * ks + chB) ^ sB7) << 4);
                ldsm4(b[ng], addr);
            }
            #pragma unroll
            for (int mi = 0; mi < 4; mi++)
                #pragma unroll
                for (int ni = 0; ni < 8; ni++)
                    mma_f16(acc[mi][ni], a[mi],
                            b[ni >> 1][(ni & 1) * 2],
                            b[ni >> 1][(ni & 1) * 2 + 1]);
        }
        // no trailing sync: slot (c+2)%3 overwritten only after next-iter sync
    }
#undef LOAD_STAGE

    const int erow = lane >> 2;
    const int ecol = (lane & 3) * 2;
    #pragma unroll
    for (int mi = 0; mi < 4; mi++) {
        int row = bm + wm * 64 + mi * 16 + erow;
        #pragma unroll
        for (int ni = 0; ni < 8; ni++) {
            int col = bn + wn * 64 + ni * 8 + ecol;
            float2 v0 = make_float2(acc[mi][ni][0], acc[mi][ni][1]);
            float2 v1 = make_float2(acc[mi][ni][2], acc[mi][ni][3]);
            *reinterpret_cast<float2*>(C + (size_t)row * ldC + col) = v0;
            *reinterpret_cast<float2*>(C + (size_t)(row + 8) * ldC + col) = v1;
        }
    }
}

// ---------------- conversions ----------------
// A for big GEMM: rows scaled by router weight, plain fp16
__global__ void convert_A_kernel(const float* __restrict__ x0,
                                 const float* __restrict__ x1,
                                 const float* __restrict__ xib) {
    const int K4 = KCAT / 4;   // 704
    const int total = BATCH * K4;
    for (int idx = blockIdx.x * blockDim.x + threadIdx.x; idx < total;
         idx += gridDim.x * blockDim.x) {
        int b = idx / K4;
        int c = (idx - b * K4) * 4;
        float w; float4 v;
        if (c < D0) {
            w = g_w[b * 3 + 0];
            v = *reinterpret_cast<const float4*>(x0 + (size_t)b * D0 + c);
        } else if (c < D0 + D1) {
            w = g_w[b * 3 + 1];
            v = *reinterpret_cast<const float4*>(x1 + (size_t)b * D1 + (c - D0));
        } else {
            w = g_w[b * 3 + 2];
            v = *reinterpret_cast<const float4*>(xib + (size_t)b * DIB + (c - D0 - D1));
        }
        __half2 h0 = __floats2half2_rn(v.x * w, v.y * w);
        __half2 h1 = __floats2half2_rn(v.z * w, v.w * w);
        uint2 u;
        u.x = *reinterpret_cast<uint32_t*>(&h0);
        u.y = *reinterpret_cast<uint32_t*>(&h1);
        *reinterpret_cast<uint2*>(g_A + (size_t)b * KCAT + c) = u;
    }
}

// A1 for router GEMM1: fp16 of x0
__global__ void convert_A1_kernel(const float* __restrict__ x0) {
    const int total = BATCH * D0 / 4;
    for (int idx = blockIdx.x * blockDim.x + threadIdx.x; idx < total;
         idx += gridDim.x * blockDim.x) {
        float4 v = *reinterpret_cast<const float4*>(x0 + (size_t)idx * 4);
        __half2 h0 = __floats2half2_rn(v.x, v.y);
        __half2 h1 = __floats2half2_rn(v.z, v.w);
        uint2 u;
        u.x = *reinterpret_cast<uint32_t*>(&h0);
        u.y = *reinterpret_cast<uint32_t*>(&h1);
        *reinterpret_cast<uint2*>(g_A1 + (size_t)idx * 4) = u;
    }
}

// B for big GEMM: average 7 experts, transpose to [n][k], fp16
__global__ void convert_B_kernel(const float* __restrict__ pW0,
                                 const float* __restrict__ pW1,
                                 const float* __restrict__ pWib) {
    __shared__ float t[32][33];
    const int k0 = blockIdx.x * 32;
    const int n0 = blockIdx.y * 32;
    const int tx = threadIdx.x, ty = threadIdx.y;
    for (int kl = ty; kl < 32; kl += 8) {
        int k = k0 + kl;
        const float* src; int lr, ld;
        if (k < D0)            { src = pW0;  lr = k;            ld = D0;  }
        else if (k < D0 + D1)  { src = pW1;  lr = k - D0;       ld = D1;  }
        else                   { src = pWib; lr = k - D0 - D1;  ld = DIB; }
        const float* p = src + (size_t)lr * DOUT + n0 + tx;
        const size_t es = (size_t)ld * DOUT;
        float s = 0.f;
        #pragma unroll
        for (int e = 0; e < NEXP; e++) s += p[(size_t)e * es];
        t[kl][tx] = s * (1.0f / 7.0f);
    }
    __syncthreads();
    for (int nl = ty; nl < 32; nl += 8)
        g_B[(size_t)(n0 + nl) * KCAT + k0 + tx] = __float2half(t[tx][nl]);
}

// B1: transpose rw1[1024,512] to [n][k], fp16
__global__ void convert_B1_kernel(const float* __restrict__ rw1) {
    __shared__ float t[32][33];
    const int k0 = blockIdx.x * 32;
    const int n0 = blockIdx.y * 32;
    const int tx = threadIdx.x, ty = threadIdx.y;
    for (int kl = ty; kl < 32; kl += 8)
        t[kl][tx] = rw1[(size_t)(k0 + kl) * H1C + n0 + tx];
    __syncthreads();
    for (int nl = ty; nl < 32; nl += 8)
        g_B1[(size_t)(n0 + nl) * D0 + k0 + tx] = __float2half(t[tx][nl]);
}

// B2: transpose rw2[512,100] to [n][k] fp16, padded to 128 rows (zeros)
__global__ void convert_B2_kernel(const float* __restrict__ rw2) {
    __shared__ float t[32][33];
    const int k0 = blockIdx.x * 32;
    const int n0 = blockIdx.y * 32;
    const int tx = threadIdx.x, ty = threadIdx.y;
    for (int kl = ty; kl < 32; kl += 8) {
        int n = n0 + tx;
        t[kl][tx] = (n < H2C) ? rw2[(size_t)(k0 + kl) * H2C + n] : 0.f;
    }
    __syncthreads();
    for (int nl = ty; nl < 32; nl += 8)
        g_B2[(size_t)(n0 + nl) * H1C + k0 + tx] = __float2half(t[tx][nl]);
}

// ---------------- misc small kernels ----------------
__global__ void zero_stats_kernel() {
    int i = blockIdx.x * blockDim.x + threadIdx.x;
    if (i < 2 * H1C) g_stats1[i] = 0.0f;
    if (i < 2 * H2C) g_stats2[i] = 0.0f;
}

__global__ void avg_bias_kernel(const float* __restrict__ pb0,
                                const float* __restrict__ pb1,
                                const float* __restrict__ pbib) {
    int i = blockIdx.x * blockDim.x + threadIdx.x;
    if (i >= 3 * DOUT) return;
    int s = i / DOUT, n = i - s * DOUT;
    const float* pb = (s == 0) ? pb0 : (s == 1) ? pb1 : pbib;
    float a = 0.f;
    #pragma unroll
    for (int e = 0; e < NEXP; e++) a += pb[e * DOUT + n];
    g_bavg[i] = a * (1.0f / 7.0f);
}

__global__ void col_stats_kernel(const float* __restrict__ H,
                                 float* __restrict__ stats,
                                 int Brows, int C, int ld) {
    int c = blockIdx.x * 32 + threadIdx.x;
    int chunk = (Brows + gridDim.y - 1) / gridDim.y;
    int r0 = blockIdx.y * chunk;
    int r1 = min(Brows, r0 + chunk);
    float s = 0.f, s2 = 0.f;
    if (c < C) {
        for (int r = r0 + threadIdx.y; r < r1; r += 8) {
            float v = H[(size_t)r * ld + c];
            s += v;
            s2 = fmaf(v, v, s2);
        }
    }
    __shared__ float sh[8][2][32];
    sh[threadIdx.y][0][threadIdx.x] = s;
    sh[threadIdx.y][1][threadIdx.x] = s2;
    __syncthreads();
    if (threadIdx.y == 0 && c < C) {
        float ts = 0.f, ts2 = 0.f;
        #pragma unroll
        for (int y = 0; y < 8; y++) { ts += sh[y][0][threadIdx.x]; ts2 += sh[y][1][threadIdx.x]; }
        atomicAdd(&stats[c], ts);
        atomicAdd(&stats[C + c], ts2);
    }
}

// BN + ReLU on h1 (fp32 in) -> fp16 out
__global__ void bn_relu_h1_kernel(const float* __restrict__ gamma,
                                  const float* __restrict__ beta) {
    const int total = BATCH * H1C;
    const float invB = 1.0f / (float)BATCH;
    for (int i = blockIdx.x * blockDim.x + threadIdx.x; i < total;
         i += gridDim.x * blockDim.x) {
        int c = i & (H1C - 1);
        float mean = g_stats1[c] * invB;
        float var  = g_stats1[H1C + c] * invB - mean * mean;
        float inv  = rsqrtf(var + 1e-5f);
        float v = g_h1[i];
        v = gamma[c] * (v - mean) * inv + beta[c];
        g_h1h[i] = __float2half(fmaxf(v, 0.f));
    }
}

__global__ void router_final_kernel(const float* __restrict__ rg2,
                                    const float* __restrict__ rbt2,
                                    const float* __restrict__ rw3,
                                    const float* __restrict__ rb3) {
    int warp = (blockIdx.x * blockDim.x + threadIdx.x) >> 5;
    int lane = threadIdx.x & 31;
    if (warp >= BATCH) return;
    const float invB = 1.0f / (float)BATCH;
    float d0 = 0.f, d1 = 0.f, d2 = 0.f;
    for (int c = lane; c < H2C; c += 32) {
        float mean = g_stats2[c] * invB;
        float var  = g_stats2[H2C + c] * invB - mean * mean;
        float v = g_h2[(size_t)warp * H2P + c];
        v = rg2[c] * (v - mean) * rsqrtf(var + 1e-5f) + rbt2[c];
        v = tanhf(v);
        d0 = fmaf(v, rw3[c * 3 + 0], d0);
        d1 = fmaf(v, rw3[c * 3 + 1], d1);
        d2 = fmaf(v, rw3[c * 3 + 2], d2);
    }
    #pragma unroll
    for (int o = 16; o > 0; o >>= 1) {
        d0 += __shfl_down_sync(0xffffffffu, d0, o);
        d1 += __shfl_down_sync(0xffffffffu, d1, o);
        d2 += __shfl_down_sync(0xffffffffu, d2, o);
    }
    if (lane == 0) {
        float l0 = 1.f / (1.f + __expf(-(d0 + rb3[0])));
        float l1 = 1.f / (1.f + __expf(-(d1 + rb3[1])));
        float l2 = 1.f / (1.f + __expf(-(d2 + rb3[2])));
        float mx = fmaxf(l0, fmaxf(l1, l2));
        float e0 = __expf(l0 - mx), e1 = __expf(l1 - mx), e2 = __expf(l2 - mx);
        float inv = 1.f / (e0 + e1 + e2);
        g_w[warp * 3 + 0] = e0 * inv;
        g_w[warp * 3 + 1] = e1 * inv;
        g_w[warp * 3 + 2] = e2 * inv;
    }
}

__global__ void normalize_rows_kernel(float* __restrict__ out) {
    int b = blockIdx.x;
    int t = threadIdx.x;
    float w0 = g_w[b * 3 + 0], w1 = g_w[b * 3 + 1], w2 = g_w[b * 3 + 2];
    float vals[6];
    float ss = 0.f;
    #pragma unroll
    for (int j = 0; j < 6; j++) {
        int n = t + j * 256;
        float v = out[(size_t)b * DOUT + n];
        v += w0 * g_bavg[n] + w1 * g_bavg[DOUT + n] + w2 * g_bavg[2 * DOUT + n];
        vals[j] = v;
        ss = fmaf(v, v, ss);
    }
    __shared__ float red[256];
    red[t] = ss;
    __syncthreads();
    #pragma unroll
    for (int s2 = 128; s2 > 0; s2 >>= 1) {
        if (t < s2) red[t] += red[t + s2];
        __syncthreads();
    }
    float inv = 1.f / fmaxf(sqrtf(red[0]), 1e-12f);
    #pragma unroll
    for (int j = 0; j < 6; j++)
        out[(size_t)b * DOUT + t + j * 256] = vals[j] * inv;
}

// ---------------- launch ----------------
extern "C" void kernel_launch(void* const* d_in, const int* in_sizes, int n_in,
                              void* d_out, int out_size) {
    const float* x0   = (const float*)d_in[0];
    const float* x1   = (const float*)d_in[1];
    const float* xib  = (const float*)d_in[2];
    const float* pW0  = (const float*)d_in[3];
    const float* pb0  = (const float*)d_in[4];
    const float* pW1  = (const float*)d_in[5];
    const float* pb1  = (const float*)d_in[6];
    const float* pWib = (const float*)d_in[7];
    const float* pbib = (const float*)d_in[8];
    const float* rw1  = (const float*)d_in[9];
    // rb1 (d_in[10]) cancels exactly under batch-norm — skipped
    const float* rg1  = (const float*)d_in[11];
    const float* rbt1 = (const float*)d_in[12];
    const float* rw2  = (const float*)d_in[13];
    // rb2 (d_in[14]) also cancels under batch-norm — skipped
    const float* rg2  = (const float*)d_in[15];
    const float* rbt2 = (const float*)d_in[16];
    const float* rw3  = (const float*)d_in[17];
    const float* rb3  = (const float*)d_in[18];
    float* out = (float*)d_out;
    (void)in_sizes; (void)n_in; (void)out_size;

    void *a_p, *b_p, *a1_p, *b1_p, *b2_p, *h1_p, *h1h_p, *h2_p, *s1_p, *s2_p;
    cudaGetSymbolAddress(&a_p,   g_A);
    cudaGetSymbolAddress(&b_p,   g_B);
    cudaGetSymbolAddress(&a1_p,  g_A1);
    cudaGetSymbolAddress(&b1_p,  g_B1);
    cudaGetSymbolAddress(&b2_p,  g_B2);
    cudaGetSymbolAddress(&h1_p,  g_h1);
    cudaGetSymbolAddress(&h1h_p, g_h1h);
    cudaGetSymbolAddress(&h2_p,  g_h2);
    cudaGetSymbolAddress(&s1_p,  g_stats1);
    cudaGetSymbolAddress(&s2_p,  g_stats2);
    const uint16_t* Ab  = (const uint16_t*)a_p;
    const uint16_t* Bb  = (const uint16_t*)b_p;
    const uint16_t* A1h = (const uint16_t*)a1_p;
    const uint16_t* B1h = (const uint16_t*)b1_p;
    const uint16_t* B2h = (const uint16_t*)b2_p;
    const uint16_t* H1h = (const uint16_t*)h1h_p;
    float* h1  = (float*)h1_p;
    float* h2  = (float*)h2_p;
    float* st1 = (float*)s1_p;
    float* st2 = (float*)s2_p;

    cudaFuncSetAttribute(hmma_gemm_kernel,
                         cudaFuncAttributeMaxDynamicSharedMemorySize, HM_SMEM);

    zero_stats_kernel<<<4, 256>>>();
    avg_bias_kernel<<<(3 * DOUT + 255) / 256, 256>>>(pb0, pb1, pbib);

    // weight-side conversions (independent of router)
    convert_B_kernel <<<dim3(KCAT / 32, DOUT / 32), dim3(32, 8)>>>(pW0, pW1, pWib);
    convert_B1_kernel<<<dim3(D0 / 32, H1C / 32),   dim3(32, 8)>>>(rw1);
    convert_B2_kernel<<<dim3(H1C / 32, H2P / 32),  dim3(32, 8)>>>(rw2);
    convert_A1_kernel<<<4096, 256>>>(x0);

    // router layer 1 (fp16 HMMA): h1 = x0 @ rw1
    hmma_gemm_kernel<<<dim3(H1C / 128, BATCH / 128), 128, HM_SMEM>>>(
        A1h, B1h, h1, D0, D0, H1C, D0 / 64, D0 / 64);
    col_stats_kernel<<<dim3(H1C / 32, 16), dim3(32, 8)>>>(h1, st1, BATCH, H1C, H1C);
    bn_relu_h1_kernel<<<4096, 256>>>(rg1, rbt1);

    // router layer 2 (fp16 HMMA, N padded to 128): h2 = relu(bn(h1)) @ rw2
    hmma_gemm_kernel<<<dim3(H2P / 128, BATCH / 128), 128, HM_SMEM>>>(
        H1h, B2h, h2, H1C, H1C, H2P, H1C / 64, H1C / 64);
    col_stats_kernel<<<dim3((H2C + 31) / 32, 16), dim3(32, 8)>>>(h2, st2, BATCH, H2C, H2P);
    router_final_kernel<<<BATCH * 32 / 256, 256>>>(rg2, rbt2, rw3, rb3);

    // big GEMM (plain fp16, 1 term)
    convert_A_kernel<<<8192, 256>>>(x0, x1, xib);
    hmma_gemm_kernel<<<dim3(DOUT / 128, BATCH / 128), 128, HM_SMEM>>>(
        Ab, Bb, out, KCAT, KCAT, DOUT, NC_BIG, NC_BIG);

    normalize_rows_kernel<<<BATCH, 256>>>(out);
}

// round 11
// speedup vs baseline: 2.5563x; 1.0553x over previous
#include <cuda_runtime.h>
#include <cuda_bf16.h>
#include <cuda_fp16.h>
#include <cstdint>
#include <math.h>

// ---------------- problem constants ----------------
#define BATCH   8192
#define D0      1024
#define D1      768
#define DIB     1024
#define KCAT    2816        // D0 + D1 + DIB
#define DOUT    1536
#define H1C     512
#define H2C     100
#define H2P     128         // padded N for layer-2 GEMM
#define NEXP    7

#define NC_BIG  (KCAT/64)   // 44 chunks
#define CEND0   15          // last chunk of x0 segment (1024/64 - 1)
#define CEND1   27          // last chunk of x1 segment (+768/64)

// ---------------- device scratch (no allocations allowed) ----------------
__device__ __half g_A  [(size_t)BATCH * KCAT];    // 46 MB  fp16 [x0|x1|xib] UNSCALED
__device__ __half g_B  [(size_t)DOUT  * KCAT];    // 8.7 MB [n][k] K-major, fp16
__device__ __half g_B1 [(size_t)H1C   * D0];      // 1 MB   rw1^T fp16
__device__ __half g_B2 [(size_t)H2P   * H1C];     // 128 KB rw2^T fp16 (padded)
__device__ __half g_h1h[BATCH * H1C];             // fp16 h1
__device__ float  g_h2 [BATCH * H2P];
__device__ float  g_stats1[2 * H1C];
__device__ float  g_stats2[2 * H2C];
__device__ float  g_w   [BATCH * 3];
__device__ float  g_bavg[3 * DOUT];

// ---------------- PTX helpers (base-target safe: sm_80+ ISA only) ------------
__device__ __forceinline__ uint32_t smem_u32(const void* p) {
    uint32_t a;
    asm("{ .reg .u64 t; cvta.to.shared.u64 t, %1; cvt.u32.u64 %0, t; }"
        : "=r"(a) : "l"(p));
    return a;
}
__device__ __forceinline__ void cp16(uint32_t saddr, const void* g) {
    asm volatile("cp.async.cg.shared.global [%0], [%1], 16;"
                 :: "r"(saddr), "l"(g));
}
__device__ __forceinline__ void ldsm4(uint32_t* r, uint32_t addr) {
    asm volatile("ldmatrix.sync.aligned.m8n8.x4.shared.b16 {%0,%1,%2,%3}, [%4];"
                 : "=r"(r[0]), "=r"(r[1]), "=r"(r[2]), "=r"(r[3]) : "r"(addr));
}
__device__ __forceinline__ void mma_f16(float* c, const uint32_t* a,
                                        uint32_t b0, uint32_t b1) {
    asm volatile(
        "mma.sync.aligned.m16n8k16.row.col.f32.f16.f16.f32 "
        "{%0,%1,%2,%3}, {%4,%5,%6,%7}, {%8,%9}, {%0,%1,%2,%3};"
        : "+f"(c[0]), "+f"(c[1]), "+f"(c[2]), "+f"(c[3])
        : "r"(a[0]), "r"(a[1]), "r"(a[2]), "r"(a[3]), "r"(b0), "r"(b1));
}

// ---------------- HMMA fp16 GEMM: C[M,N] = A[M,K] @ B[N,K]^T -----------------
// CTA 128x128, BK=64, 3-stage cp.async pipeline (96 KB smem, 2 CTA/SM),
// 4 warps 2(m) x 2(n), warp tile 64x64, mma.sync.m16n8k16.
// WSCALE: per-row MoE weighting via segment-boundary accumulator rescale:
//   after chunk CEND0: acc *= w0/w1; after CEND1: acc *= w1/w2; final: *= w2.
// OUT16: write __half output instead of float.
#define STAGE_BYTES 32768               // A 16KB + B 16KB
#define HM_SMEM     (3 * STAGE_BYTES)   // 98304

template<bool OUT16, bool WSCALE>
__global__ void __launch_bounds__(128, 2)
hmma_gemm_kernel(const uint16_t* __restrict__ A,
                 const uint16_t* __restrict__ B,
                 float* __restrict__ C,
                 const float* __restrict__ W,
                 int ldA, int ldB, int ldC, int nchunks) {
    extern __shared__ char smem[];
    const uint32_t sbase = smem_u32(smem);
    const int tid  = threadIdx.x;
    const int lane = tid & 31;
    const int wid  = tid >> 5;          // 0..3
    const int wm   = wid & 1;
    const int wn   = wid >> 1;
    const int bm   = blockIdx.y * 128;
    const int bn   = blockIdx.x * 128;
    const int erow = lane >> 2;
    const int ecol = (lane & 3) * 2;

    const int srow = tid >> 3;          // 0..15
    const int scol = tid & 7;           // 16B unit
    const uint32_t stoff = (uint32_t)srow * 128 +
                           (uint32_t)((scol ^ (srow & 7)) << 4);
    const uint16_t* gA0 = A + (size_t)(bm + srow) * ldA + scol * 8;
    const uint16_t* gB0 = B + (size_t)(bn + srow) * ldB + scol * 8;

    // per-row router-weight ratios (WSCALE only)
    float r01[4][2], r12[4][2], wfin[4][2];
    if (WSCALE) {
        #pragma unroll
        for (int mi = 0; mi < 4; mi++)
            #pragma unroll
            for (int h = 0; h < 2; h++) {
                int row = bm + wm * 64 + mi * 16 + erow + h * 8;
                float w0 = W[row * 3 + 0];
                float w1 = W[row * 3 + 1];
                float w2 = W[row * 3 + 2];
                r01[mi][h]  = w0 / w1;
                r12[mi][h]  = w1 / w2;
                wfin[mi][h] = w2;
            }
    }

    float acc[4][8][4];
    #pragma unroll
    for (int i = 0; i < 4; i++)
        #pragma unroll
        for (int j = 0; j < 8; j++)
            #pragma unroll
            for (int r = 0; r < 4; r++) acc[i][j][r] = 0.f;

    const int g  = lane >> 3;
    const int lr = lane & 7;
    const int rA  = wm * 64 + lr + (g & 1) * 8;
    const int chA = g >> 1;
    const int sA7 = rA & 7;
    const int rB  = wn * 64 + lr + (g >> 1) * 8;
    const int chB = g & 1;
    const int sB7 = rB & 7;

#define LOAD_STAGE(s, c_)                                                      \
    do {                                                                       \
        int k0_ = (c_) * 64;                                                   \
        uint32_t dA = sbase + (s) * STAGE_BYTES + stoff;                       \
        const uint16_t* ga = gA0 + k0_;                                        \
        _Pragma("unroll")                                                      \
        for (int i = 0; i < 8; i++)                                            \
            cp16(dA + i * 2048, ga + (size_t)i * 16 * ldA);                    \
        uint32_t dB = sbase + (s) * STAGE_BYTES + 16384 + stoff;               \
        const uint16_t* gb = gB0 + k0_;                                        \
        _Pragma("unroll")                                                      \
        for (int i = 0; i < 8; i++)                                            \
            cp16(dB + i * 2048, gb + (size_t)i * 16 * ldB);                    \
        asm volatile("cp.async.commit_group;" ::: "memory");                   \
    } while (0)

    LOAD_STAGE(0, 0);
    LOAD_STAGE(1, 1);

    for (int c = 0; c < nchunks; c++) {
        if (c + 2 < nchunks) {
            asm volatile("cp.async.wait_group 1;" ::: "memory");
        } else {
            asm volatile("cp.async.wait_group 0;" ::: "memory");
        }
        __syncthreads();
        if (c + 2 < nchunks) {
            int s2 = (c + 2) % 3;
            LOAD_STAGE(s2, c + 2);
        }

        const uint32_t aB = sbase + (c % 3) * STAGE_BYTES;
        const uint32_t bB = aB + 16384;
        #pragma unroll
        for (int ks = 0; ks < 4; ks++) {
            uint32_t a[4][4];
            #pragma unroll
            for (int mi = 0; mi < 4; mi++) {
                uint32_t addr = aB + (uint32_t)(rA + mi * 16) * 128 +
                                (uint32_t)(((2 * ks + chA) ^ sA7) << 4);
                ldsm4(a[mi], addr);
            }
            uint32_t b[4][4];
            #pragma unroll
            for (int ng = 0; ng < 4; ng++) {
                uint32_t addr = bB + (uint32_t)(rB + ng * 16) * 128 +
                                (uint32_t)(((2 * ks + chB) ^ sB7) << 4);
                ldsm4(b[ng], addr);
            }
            #pragma unroll
            for (int mi = 0; mi < 4; mi++)
                #pragma unroll
                for (int ni = 0; ni < 8; ni++)
                    mma_f16(acc[mi][ni], a[mi],
                            b[ni >> 1][(ni & 1) * 2],
                            b[ni >> 1][(ni & 1) * 2 + 1]);
        }
        if (WSCALE && (c == CEND0 || c == CEND1)) {
            #pragma unroll
            for (int mi = 0; mi < 4; mi++)
                #pragma unroll
                for (int ni = 0; ni < 8; ni++)
                    #pragma unroll
                    for (int r = 0; r < 4; r++) {
                        float rt = (c == CEND0) ? r01[mi][r >> 1]
                                                : r12[mi][r >> 1];
                        acc[mi][ni][r] *= rt;
                    }
        }
        // no trailing sync: slot (c+2)%3 overwritten only after next-iter sync
    }
#undef LOAD_STAGE

    #pragma unroll
    for (int mi = 0; mi < 4; mi++) {
        int row = bm + wm * 64 + mi * 16 + erow;
        #pragma unroll
        for (int ni = 0; ni < 8; ni++) {
            int col = bn + wn * 64 + ni * 8 + ecol;
            float s0 = WSCALE ? wfin[mi][0] : 1.f;
            float s1 = WSCALE ? wfin[mi][1] : 1.f;
            if (OUT16) {
                __half* C16 = reinterpret_cast<__half*>(C);
                __half2 v0 = __floats2half2_rn(acc[mi][ni][0] * s0,
                                               acc[mi][ni][1] * s0);
                __half2 v1 = __floats2half2_rn(acc[mi][ni][2] * s1,
                                               acc[mi][ni][3] * s1);
                *reinterpret_cast<__half2*>(C16 + (size_t)row * ldC + col) = v0;
                *reinterpret_cast<__half2*>(C16 + (size_t)(row + 8) * ldC + col) = v1;
            } else {
                float2 v0 = make_float2(acc[mi][ni][0] * s0, acc[mi][ni][1] * s0);
                float2 v1 = make_float2(acc[mi][ni][2] * s1, acc[mi][ni][3] * s1);
                *reinterpret_cast<float2*>(C + (size_t)row * ldC + col) = v0;
                *reinterpret_cast<float2*>(C + (size_t)(row + 8) * ldC + col) = v1;
            }
        }
    }
}

// ---------------- conversions ----------------
// A: plain fp16 of [x0 | x1 | xib]  (router-independent, unscaled)
__global__ void convert_A_kernel(const float* __restrict__ x0,
                                 const float* __restrict__ x1,
                                 const float* __restrict__ xib) {
    const int K4 = KCAT / 4;   // 704
    const int total = BATCH * K4;
    for (int idx = blockIdx.x * blockDim.x + threadIdx.x; idx < total;
         idx += gridDim.x * blockDim.x) {
        int b = idx / K4;
        int c = (idx - b * K4) * 4;
        float4 v;
        if (c < D0)
            v = *reinterpret_cast<const float4*>(x0 + (size_t)b * D0 + c);
        else if (c < D0 + D1)
            v = *reinterpret_cast<const float4*>(x1 + (size_t)b * D1 + (c - D0));
        else
            v = *reinterpret_cast<const float4*>(xib + (size_t)b * DIB + (c - D0 - D1));
        __half2 h0 = __floats2half2_rn(v.x, v.y);
        __half2 h1 = __floats2half2_rn(v.z, v.w);
        uint2 u;
        u.x = *reinterpret_cast<uint32_t*>(&h0);
        u.y = *reinterpret_cast<uint32_t*>(&h1);
        *reinterpret_cast<uint2*>(g_A + (size_t)b * KCAT + c) = u;
    }
}

// B for big GEMM: average 7 experts, transpose to [n][k], fp16
__global__ void convert_B_kernel(const float* __restrict__ pW0,
                                 const float* __restrict__ pW1,
                                 const float* __restrict__ pWib) {
    __shared__ float t[32][33];
    const int k0 = blockIdx.x * 32;
    const int n0 = blockIdx.y * 32;
    const int tx = threadIdx.x, ty = threadIdx.y;
    for (int kl = ty; kl < 32; kl += 8) {
        int k = k0 + kl;
        const float* src; int lr, ld;
        if (k < D0)            { src = pW0;  lr = k;            ld = D0;  }
        else if (k < D0 + D1)  { src = pW1;  lr = k - D0;       ld = D1;  }
        else                   { src = pWib; lr = k - D0 - D1;  ld = DIB; }
        const float* p = src + (size_t)lr * DOUT + n0 + tx;
        const size_t es = (size_t)ld * DOUT;
        float s = 0.f;
        #pragma unroll
        for (int e = 0; e < NEXP; e++) s += p[(size_t)e * es];
        t[kl][tx] = s * (1.0f / 7.0f);
    }
    __syncthreads();
    for (int nl = ty; nl < 32; nl += 8)
        g_B[(size_t)(n0 + nl) * KCAT + k0 + tx] = __float2half(t[tx][nl]);
}

// B1: transpose rw1[1024,512] to [n][k], fp16
__global__ void convert_B1_kernel(const float* __restrict__ rw1) {
    __shared__ float t[32][33];
    const int k0 = blockIdx.x * 32;
    const int n0 = blockIdx.y * 32;
    const int tx = threadIdx.x, ty = threadIdx.y;
    for (int kl = ty; kl < 32; kl += 8)
        t[kl][tx] = rw1[(size_t)(k0 + kl) * H1C + n0 + tx];
    __syncthreads();
    for (int nl = ty; nl < 32; nl += 8)
        g_B1[(size_t)(n0 + nl) * D0 + k0 + tx] = __float2half(t[tx][nl]);
}

// B2: transpose rw2[512,100] to [n][k] fp16, padded to 128 rows (zeros)
__global__ void convert_B2_kernel(const float* __restrict__ rw2) {
    __shared__ float t[32][33];
    const int k0 = blockIdx.x * 32;
    const int n0 = blockIdx.y * 32;
    const int tx = threadIdx.x, ty = threadIdx.y;
    for (int kl = ty; kl < 32; kl += 8) {
        int n = n0 + tx;
        t[kl][tx] = (n < H2C) ? rw2[(size_t)(k0 + kl) * H2C + n] : 0.f;
    }
    __syncthreads();
    for (int nl = ty; nl < 32; nl += 8)
        g_B2[(size_t)(n0 + nl) * H1C + k0 + tx] = __float2half(t[tx][nl]);
}

// ---------------- misc small kernels ----------------
// merged: zero BN-stat accumulators + average projection biases
__global__ void init_kernel(const float* __restrict__ pb0,
                            const float* __restrict__ pb1,
                            const float* __restrict__ pbib) {
    int i = blockIdx.x * blockDim.x + threadIdx.x;
    if (i < 2 * H1C) g_stats1[i] = 0.0f;
    if (i < 2 * H2C) g_stats2[i] = 0.0f;
    if (i < 3 * DOUT) {
        int s = i / DOUT, n = i - s * DOUT;
        const float* pb = (s == 0) ? pb0 : (s == 1) ? pb1 : pbib;
        float a = 0.f;
        #pragma unroll
        for (int e = 0; e < NEXP; e++) a += pb[e * DOUT + n];
        g_bavg[i] = a * (1.0f / 7.0f);
    }
}

template<typename T>
__global__ void col_stats_kernel(const T* __restrict__ H,
                                 float* __restrict__ stats,
                                 int Brows, int C, int ld) {
    int c = blockIdx.x * 32 + threadIdx.x;
    int chunk = (Brows + gridDim.y - 1) / gridDim.y;
    int r0 = blockIdx.y * chunk;
    int r1 = min(Brows, r0 + chunk);
    float s = 0.f, s2 = 0.f;
    if (c < C) {
        for (int r = r0 + threadIdx.y; r < r1; r += 8) {
            float v = (float)H[(size_t)r * ld + c];
            s += v;
            s2 = fmaf(v, v, s2);
        }
    }
    __shared__ float sh[8][2][32];
    sh[threadIdx.y][0][threadIdx.x] = s;
    sh[threadIdx.y][1][threadIdx.x] = s2;
    __syncthreads();
    if (threadIdx.y == 0 && c < C) {
        float ts = 0.f, ts2 = 0.f;
        #pragma unroll
        for (int y = 0; y < 8; y++) { ts += sh[y][0][threadIdx.x]; ts2 += sh[y][1][threadIdx.x]; }
        atomicAdd(&stats[c], ts);
        atomicAdd(&stats[C + c], ts2);
    }
}

// BN + ReLU in place on fp16 h1
__global__ void bn_relu_h1_kernel(const float* __restrict__ gamma,
                                  const float* __restrict__ beta) {
    const int total = BATCH * H1C;
    const float invB = 1.0f / (float)BATCH;
    for (int i = blockIdx.x * blockDim.x + threadIdx.x; i < total;
         i += gridDim.x * blockDim.x) {
        int c = i & (H1C - 1);
        float mean = g_stats1[c] * invB;
        float var  = g_stats1[H1C + c] * invB - mean * mean;
        float inv  = rsqrtf(var + 1e-5f);
        float v = __half2float(g_h1h[i]);
        v = gamma[c] * (v - mean) * inv + beta[c];
        g_h1h[i] = __float2half(fmaxf(v, 0.f));
    }
}

__global__ void router_final_kernel(const float* __restrict__ rg2,
                                    const float* __restrict__ rbt2,
                                    const float* __restrict__ rw3,
                                    const float* __restrict__ rb3) {
    int warp = (blockIdx.x * blockDim.x + threadIdx.x) >> 5;
    int lane = threadIdx.x & 31;
    if (warp >= BATCH) return;
    const float invB = 1.0f / (float)BATCH;
    float d0 = 0.f, d1 = 0.f, d2 = 0.f;
    for (int c = lane; c < H2C; c += 32) {
        float mean = g_stats2[c] * invB;
        float var  = g_stats2[H2C + c] * invB - mean * mean;
        float v = g_h2[(size_t)warp * H2P + c];
        v = rg2[c] * (v - mean) * rsqrtf(var + 1e-5f) + rbt2[c];
        v = tanhf(v);
        d0 = fmaf(v, rw3[c * 3 + 0], d0);
        d1 = fmaf(v, rw3[c * 3 + 1], d1);
        d2 = fmaf(v, rw3[c * 3 + 2], d2);
    }
    #pragma unroll
    for (int o = 16; o > 0; o >>= 1) {
        d0 += __shfl_down_sync(0xffffffffu, d0, o);
        d1 += __shfl_down_sync(0xffffffffu, d1, o);
        d2 += __shfl_down_sync(0xffffffffu, d2, o);
    }
    if (lane == 0) {
        float l0 = 1.f / (1.f + __expf(-(d0 + rb3[0])));
        float l1 = 1.f / (1.f + __expf(-(d1 + rb3[1])));
        float l2 = 1.f / (1.f + __expf(-(d2 + rb3[2])));
        float mx = fmaxf(l0, fmaxf(l1, l2));
        float e0 = __expf(l0 - mx), e1 = __expf(l1 - mx), e2 = __expf(l2 - mx);
        float inv = 1.f / (e0 + e1 + e2);
        g_w[warp * 3 + 0] = e0 * inv;
        g_w[warp * 3 + 1] = e1 * inv;
        g_w[warp * 3 + 2] = e2 * inv;
    }
}

__global__ void normalize_rows_kernel(float* __restrict__ out) {
    int b = blockIdx.x;
    int t = threadIdx.x;
    float w0 = g_w[b * 3 + 0], w1 = g_w[b * 3 + 1], w2 = g_w[b * 3 + 2];
    float vals[6];
    float ss = 0.f;
    #pragma unroll
    for (int j = 0; j < 6; j++) {
        int n = t + j * 256;
        float v = out[(size_t)b * DOUT + n];
        v += w0 * g_bavg[n] + w1 * g_bavg[DOUT + n] + w2 * g_bavg[2 * DOUT + n];
        vals[j] = v;
        ss = fmaf(v, v, ss);
    }
    __shared__ float red[256];
    red[t] = ss;
    __syncthreads();
    #pragma unroll
    for (int s2 = 128; s2 > 0; s2 >>= 1) {
        if (t < s2) red[t] += red[t + s2];
        __syncthreads();
    }
    float inv = 1.f / fmaxf(sqrtf(red[0]), 1e-12f);
    #pragma unroll
    for (int j = 0; j < 6; j++)
        out[(size_t)b * DOUT + t + j * 256] = vals[j] * inv;
}

// ---------------- launch ----------------
extern "C" void kernel_launch(void* const* d_in, const int* in_sizes, int n_in,
                              void* d_out, int out_size) {
    const float* x0   = (const float*)d_in[0];
    const float* x1   = (const float*)d_in[1];
    const float* xib  = (const float*)d_in[2];
    const float* pW0  = (const float*)d_in[3];
    const float* pb0  = (const float*)d_in[4];
    const float* pW1  = (const float*)d_in[5];
    const float* pb1  = (const float*)d_in[6];
    const float* pWib = (const float*)d_in[7];
    const float* pbib = (const float*)d_in[8];
    const float* rw1  = (const float*)d_in[9];
    // rb1 (d_in[10]) cancels exactly under batch-norm — skipped
    const float* rg1  = (const float*)d_in[11];
    const float* rbt1 = (const float*)d_in[12];
    const float* rw2  = (const float*)d_in[13];
    // rb2 (d_in[14]) also cancels under batch-norm — skipped
    const float* rg2  = (const float*)d_in[15];
    const float* rbt2 = (const float*)d_in[16];
    const float* rw3  = (const float*)d_in[17];
    const float* rb3  = (const float*)d_in[18];
    float* out = (float*)d_out;
    (void)in_sizes; (void)n_in; (void)out_size;

    void *a_p, *b_p, *b1_p, *b2_p, *h1h_p, *h2_p, *s1_p, *s2_p, *w_p;
    cudaGetSymbolAddress(&a_p,   g_A);
    cudaGetSymbolAddress(&b_p,   g_B);
    cudaGetSymbolAddress(&b1_p,  g_B1);
    cudaGetSymbolAddress(&b2_p,  g_B2);
    cudaGetSymbolAddress(&h1h_p, g_h1h);
    cudaGetSymbolAddress(&h2_p,  g_h2);
    cudaGetSymbolAddress(&s1_p,  g_stats1);
    cudaGetSymbolAddress(&s2_p,  g_stats2);
    cudaGetSymbolAddress(&w_p,   g_w);
    const uint16_t* Ab  = (const uint16_t*)a_p;
    const uint16_t* Bb  = (const uint16_t*)b_p;
    const uint16_t* B1h = (const uint16_t*)b1_p;
    const uint16_t* B2h = (const uint16_t*)b2_p;
    const uint16_t* H1u = (const uint16_t*)h1h_p;
    const __half*   H1h = (const __half*)h1h_p;
    float* h1f = (float*)h1h_p;   // reinterpreted for OUT16 GEMM param
    float* h2  = (float*)h2_p;
    float* st1 = (float*)s1_p;
    float* st2 = (float*)s2_p;
    const float* Wp = (const float*)w_p;

    cudaFuncSetAttribute((const void*)hmma_gemm_kernel<false, false>,
                         cudaFuncAttributeMaxDynamicSharedMemorySize, HM_SMEM);
    cudaFuncSetAttribute((const void*)hmma_gemm_kernel<true, false>,
                         cudaFuncAttributeMaxDynamicSharedMemorySize, HM_SMEM);
    cudaFuncSetAttribute((const void*)hmma_gemm_kernel<false, true>,
                         cudaFuncAttributeMaxDynamicSharedMemorySize, HM_SMEM);

    init_kernel<<<(3 * DOUT + 255) / 256, 256>>>(pb0, pb1, pbib);

    // conversions (all router-independent now)
    convert_A_kernel <<<8192, 256>>>(x0, x1, xib);
    convert_B_kernel <<<dim3(KCAT / 32, DOUT / 32), dim3(32, 8)>>>(pW0, pW1, pWib);
    convert_B1_kernel<<<dim3(D0 / 32, H1C / 32),   dim3(32, 8)>>>(rw1);
    convert_B2_kernel<<<dim3(H1C / 32, H2P / 32),  dim3(32, 8)>>>(rw2);

    // router layer 1 (fp16 HMMA, fp16 out): h1 = x0 @ rw1
    //   x0 = first D0 columns of g_A (ldA = KCAT)
    hmma_gemm_kernel<true, false><<<dim3(H1C / 128, BATCH / 128), 128, HM_SMEM>>>(
        Ab, B1h, h1f, nullptr, KCAT, D0, H1C, D0 / 64);
    col_stats_kernel<__half><<<dim3(H1C / 32, 16), dim3(32, 8)>>>(
        H1h, st1, BATCH, H1C, H1C);
    bn_relu_h1_kernel<<<4096, 256>>>(rg1, rbt1);

    // router layer 2 (fp16 HMMA, N padded to 128): h2 = relu(bn(h1)) @ rw2
    hmma_gemm_kernel<false, false><<<dim3(H2P / 128, BATCH / 128), 128, HM_SMEM>>>(
        H1u, B2h, h2, nullptr, H1C, H1C, H2P, H1C / 64);
    col_stats_kernel<float><<<dim3((H2C + 31) / 32, 16), dim3(32, 8)>>>(
        h2, st2, BATCH, H2C, H2P);
    router_final_kernel<<<BATCH * 32 / 256, 256>>>(rg2, rbt2, rw3, rb3);

    // big GEMM (plain fp16) with per-row MoE weighting in the epilogue
    hmma_gemm_kernel<false, true><<<dim3(DOUT / 128, BATCH / 128), 128, HM_SMEM>>>(
        Ab, Bb, out, Wp, KCAT, KCAT, DOUT, NC_BIG);

    normalize_rows_kernel<<<BATCH, 256>>>(out);
}

// round 12
// speedup vs baseline: 2.5863x; 1.0117x over previous
#include <cuda_runtime.h>
#include <cuda_bf16.h>
#include <cuda_fp16.h>
#include <cstdint>
#include <math.h>

// ---------------- problem constants ----------------
#define BATCH   8192
#define D0      1024
#define D1      768
#define DIB     1024
#define KCAT    2816        // D0 + D1 + DIB
#define DOUT    1536
#define H1C     512
#define H2C     100
#define H2P     128         // padded N for layer-2 GEMM
#define NEXP    7

#define NC_BIG  (KCAT/64)   // 44 chunks
#define CEND0   15          // last chunk of x0 segment (1024/64 - 1)
#define CEND1   27          // last chunk of x1 segment (+768/64)

// ---------------- device scratch (no allocations allowed) ----------------
__device__ __half g_A  [(size_t)BATCH * KCAT];    // 46 MB  fp16 [x0|x1|xib] UNSCALED
__device__ __half g_B  [(size_t)DOUT  * KCAT];    // 8.7 MB [n][k] K-major, fp16
__device__ __half g_B1 [(size_t)H1C   * D0];      // 1 MB   rw1^T fp16
__device__ __half g_B2 [(size_t)H2P   * H1C];     // 128 KB rw2^T fp16 (padded)
__device__ __half g_h1h[BATCH * H1C];             // fp16 h1
__device__ float  g_h2 [BATCH * H2P];
__device__ float  g_stats1[2 * H1C];
__device__ float  g_stats2[2 * H2C];
__device__ float  g_w   [BATCH * 3];
__device__ float  g_bavg[3 * DOUT];

// ---------------- PTX helpers (base-target safe: sm_80+ ISA only) ------------
__device__ __forceinline__ uint32_t smem_u32(const void* p) {
    uint32_t a;
    asm("{ .reg .u64 t; cvta.to.shared.u64 t, %1; cvt.u32.u64 %0, t; }"
        : "=r"(a) : "l"(p));
    return a;
}
__device__ __forceinline__ void cp16(uint32_t saddr, const void* g) {
    asm volatile("cp.async.cg.shared.global [%0], [%1], 16;"
                 :: "r"(saddr), "l"(g));
}
__device__ __forceinline__ void ldsm4(uint32_t* r, uint32_t addr) {
    asm volatile("ldmatrix.sync.aligned.m8n8.x4.shared.b16 {%0,%1,%2,%3}, [%4];"
                 : "=r"(r[0]), "=r"(r[1]), "=r"(r[2]), "=r"(r[3]) : "r"(addr));
}
__device__ __forceinline__ void mma_f16(float* c, const uint32_t* a,
                                        uint32_t b0, uint32_t b1) {
    asm volatile(
        "mma.sync.aligned.m16n8k16.row.col.f32.f16.f16.f32 "
        "{%0,%1,%2,%3}, {%4,%5,%6,%7}, {%8,%9}, {%0,%1,%2,%3};"
        : "+f"(c[0]), "+f"(c[1]), "+f"(c[2]), "+f"(c[3])
        : "r"(a[0]), "r"(a[1]), "r"(a[2]), "r"(a[3]), "r"(b0), "r"(b1));
}

// ---------------- HMMA fp16 GEMM: C[M,N] = A[M,K] @ B[N,K]^T -----------------
// CTA 128x128, BK=64, 3-stage cp.async pipeline (96 KB smem, 2 CTA/SM),
// 4 warps 2(m) x 2(n), warp tile 64x64, mma.sync.m16n8k16.
// WSCALE: per-row MoE weighting via segment-boundary accumulator rescale.
// OUT16 : write __half output.
// STATS : per-column sum/sumsq atomically accumulated into `stats` (len 2*statsC)
//         from the fp32 accumulators (fused BN batch-stat pass).
#define STAGE_BYTES 32768               // A 16KB + B 16KB
#define HM_SMEM     (3 * STAGE_BYTES)   // 98304

template<bool OUT16, bool WSCALE, bool STATS>
__global__ void __launch_bounds__(128, 2)
hmma_gemm_kernel(const uint16_t* __restrict__ A,
                 const uint16_t* __restrict__ B,
                 float* __restrict__ C,
                 const float* __restrict__ W,
                 float* __restrict__ stats, int statsC,
                 int ldA, int ldB, int ldC, int nchunks) {
    extern __shared__ char smem[];
    const uint32_t sbase = smem_u32(smem);
    const int tid  = threadIdx.x;
    const int lane = tid & 31;
    const int wid  = tid >> 5;          // 0..3
    const int wm   = wid & 1;
    const int wn   = wid >> 1;
    const int bm   = blockIdx.y * 128;
    const int bn   = blockIdx.x * 128;
    const int erow = lane >> 2;
    const int ecol = (lane & 3) * 2;

    const int srow = tid >> 3;          // 0..15
    const int scol = tid & 7;           // 16B unit
    const uint32_t stoff = (uint32_t)srow * 128 +
                           (uint32_t)((scol ^ (srow & 7)) << 4);
    const uint16_t* gA0 = A + (size_t)(bm + srow) * ldA + scol * 8;
    const uint16_t* gB0 = B + (size_t)(bn + srow) * ldB + scol * 8;

    // per-row router-weight ratios (WSCALE only)
    float r01[4][2], r12[4][2], wfin[4][2];
    if (WSCALE) {
        #pragma unroll
        for (int mi = 0; mi < 4; mi++)
            #pragma unroll
            for (int h = 0; h < 2; h++) {
                int row = bm + wm * 64 + mi * 16 + erow + h * 8;
                float w0 = W[row * 3 + 0];
                float w1 = W[row * 3 + 1];
                float w2 = W[row * 3 + 2];
                r01[mi][h]  = w0 / w1;
                r12[mi][h]  = w1 / w2;
                wfin[mi][h] = w2;
            }
    }

    float acc[4][8][4];
    #pragma unroll
    for (int i = 0; i < 4; i++)
        #pragma unroll
        for (int j = 0; j < 8; j++)
            #pragma unroll
            for (int r = 0; r < 4; r++) acc[i][j][r] = 0.f;

    const int g  = lane >> 3;
    const int lr = lane & 7;
    const int rA  = wm * 64 + lr + (g & 1) * 8;
    const int chA = g >> 1;
    const int sA7 = rA & 7;
    const int rB  = wn * 64 + lr + (g >> 1) * 8;
    const int chB = g & 1;
    const int sB7 = rB & 7;

#define LOAD_STAGE(s, c_)                                                      \
    do {                                                                       \
        int k0_ = (c_) * 64;                                                   \
        uint32_t dA = sbase + (s) * STAGE_BYTES + stoff;                       \
        const uint16_t* ga = gA0 + k0_;                                        \
        _Pragma("unroll")                                                      \
        for (int i = 0; i < 8; i++)                                            \
            cp16(dA + i * 2048, ga + (size_t)i * 16 * ldA);                    \
        uint32_t dB = sbase + (s) * STAGE_BYTES + 16384 + stoff;               \
        const uint16_t* gb = gB0 + k0_;                                        \
        _Pragma("unroll")                                                      \
        for (int i = 0; i < 8; i++)                                            \
            cp16(dB + i * 2048, gb + (size_t)i * 16 * ldB);                    \
        asm volatile("cp.async.commit_group;" ::: "memory");                   \
    } while (0)

    LOAD_STAGE(0, 0);
    LOAD_STAGE(1, 1);

    for (int c = 0; c < nchunks; c++) {
        if (c + 2 < nchunks) {
            asm volatile("cp.async.wait_group 1;" ::: "memory");
        } else {
            asm volatile("cp.async.wait_group 0;" ::: "memory");
        }
        __syncthreads();
        if (c + 2 < nchunks) {
            int s2 = (c + 2) % 3;
            LOAD_STAGE(s2, c + 2);
        }

        const uint32_t aB = sbase + (c % 3) * STAGE_BYTES;
        const uint32_t bB = aB + 16384;
        #pragma unroll
        for (int ks = 0; ks < 4; ks++) {
            uint32_t a[4][4];
            #pragma unroll
            for (int mi = 0; mi < 4; mi++) {
                uint32_t addr = aB + (uint32_t)(rA + mi * 16) * 128 +
                                (uint32_t)(((2 * ks + chA) ^ sA7) << 4);
                ldsm4(a[mi], addr);
            }
            uint32_t b[4][4];
            #pragma unroll
            for (int ng = 0; ng < 4; ng++) {
                uint32_t addr = bB + (uint32_t)(rB + ng * 16) * 128 +
                                (uint32_t)(((2 * ks + chB) ^ sB7) << 4);
                ldsm4(b[ng], addr);
            }
            #pragma unroll
            for (int mi = 0; mi < 4; mi++)
                #pragma unroll
                for (int ni = 0; ni < 8; ni++)
                    mma_f16(acc[mi][ni], a[mi],
                            b[ni >> 1][(ni & 1) * 2],
                            b[ni >> 1][(ni & 1) * 2 + 1]);
        }
        if (WSCALE && (c == CEND0 || c == CEND1)) {
            #pragma unroll
            for (int mi = 0; mi < 4; mi++)
                #pragma unroll
                for (int ni = 0; ni < 8; ni++)
                    #pragma unroll
                    for (int r = 0; r < 4; r++) {
                        float rt = (c == CEND0) ? r01[mi][r >> 1]
                                                : r12[mi][r >> 1];
                        acc[mi][ni][r] *= rt;
                    }
        }
        // no trailing sync: slot (c+2)%3 overwritten only after next-iter sync
    }
#undef LOAD_STAGE

    // fused BN batch-stats: per-column sum/sumsq over this CTA's 128 rows
    if (STATS) {
        #pragma unroll
        for (int ni = 0; ni < 8; ni++) {
            float s0 = 0.f, s1 = 0.f, q0 = 0.f, q1 = 0.f;
            #pragma unroll
            for (int mi = 0; mi < 4; mi++)
                #pragma unroll
                for (int r = 0; r < 4; r++) {
                    float v = acc[mi][ni][r];
                    if (r & 1) { s1 += v; q1 = fmaf(v, v, q1); }
                    else       { s0 += v; q0 = fmaf(v, v, q0); }
                }
            #pragma unroll
            for (int o = 16; o >= 4; o >>= 1) {
                s0 += __shfl_down_sync(0xffffffffu, s0, o);
                s1 += __shfl_down_sync(0xffffffffu, s1, o);
                q0 += __shfl_down_sync(0xffffffffu, q0, o);
                q1 += __shfl_down_sync(0xffffffffu, q1, o);
            }
            if (lane < 4) {
                int col = bn + wn * 64 + ni * 8 + lane * 2;
                if (col < statsC) {
                    atomicAdd(&stats[col], s0);
                    atomicAdd(&stats[statsC + col], q0);
                }
                if (col + 1 < statsC) {
                    atomicAdd(&stats[col + 1], s1);
                    atomicAdd(&stats[statsC + col + 1], q1);
                }
            }
        }
    }

    #pragma unroll
    for (int mi = 0; mi < 4; mi++) {
        int row = bm + wm * 64 + mi * 16 + erow;
        #pragma unroll
        for (int ni = 0; ni < 8; ni++) {
            int col = bn + wn * 64 + ni * 8 + ecol;
            float s0 = WSCALE ? wfin[mi][0] : 1.f;
            float s1 = WSCALE ? wfin[mi][1] : 1.f;
            if (OUT16) {
                __half* C16 = reinterpret_cast<__half*>(C);
                __half2 v0 = __floats2half2_rn(acc[mi][ni][0] * s0,
                                               acc[mi][ni][1] * s0);
                __half2 v1 = __floats2half2_rn(acc[mi][ni][2] * s1,
                                               acc[mi][ni][3] * s1);
                *reinterpret_cast<__half2*>(C16 + (size_t)row * ldC + col) = v0;
                *reinterpret_cast<__half2*>(C16 + (size_t)(row + 8) * ldC + col) = v1;
            } else {
                float2 v0 = make_float2(acc[mi][ni][0] * s0, acc[mi][ni][1] * s0);
                float2 v1 = make_float2(acc[mi][ni][2] * s1, acc[mi][ni][3] * s1);
                *reinterpret_cast<float2*>(C + (size_t)row * ldC + col) = v0;
                *reinterpret_cast<float2*>(C + (size_t)(row + 8) * ldC + col) = v1;
            }
        }
    }
}

// ---------------- conversions ----------------
// A: plain fp16 of [x0 | x1 | xib]  (router-independent, unscaled)
__global__ void convert_A_kernel(const float* __restrict__ x0,
                                 const float* __restrict__ x1,
                                 const float* __restrict__ xib) {
    const int K4 = KCAT / 4;   // 704
    const int total = BATCH * K4;
    for (int idx = blockIdx.x * blockDim.x + threadIdx.x; idx < total;
         idx += gridDim.x * blockDim.x) {
        int b = idx / K4;
        int c = (idx - b * K4) * 4;
        float4 v;
        if (c < D0)
            v = *reinterpret_cast<const float4*>(x0 + (size_t)b * D0 + c);
        else if (c < D0 + D1)
            v = *reinterpret_cast<const float4*>(x1 + (size_t)b * D1 + (c - D0));
        else
            v = *reinterpret_cast<const float4*>(xib + (size_t)b * DIB + (c - D0 - D1));
        __half2 h0 = __floats2half2_rn(v.x, v.y);
        __half2 h1 = __floats2half2_rn(v.z, v.w);
        uint2 u;
        u.x = *reinterpret_cast<uint32_t*>(&h0);
        u.y = *reinterpret_cast<uint32_t*>(&h1);
        *reinterpret_cast<uint2*>(g_A + (size_t)b * KCAT + c) = u;
    }
}

// B for big GEMM: average 7 experts, transpose to [n][k], fp16
__global__ void convert_B_kernel(const float* __restrict__ pW0,
                                 const float* __restrict__ pW1,
                                 const float* __restrict__ pWib) {
    __shared__ float t[32][33];
    const int k0 = blockIdx.x * 32;
    const int n0 = blockIdx.y * 32;
    const int tx = threadIdx.x, ty = threadIdx.y;
    for (int kl = ty; kl < 32; kl += 8) {
        int k = k0 + kl;
        const float* src; int lr, ld;
        if (k < D0)            { src = pW0;  lr = k;            ld = D0;  }
        else if (k < D0 + D1)  { src = pW1;  lr = k - D0;       ld = D1;  }
        else                   { src = pWib; lr = k - D0 - D1;  ld = DIB; }
        const float* p = src + (size_t)lr * DOUT + n0 + tx;
        const size_t es = (size_t)ld * DOUT;
        float s = 0.f;
        #pragma unroll
        for (int e = 0; e < NEXP; e++) s += p[(size_t)e * es];
        t[kl][tx] = s * (1.0f / 7.0f);
    }
    __syncthreads();
    for (int nl = ty; nl < 32; nl += 8)
        g_B[(size_t)(n0 + nl) * KCAT + k0 + tx] = __float2half(t[tx][nl]);
}

// B1: transpose rw1[1024,512] to [n][k], fp16
__global__ void convert_B1_kernel(const float* __restrict__ rw1) {
    __shared__ float t[32][33];
    const int k0 = blockIdx.x * 32;
    const int n0 = blockIdx.y * 32;
    const int tx = threadIdx.x, ty = threadIdx.y;
    for (int kl = ty; kl < 32; kl += 8)
        t[kl][tx] = rw1[(size_t)(k0 + kl) * H1C + n0 + tx];
    __syncthreads();
    for (int nl = ty; nl < 32; nl += 8)
        g_B1[(size_t)(n0 + nl) * D0 + k0 + tx] = __float2half(t[tx][nl]);
}

// B2: transpose rw2[512,100] to [n][k] fp16, padded to 128 rows (zeros)
__global__ void convert_B2_kernel(const float* __restrict__ rw2) {
    __shared__ float t[32][33];
    const int k0 = blockIdx.x * 32;
    const int n0 = blockIdx.y * 32;
    const int tx = threadIdx.x, ty = threadIdx.y;
    for (int kl = ty; kl < 32; kl += 8) {
        int n = n0 + tx;
        t[kl][tx] = (n < H2C) ? rw2[(size_t)(k0 + kl) * H2C + n] : 0.f;
    }
    __syncthreads();
    for (int nl = ty; nl < 32; nl += 8)
        g_B2[(size_t)(n0 + nl) * H1C + k0 + tx] = __float2half(t[tx][nl]);
}

// ---------------- misc small kernels ----------------
// merged: zero BN-stat accumulators + average projection biases
__global__ void init_kernel(const float* __restrict__ pb0,
                            const float* __restrict__ pb1,
                            const float* __restrict__ pbib) {
    int i = blockIdx.x * blockDim.x + threadIdx.x;
    if (i < 2 * H1C) g_stats1[i] = 0.0f;
    if (i < 2 * H2C) g_stats2[i] = 0.0f;
    if (i < 3 * DOUT) {
        int s = i / DOUT, n = i - s * DOUT;
        const float* pb = (s == 0) ? pb0 : (s == 1) ? pb1 : pbib;
        float a = 0.f;
        #pragma unroll
        for (int e = 0; e < NEXP; e++) a += pb[e * DOUT + n];
        g_bavg[i] = a * (1.0f / 7.0f);
    }
}

// BN + ReLU in place on fp16 h1
__global__ void bn_relu_h1_kernel(const float* __restrict__ gamma,
                                  const float* __restrict__ beta) {
    const int total = BATCH * H1C;
    const float invB = 1.0f / (float)BATCH;
    for (int i = blockIdx.x * blockDim.x + threadIdx.x; i < total;
         i += gridDim.x * blockDim.x) {
        int c = i & (H1C - 1);
        float mean = g_stats1[c] * invB;
        float var  = g_stats1[H1C + c] * invB - mean * mean;
        float inv  = rsqrtf(var + 1e-5f);
        float v = __half2float(g_h1h[i]);
        v = gamma[c] * (v - mean) * inv + beta[c];
        g_h1h[i] = __float2half(fmaxf(v, 0.f));
    }
}

__global__ void router_final_kernel(const float* __restrict__ rg2,
                                    const float* __restrict__ rbt2,
                                    const float* __restrict__ rw3,
                                    const float* __restrict__ rb3) {
    int warp = (blockIdx.x * blockDim.x + threadIdx.x) >> 5;
    int lane = threadIdx.x & 31;
    if (warp >= BATCH) return;
    const float invB = 1.0f / (float)BATCH;
    float d0 = 0.f, d1 = 0.f, d2 = 0.f;
    for (int c = lane; c < H2C; c += 32) {
        float mean = g_stats2[c] * invB;
        float var  = g_stats2[H2C + c] * invB - mean * mean;
        float v = g_h2[(size_t)warp * H2P + c];
        v = rg2[c] * (v - mean) * rsqrtf(var + 1e-5f) + rbt2[c];
        v = tanhf(v);
        d0 = fmaf(v, rw3[c * 3 + 0], d0);
        d1 = fmaf(v, rw3[c * 3 + 1], d1);
        d2 = fmaf(v, rw3[c * 3 + 2], d2);
    }
    #pragma unroll
    for (int o = 16; o > 0; o >>= 1) {
        d0 += __shfl_down_sync(0xffffffffu, d0, o);
        d1 += __shfl_down_sync(0xffffffffu, d1, o);
        d2 += __shfl_down_sync(0xffffffffu, d2, o);
    }
    if (lane == 0) {
        float l0 = 1.f / (1.f + __expf(-(d0 + rb3[0])));
        float l1 = 1.f / (1.f + __expf(-(d1 + rb3[1])));
        float l2 = 1.f / (1.f + __expf(-(d2 + rb3[2])));
        float mx = fmaxf(l0, fmaxf(l1, l2));
        float e0 = __expf(l0 - mx), e1 = __expf(l1 - mx), e2 = __expf(l2 - mx);
        float inv = 1.f / (e0 + e1 + e2);
        g_w[warp * 3 + 0] = e0 * inv;
        g_w[warp * 3 + 1] = e1 * inv;
        g_w[warp * 3 + 2] = e2 * inv;
    }
}

__global__ void normalize_rows_kernel(float* __restrict__ out) {
    int b = blockIdx.x;
    int t = threadIdx.x;
    float w0 = g_w[b * 3 + 0], w1 = g_w[b * 3 + 1], w2 = g_w[b * 3 + 2];
    float vals[6];
    float ss = 0.f;
    #pragma unroll
    for (int j = 0; j < 6; j++) {
        int n = t + j * 256;
        float v = out[(size_t)b * DOUT + n];
        v += w0 * g_bavg[n] + w1 * g_bavg[DOUT + n] + w2 * g_bavg[2 * DOUT + n];
        vals[j] = v;
        ss = fmaf(v, v, ss);
    }
    __shared__ float red[256];
    red[t] = ss;
    __syncthreads();
    #pragma unroll
    for (int s2 = 128; s2 > 0; s2 >>= 1) {
        if (t < s2) red[t] += red[t + s2];
        __syncthreads();
    }
    float inv = 1.f / fmaxf(sqrtf(red[0]), 1e-12f);
    #pragma unroll
    for (int j = 0; j < 6; j++)
        out[(size_t)b * DOUT + t + j * 256] = vals[j] * inv;
}

// ---------------- launch ----------------
extern "C" void kernel_launch(void* const* d_in, const int* in_sizes, int n_in,
                              void* d_out, int out_size) {
    const float* x0   = (const float*)d_in[0];
    const float* x1   = (const float*)d_in[1];
    const float* xib  = (const float*)d_in[2];
    const float* pW0  = (const float*)d_in[3];
    const float* pb0  = (const float*)d_in[4];
    const float* pW1  = (const float*)d_in[5];
    const float* pb1  = (const float*)d_in[6];
    const float* pWib = (const float*)d_in[7];
    const float* pbib = (const float*)d_in[8];
    const float* rw1  = (const float*)d_in[9];
    // rb1 (d_in[10]) cancels exactly under batch-norm — skipped
    const float* rg1  = (const float*)d_in[11];
    const float* rbt1 = (const float*)d_in[12];
    const float* rw2  = (const float*)d_in[13];
    // rb2 (d_in[14]) also cancels under batch-norm — skipped
    const float* rg2  = (const float*)d_in[15];
    const float* rbt2 = (const float*)d_in[16];
    const float* rw3  = (const float*)d_in[17];
    const float* rb3  = (const float*)d_in[18];
    float* out = (float*)d_out;
    (void)in_sizes; (void)n_in; (void)out_size;

    void *a_p, *b_p, *b1_p, *b2_p, *h1h_p, *h2_p, *s1_p, *s2_p, *w_p;
    cudaGetSymbolAddress(&a_p,   g_A);
    cudaGetSymbolAddress(&b_p,   g_B);
    cudaGetSymbolAddress(&b1_p,  g_B1);
    cudaGetSymbolAddress(&b2_p,  g_B2);
    cudaGetSymbolAddress(&h1h_p, g_h1h);
    cudaGetSymbolAddress(&h2_p,  g_h2);
    cudaGetSymbolAddress(&s1_p,  g_stats1);
    cudaGetSymbolAddress(&s2_p,  g_stats2);
    cudaGetSymbolAddress(&w_p,   g_w);
    const uint16_t* Ab  = (const uint16_t*)a_p;
    const uint16_t* Bb  = (const uint16_t*)b_p;
    const uint16_t* B1h = (const uint16_t*)b1_p;
    const uint16_t* B2h = (const uint16_t*)b2_p;
    const uint16_t* H1u = (const uint16_t*)h1h_p;
    float* h1f = (float*)h1h_p;   // reinterpreted for OUT16 GEMM param
    float* h2  = (float*)h2_p;
    float* st1 = (float*)s1_p;
    float* st2 = (float*)s2_p;
    const float* Wp = (const float*)w_p;

    cudaFuncSetAttribute((const void*)hmma_gemm_kernel<true, false, true>,
                         cudaFuncAttributeMaxDynamicSharedMemorySize, HM_SMEM);
    cudaFuncSetAttribute((const void*)hmma_gemm_kernel<false, false, true>,
                         cudaFuncAttributeMaxDynamicSharedMemorySize, HM_SMEM);
    cudaFuncSetAttribute((const void*)hmma_gemm_kernel<false, true, false>,
                         cudaFuncAttributeMaxDynamicSharedMemorySize, HM_SMEM);

    // side stream + fork/join events (created once; identical work every call)
    static cudaStream_t sB = nullptr;
    static cudaEvent_t  eFork = nullptr, eJoin = nullptr;
    if (sB == nullptr) {
        cudaStreamCreateWithFlags(&sB, cudaStreamNonBlocking);
        cudaEventCreateWithFlags(&eFork, cudaEventDisableTiming);
        cudaEventCreateWithFlags(&eJoin, cudaEventDisableTiming);
    }

    init_kernel<<<(3 * DOUT + 255) / 256, 256>>>(pb0, pb1, pbib);

    // conversions needed by the router chain (main stream)
    convert_A_kernel <<<8192, 256>>>(x0, x1, xib);
    convert_B1_kernel<<<dim3(D0 / 32, H1C / 32),  dim3(32, 8)>>>(rw1);
    convert_B2_kernel<<<dim3(H1C / 32, H2P / 32), dim3(32, 8)>>>(rw2);

    // fork: expert-weight conversion overlaps with the router chain
    cudaEventRecord(eFork, 0);
    cudaStreamWaitEvent(sB, eFork, 0);
    convert_B_kernel<<<dim3(KCAT / 32, DOUT / 32), dim3(32, 8), 0, sB>>>(
        pW0, pW1, pWib);
    cudaEventRecord(eJoin, sB);

    // router layer 1 (fp16 HMMA, fp16 out, fused column stats): h1 = x0 @ rw1
    hmma_gemm_kernel<true, false, true>
        <<<dim3(H1C / 128, BATCH / 128), 128, HM_SMEM>>>(
        Ab, B1h, h1f, nullptr, st1, H1C, KCAT, D0, H1C, D0 / 64);
    bn_relu_h1_kernel<<<4096, 256>>>(rg1, rbt1);

    // router layer 2 (fp16 HMMA, fused stats over first 100 cols)
    hmma_gemm_kernel<false, false, true>
        <<<dim3(H2P / 128, BATCH / 128), 128, HM_SMEM>>>(
        H1u, B2h, h2, nullptr, st2, H2C, H1C, H1C, H2P, H1C / 64);
    router_final_kernel<<<BATCH * 32 / 256, 256>>>(rg2, rbt2, rw3, rb3);

    // join: big GEMM needs g_B
    cudaStreamWaitEvent(0, eJoin, 0);

    // big GEMM (plain fp16) with per-row MoE weighting in the epilogue
    hmma_gemm_kernel<false, true, false>
        <<<dim3(DOUT / 128, BATCH / 128), 128, HM_SMEM>>>(
        Ab, Bb, out, Wp, nullptr, 0, KCAT, KCAT, DOUT, NC_BIG);

    normalize_rows_kernel<<<BATCH, 256>>>(out);
}

// round 15
// speedup vs baseline: 2.6333x; 1.0182x over previous
#include <cuda_runtime.h>
#include <cuda_bf16.h>
#include <cuda_fp16.h>
#include <cstdint>
#include <math.h>

// ---------------- problem constants ----------------
#define BATCH   8192
#define D0      1024
#define D1      768
#define DIB     1024
#define KCAT    2816        // D0 + D1 + DIB
#define DOUT    1536
#define H1C     512
#define H2C     100
#define H2P     128         // padded N for layer-2 GEMM
#define NEXP    7

#define NC_BIG  (KCAT/64)   // 44 chunks
#define CEND0   15          // last chunk of x0 segment (1024/64 - 1)
#define CEND1   27          // last chunk of x1 segment (+768/64)

// ---------------- device scratch (no allocations allowed) ----------------
__device__ __half g_A  [(size_t)BATCH * KCAT];    // 46 MB  fp16 [x0|x1|xib] UNSCALED
__device__ __half g_B  [(size_t)DOUT  * KCAT];    // 8.7 MB [n][k] K-major, fp16
__device__ __half g_B1 [(size_t)H1C   * D0];      // 1 MB   rw1^T fp16
__device__ __half g_B2 [(size_t)H2P   * H1C];     // 128 KB rw2^T fp16 (padded)
__device__ __half g_h1h[BATCH * H1C];             // fp16 h1 (pre-BN)
__device__ float  g_h2 [BATCH * H2P];
__device__ float  g_stats1[2 * H1C];
__device__ float  g_stats2[2 * H2C];
__device__ float  g_w   [BATCH * 3];
__device__ float  g_bavg[3 * DOUT];
__device__ __half g_bnAa[H1C];                    // fused-BN scale (fp16)
__device__ __half g_bnAb[H1C];                    // fused-BN shift (fp16)

// ---------------- PTX helpers (base-target safe: sm_80+ ISA only) ------------
__device__ __forceinline__ uint32_t smem_u32(const void* p) {
    uint32_t a;
    asm("{ .reg .u64 t; cvta.to.shared.u64 t, %1; cvt.u32.u64 %0, t; }"
        : "=r"(a) : "l"(p));
    return a;
}
__device__ __forceinline__ void cp16(uint32_t saddr, const void* g) {
    asm volatile("cp.async.cg.shared.global [%0], [%1], 16;"
                 :: "r"(saddr), "l"(g));
}
__device__ __forceinline__ void ldsm4(uint32_t* r, uint32_t addr) {
    asm volatile("ldmatrix.sync.aligned.m8n8.x4.shared.b16 {%0,%1,%2,%3}, [%4];"
                 : "=r"(r[0]), "=r"(r[1]), "=r"(r[2]), "=r"(r[3]) : "r"(addr));
}
__device__ __forceinline__ void mma_f16(float* c, const uint32_t* a,
                                        uint32_t b0, uint32_t b1) {
    asm volatile(
        "mma.sync.aligned.m16n8k16.row.col.f32.f16.f16.f32 "
        "{%0,%1,%2,%3}, {%4,%5,%6,%7}, {%8,%9}, {%0,%1,%2,%3};"
        : "+f"(c[0]), "+f"(c[1]), "+f"(c[2]), "+f"(c[3])
        : "r"(a[0]), "r"(a[1]), "r"(a[2]), "r"(a[3]), "r"(b0), "r"(b1));
}

// ---------------- HMMA fp16 GEMM: C[M,N] = A[M,K] @ B[N,K]^T -----------------
// CTA 128x128, BK=64, 3-stage cp.async pipeline (96 KB smem, 2 CTA/SM),
// 4 warps 2(m) x 2(n), warp tile 64x64, mma.sync.m16n8k16.
// WSCALE: per-row MoE weighting via segment-boundary accumulator rescale.
// OUT16 : write __half output.
// STATS : per-column sum/sumsq atomically accumulated into `stats`.
// BNA   : apply per-k affine+ReLU to A fragments after ldmatrix (fused BN).
//         A frag k map (m16n8k16): regs 0,1 -> k=(lane&3)*2+{0,1};
//         regs 2,3 -> k+8; slab base = chunk*64 + ks*16.
#define STAGE_BYTES 32768               // A 16KB + B 16KB
#define HM_SMEM     (3 * STAGE_BYTES)   // 98304

template<bool OUT16, bool WSCALE, bool STATS, bool BNA>
__global__ void __launch_bounds__(128, 2)
hmma_gemm_kernel(const uint16_t* __restrict__ A,
                 const uint16_t* __restrict__ B,
                 float* __restrict__ C,
                 const float* __restrict__ W,
                 float* __restrict__ stats, int statsC,
                 const __half2* __restrict__ bnAa,
                 const __half2* __restrict__ bnAb,
                 int ldA, int ldB, int ldC, int nchunks) {
    extern __shared__ char smem[];
    const uint32_t sbase = smem_u32(smem);
    const int tid  = threadIdx.x;
    const int lane = tid & 31;
    const int wid  = tid >> 5;          // 0..3
    const int wm   = wid & 1;
    const int wn   = wid >> 1;
    const int bm   = blockIdx.y * 128;
    const int bn   = blockIdx.x * 128;
    const int erow = lane >> 2;
    const int ecol = (lane & 3) * 2;

    const int srow = tid >> 3;          // 0..15
    const int scol = tid & 7;           // 16B unit
    const uint32_t stoff = (uint32_t)srow * 128 +
                           (uint32_t)((scol ^ (srow & 7)) << 4);
    const uint16_t* gA0 = A + (size_t)(bm + srow) * ldA + scol * 8;
    const uint16_t* gB0 = B + (size_t)(bn + srow) * ldB + scol * 8;

    // per-row router-weight ratios (WSCALE only)
    float r01[4][2], r12[4][2], wfin[4][2];
    if (WSCALE) {
        #pragma unroll
        for (int mi = 0; mi < 4; mi++)
            #pragma unroll
            for (int h = 0; h < 2; h++) {
                int row = bm + wm * 64 + mi * 16 + erow + h * 8;
                float w0 = W[row * 3 + 0];
                float w1 = W[row * 3 + 1];
                float w2 = W[row * 3 + 2];
                r01[mi][h]  = w0 / w1;
                r12[mi][h]  = w1 / w2;
                wfin[mi][h] = w2;
            }
    }

    float acc[4][8][4];
    #pragma unroll
    for (int i = 0; i < 4; i++)
        #pragma unroll
        for (int j = 0; j < 8; j++)
            #pragma unroll
            for (int r = 0; r < 4; r++) acc[i][j][r] = 0.f;

    const int g  = lane >> 3;
    const int lr = lane & 7;
    const int rA  = wm * 64 + lr + (g & 1) * 8;
    const int chA = g >> 1;
    const int sA7 = rA & 7;
    const int rB  = wn * 64 + lr + (g >> 1) * 8;
    const int chB = g & 1;
    const int sB7 = rB & 7;

#define LOAD_STAGE(s, c_)                                                      \
    do {                                                                       \
        int k0_ = (c_) * 64;                                                   \
        uint32_t dA = sbase + (s) * STAGE_BYTES + stoff;                       \
        const uint16_t* ga = gA0 + k0_;                                        \
        _Pragma("unroll")                                                      \
        for (int i = 0; i < 8; i++)                                            \
            cp16(dA + i * 2048, ga + (size_t)i * 16 * ldA);                    \
        uint32_t dB = sbase + (s) * STAGE_BYTES + 16384 + stoff;               \
        const uint16_t* gb = gB0 + k0_;                                        \
        _Pragma("unroll")                                                      \
        for (int i = 0; i < 8; i++)                                            \
            cp16(dB + i * 2048, gb + (size_t)i * 16 * ldB);                    \
        asm volatile("cp.async.commit_group;" ::: "memory");                   \
    } while (0)

    LOAD_STAGE(0, 0);
    LOAD_STAGE(1, 1);

    for (int c = 0; c < nchunks; c++) {
        if (c + 2 < nchunks) {
            asm volatile("cp.async.wait_group 1;" ::: "memory");
        } else {
            asm volatile("cp.async.wait_group 0;" ::: "memory");
        }
        __syncthreads();
        if (c + 2 < nchunks) {
            int s2 = (c + 2) % 3;
            LOAD_STAGE(s2, c + 2);
        }

        const uint32_t aB = sbase + (c % 3) * STAGE_BYTES;
        const uint32_t bB = aB + 16384;
        #pragma unroll
        for (int ks = 0; ks < 4; ks++) {
            __half2 al_lo, be_lo, al_hi, be_hi;
            if (BNA) {
                int kk = (c * 64 + ks * 16 + (lane & 3) * 2) >> 1;
                al_lo = bnAa[kk];     be_lo = bnAb[kk];
                al_hi = bnAa[kk + 4]; be_hi = bnAb[kk + 4];
            }
            uint32_t a[4][4];
            #pragma unroll
            for (int mi = 0; mi < 4; mi++) {
                uint32_t addr = aB + (uint32_t)(rA + mi * 16) * 128 +
                                (uint32_t)(((2 * ks + chA) ^ sA7) << 4);
                ldsm4(a[mi], addr);
                if (BNA) {
                    const __half2 z = __floats2half2_rn(0.f, 0.f);
                    __half2* ah = reinterpret_cast<__half2*>(a[mi]);
                    ah[0] = __hmax2(__hfma2(ah[0], al_lo, be_lo), z);
                    ah[1] = __hmax2(__hfma2(ah[1], al_lo, be_lo), z);
                    ah[2] = __hmax2(__hfma2(ah[2], al_hi, be_hi), z);
                    ah[3] = __hmax2(__hfma2(ah[3], al_hi, be_hi), z);
                }
            }
            uint32_t b[4][4];
            #pragma unroll
            for (int ng = 0; ng < 4; ng++) {
                uint32_t addr = bB + (uint32_t)(rB + ng * 16) * 128 +
                                (uint32_t)(((2 * ks + chB) ^ sB7) << 4);
                ldsm4(b[ng], addr);
            }
            #pragma unroll
            for (int mi = 0; mi < 4; mi++)
                #pragma unroll
                for (int ni = 0; ni < 8; ni++)
                    mma_f16(acc[mi][ni], a[mi],
                            b[ni >> 1][(ni & 1) * 2],
                            b[ni >> 1][(ni & 1) * 2 + 1]);
        }
        if (WSCALE && (c == CEND0 || c == CEND1)) {
            #pragma unroll
            for (int mi = 0; mi < 4; mi++)
                #pragma unroll
                for (int ni = 0; ni < 8; ni++)
                    #pragma unroll
                    for (int r = 0; r < 4; r++) {
                        float rt = (c == CEND0) ? r01[mi][r >> 1]
                                                : r12[mi][r >> 1];
                        acc[mi][ni][r] *= rt;
                    }
        }
        // no trailing sync: slot (c+2)%3 overwritten only after next-iter sync
    }
#undef LOAD_STAGE

    // fused BN batch-stats: per-column sum/sumsq over this CTA's 128 rows
    if (STATS) {
        #pragma unroll
        for (int ni = 0; ni < 8; ni++) {
            float s0 = 0.f, s1 = 0.f, q0 = 0.f, q1 = 0.f;
            #pragma unroll
            for (int mi = 0; mi < 4; mi++)
                #pragma unroll
                for (int r = 0; r < 4; r++) {
                    float v = acc[mi][ni][r];
                    if (r & 1) { s1 += v; q1 = fmaf(v, v, q1); }
                    else       { s0 += v; q0 = fmaf(v, v, q0); }
                }
            #pragma unroll
            for (int o = 16; o >= 4; o >>= 1) {
                s0 += __shfl_down_sync(0xffffffffu, s0, o);
                s1 += __shfl_down_sync(0xffffffffu, s1, o);
                q0 += __shfl_down_sync(0xffffffffu, q0, o);
                q1 += __shfl_down_sync(0xffffffffu, q1, o);
            }
            if (lane < 4) {
                int col = bn + wn * 64 + ni * 8 + lane * 2;
                if (col < statsC) {
                    atomicAdd(&stats[col], s0);
                    atomicAdd(&stats[statsC + col], q0);
                }
                if (col + 1 < statsC) {
                    atomicAdd(&stats[col + 1], s1);
                    atomicAdd(&stats[statsC + col + 1], q1);
                }
            }
        }
    }

    #pragma unroll
    for (int mi = 0; mi < 4; mi++) {
        int row = bm + wm * 64 + mi * 16 + erow;
        #pragma unroll
        for (int ni = 0; ni < 8; ni++) {
            int col = bn + wn * 64 + ni * 8 + ecol;
            float s0 = WSCALE ? wfin[mi][0] : 1.f;
            float s1 = WSCALE ? wfin[mi][1] : 1.f;
            if (OUT16) {
                __half* C16 = reinterpret_cast<__half*>(C);
                __half2 v0 = __floats2half2_rn(acc[mi][ni][0] * s0,
                                               acc[mi][ni][1] * s0);
                __half2 v1 = __floats2half2_rn(acc[mi][ni][2] * s1,
                                               acc[mi][ni][3] * s1);
                *reinterpret_cast<__half2*>(C16 + (size_t)row * ldC + col) = v0;
                *reinterpret_cast<__half2*>(C16 + (size_t)(row + 8) * ldC + col) = v1;
            } else {
                float2 v0 = make_float2(acc[mi][ni][0] * s0, acc[mi][ni][1] * s0);
                float2 v1 = make_float2(acc[mi][ni][2] * s1, acc[mi][ni][3] * s1);
                *reinterpret_cast<float2*>(C + (size_t)row * ldC + col) = v0;
                *reinterpret_cast<float2*>(C + (size_t)(row + 8) * ldC + col) = v1;
            }
        }
    }
}

// ---------------- conversions ----------------
// A: plain fp16 of columns [c4_begin*4, (c4_begin+c4_count)*4) of [x0|x1|xib]
__global__ void convert_A_kernel(const float* __restrict__ x0,
                                 const float* __restrict__ x1,
                                 const float* __restrict__ xib,
                                 int c4_begin, int c4_count) {
    const int total = BATCH * c4_count;
    for (int idx = blockIdx.x * blockDim.x + threadIdx.x; idx < total;
         idx += gridDim.x * blockDim.x) {
        int b = idx / c4_count;
        int c = (c4_begin + (idx - b * c4_count)) * 4;
        float4 v;
        if (c < D0)
            v = *reinterpret_cast<const float4*>(x0 + (size_t)b * D0 + c);
        else if (c < D0 + D1)
            v = *reinterpret_cast<const float4*>(x1 + (size_t)b * D1 + (c - D0));
        else
            v = *reinterpret_cast<const float4*>(xib + (size_t)b * DIB + (c - D0 - D1));
        __half2 h0 = __floats2half2_rn(v.x, v.y);
        __half2 h1 = __floats2half2_rn(v.z, v.w);
        uint2 u;
        u.x = *reinterpret_cast<uint32_t*>(&h0);
        u.y = *reinterpret_cast<uint32_t*>(&h1);
        *reinterpret_cast<uint2*>(g_A + (size_t)b * KCAT + c) = u;
    }
}

// B for big GEMM: average 7 experts, transpose to [n][k], fp16
__global__ void convert_B_kernel(const float* __restrict__ pW0,
                                 const float* __restrict__ pW1,
                                 const float* __restrict__ pWib) {
    __shared__ float t[32][33];
    const int k0 = blockIdx.x * 32;
    const int n0 = blockIdx.y * 32;
    const int tx = threadIdx.x, ty = threadIdx.y;
    for (int kl = ty; kl < 32; kl += 8) {
        int k = k0 + kl;
        const float* src; int lr, ld;
        if (k < D0)            { src = pW0;  lr = k;            ld = D0;  }
        else if (k < D0 + D1)  { src = pW1;  lr = k - D0;       ld = D1;  }
        else                   { src = pWib; lr = k - D0 - D1;  ld = DIB; }
        const float* p = src + (size_t)lr * DOUT + n0 + tx;
        const size_t es = (size_t)ld * DOUT;
        float s = 0.f;
        #pragma unroll
        for (int e = 0; e < NEXP; e++) s += p[(size_t)e * es];
        t[kl][tx] = s * (1.0f / 7.0f);
    }
    __syncthreads();
    for (int nl = ty; nl < 32; nl += 8)
        g_B[(size_t)(n0 + nl) * KCAT + k0 + tx] = __float2half(t[tx][nl]);
}

// merged: B1 = rw1^T (512 tiles) then B2 = rw2^T padded (64 tiles)
#define B1_TILES ((D0 / 32) * (H1C / 32))   // 512
#define B2_TILES ((H1C / 32) * (H2P / 32))  // 64
__global__ void convert_B12_kernel(const float* __restrict__ rw1,
                                   const float* __restrict__ rw2) {
    __shared__ float t[32][33];
    const int tx = threadIdx.x, ty = threadIdx.y;
    int bx = blockIdx.x;
    if (bx < B1_TILES) {
        const int k0 = (bx % (D0 / 32)) * 32;
        const int n0 = (bx / (D0 / 32)) * 32;
        for (int kl = ty; kl < 32; kl += 8)
            t[kl][tx] = rw1[(size_t)(k0 + kl) * H1C + n0 + tx];
        __syncthreads();
        for (int nl = ty; nl < 32; nl += 8)
            g_B1[(size_t)(n0 + nl) * D0 + k0 + tx] = __float2half(t[tx][nl]);
    } else {
        bx -= B1_TILES;
        const int k0 = (bx % (H1C / 32)) * 32;
        const int n0 = (bx / (H1C / 32)) * 32;
        for (int kl = ty; kl < 32; kl += 8) {
            int n = n0 + tx;
            t[kl][tx] = (n < H2C) ? rw2[(size_t)(k0 + kl) * H2C + n] : 0.f;
        }
        __syncthreads();
        for (int nl = ty; nl < 32; nl += 8)
            g_B2[(size_t)(n0 + nl) * H1C + k0 + tx] = __float2half(t[tx][nl]);
    }
}

// ---------------- misc small kernels ----------------
// merged: zero BN-stat accumulators + average projection biases
__global__ void init_kernel(const float* __restrict__ pb0,
                            const float* __restrict__ pb1,
                            const float* __restrict__ pbib) {
    int i = blockIdx.x * blockDim.x + threadIdx.x;
    if (i < 2 * H1C) g_stats1[i] = 0.0f;
    if (i < 2 * H2C) g_stats2[i] = 0.0f;
    if (i < 3 * DOUT) {
        int s = i / DOUT, n = i - s * DOUT;
        const float* pb = (s == 0) ? pb0 : (s == 1) ? pb1 : pbib;
        float a = 0.f;
        #pragma unroll
        for (int e = 0; e < NEXP; e++) a += pb[e * DOUT + n];
        g_bavg[i] = a * (1.0f / 7.0f);
    }
}

// fold h1 batch stats + gamma/beta into per-column fp16 affine (alpha, beta)
__global__ void bn_prep_kernel(const float* __restrict__ gamma,
                               const float* __restrict__ beta) {
    int c = blockIdx.x * blockDim.x + threadIdx.x;
    if (c >= H1C) return;
    const float invB = 1.0f / (float)BATCH;
    float mean = g_stats1[c] * invB;
    float var  = g_stats1[H1C + c] * invB - mean * mean;
    float a = gamma[c] * rsqrtf(var + 1e-5f);
    float b = beta[c] - a * mean;
    g_bnAa[c] = __float2half(a);
    g_bnAb[c] = __float2half(b);
}

__global__ void router_final_kernel(const float* __restrict__ rg2,
                                    const float* __restrict__ rbt2,
                                    const float* __restrict__ rw3,
                                    const float* __restrict__ rb3) {
    int warp = (blockIdx.x * blockDim.x + threadIdx.x) >> 5;
    int lane = threadIdx.x & 31;
    if (warp >= BATCH) return;
    const float invB = 1.0f / (float)BATCH;
    float d0 = 0.f, d1 = 0.f, d2 = 0.f;
    for (int c = lane; c < H2C; c += 32) {
        float mean = g_stats2[c] * invB;
        float var  = g_stats2[H2C + c] * invB - mean * mean;
        float v = g_h2[(size_t)warp * H2P + c];
        v = rg2[c] * (v - mean) * rsqrtf(var + 1e-5f) + rbt2[c];
        v = tanhf(v);
        d0 = fmaf(v, rw3[c * 3 + 0], d0);
        d1 = fmaf(v, rw3[c * 3 + 1], d1);
        d2 = fmaf(v, rw3[c * 3 + 2], d2);
    }
    #pragma unroll
    for (int o = 16; o > 0; o >>= 1) {
        d0 += __shfl_down_sync(0xffffffffu, d0, o);
        d1 += __shfl_down_sync(0xffffffffu, d1, o);
        d2 += __shfl_down_sync(0xffffffffu, d2, o);
    }
    if (lane == 0) {
        float l0 = 1.f / (1.f + __expf(-(d0 + rb3[0])));
        float l1 = 1.f / (1.f + __expf(-(d1 + rb3[1])));
        float l2 = 1.f / (1.f + __expf(-(d2 + rb3[2])));
        float mx = fmaxf(l0, fmaxf(l1, l2));
        float e0 = __expf(l0 - mx), e1 = __expf(l1 - mx), e2 = __expf(l2 - mx);
        float inv = 1.f / (e0 + e1 + e2);
        g_w[warp * 3 + 0] = e0 * inv;
        g_w[warp * 3 + 1] = e1 * inv;
        g_w[warp * 3 + 2] = e2 * inv;
    }
}

__global__ void normalize_rows_kernel(float* __restrict__ out) {
    int b = blockIdx.x;
    int t = threadIdx.x;
    float w0 = g_w[b * 3 + 0], w1 = g_w[b * 3 + 1], w2 = g_w[b * 3 + 2];
    float vals[6];
    float ss = 0.f;
    #pragma unroll
    for (int j = 0; j < 6; j++) {
        int n = t + j * 256;
        float v = out[(size_t)b * DOUT + n];
        v += w0 * g_bavg[n] + w1 * g_bavg[DOUT + n] + w2 * g_bavg[2 * DOUT + n];
        vals[j] = v;
        ss = fmaf(v, v, ss);
    }
    __shared__ float red[256];
    red[t] = ss;
    __syncthreads();
    #pragma unroll
    for (int s2 = 128; s2 > 0; s2 >>= 1) {
        if (t < s2) red[t] += red[t + s2];
        __syncthreads();
    }
    float inv = 1.f / fmaxf(sqrtf(red[0]), 1e-12f);
    #pragma unroll
    for (int j = 0; j < 6; j++)
        out[(size_t)b * DOUT + t + j * 256] = vals[j] * inv;
}

// ---------------- launch ----------------
extern "C" void kernel_launch(void* const* d_in, const int* in_sizes, int n_in,
                              void* d_out, int out_size) {
    const float* x0   = (const float*)d_in[0];
    const float* x1   = (const float*)d_in[1];
    const float* xib  = (const float*)d_in[2];
    const float* pW0  = (const float*)d_in[3];
    const float* pb0  = (const float*)d_in[4];
    const float* pW1  = (const float*)d_in[5];
    const float* pb1  = (const float*)d_in[6];
    const float* pWib = (const float*)d_in[7];
    const float* pbib = (const float*)d_in[8];
    const float* rw1  = (const float*)d_in[9];
    // rb1 (d_in[10]) cancels exactly under batch-norm — skipped
    const float* rg1  = (const float*)d_in[11];
    const float* rbt1 = (const float*)d_in[12];
    const float* rw2  = (const float*)d_in[13];
    // rb2 (d_in[14]) also cancels under batch-norm — skipped
    const float* rg2  = (const float*)d_in[15];
    const float* rbt2 = (const float*)d_in[16];
    const float* rw3  = (const float*)d_in[17];
    const float* rb3  = (const float*)d_in[18];
    float* out = (float*)d_out;
    (void)in_sizes; (void)n_in; (void)out_size;

    void *a_p, *b_p, *b1_p, *b2_p, *h1h_p, *h2_p, *s1_p, *s2_p, *w_p;
    void *bna_p, *bnb_p;
    cudaGetSymbolAddress(&a_p,   g_A);
    cudaGetSymbolAddress(&b_p,   g_B);
    cudaGetSymbolAddress(&b1_p,  g_B1);
    cudaGetSymbolAddress(&b2_p,  g_B2);
    cudaGetSymbolAddress(&h1h_p, g_h1h);
    cudaGetSymbolAddress(&h2_p,  g_h2);
    cudaGetSymbolAddress(&s1_p,  g_stats1);
    cudaGetSymbolAddress(&s2_p,  g_stats2);
    cudaGetSymbolAddress(&w_p,   g_w);
    cudaGetSymbolAddress(&bna_p, g_bnAa);
    cudaGetSymbolAddress(&bnb_p, g_bnAb);
    const uint16_t* Ab  = (const uint16_t*)a_p;
    const uint16_t* Bb  = (const uint16_t*)b_p;
    const uint16_t* B1h = (const uint16_t*)b1_p;
    const uint16_t* B2h = (const uint16_t*)b2_p;
    const uint16_t* H1u = (const uint16_t*)h1h_p;
    float* h1f = (float*)h1h_p;   // reinterpreted for OUT16 GEMM param
    float* h2  = (float*)h2_p;
    float* st1 = (float*)s1_p;
    float* st2 = (float*)s2_p;
    const float* Wp = (const float*)w_p;
    const __half2* bnAa = (const __half2*)bna_p;
    const __half2* bnAb = (const __half2*)bnb_p;

    cudaFuncSetAttribute((const void*)hmma_gemm_kernel<true, false, true, false>,
                         cudaFuncAttributeMaxDynamicSharedMemorySize, HM_SMEM);
    cudaFuncSetAttribute((const void*)hmma_gemm_kernel<false, false, true, true>,
                         cudaFuncAttributeMaxDynamicSharedMemorySize, HM_SMEM);
    cudaFuncSetAttribute((const void*)hmma_gemm_kernel<false, true, false, false>,
                         cudaFuncAttributeMaxDynamicSharedMemorySize, HM_SMEM);

    // side stream + fork/join events (created once; identical work every call)
    static cudaStream_t sB = nullptr;
    static cudaEvent_t  eFork = nullptr, eJoin = nullptr;
    if (sB == nullptr) {
        cudaStreamCreateWithFlags(&sB, cudaStreamNonBlocking);
        cudaEventCreateWithFlags(&eFork, cudaEventDisableTiming);
        cudaEventCreateWithFlags(&eJoin, cudaEventDisableTiming);
    }

    // fork immediately: side stream handles work not needed until the big GEMM
    cudaEventRecord(eFork, 0);
    cudaStreamWaitEvent(sB, eFork, 0);
    convert_A_kernel<<<8192, 256, 0, sB>>>(x0, x1, xib,
                                           D0 / 4, (KCAT - D0) / 4);  // x1|xib
    convert_B_kernel<<<dim3(KCAT / 32, DOUT / 32), dim3(32, 8), 0, sB>>>(
        pW0, pW1, pWib);
    cudaEventRecord(eJoin, sB);

    // main stream: router-critical work only
    init_kernel<<<(3 * DOUT + 255) / 256, 256>>>(pb0, pb1, pbib);
    convert_A_kernel <<<4096, 256>>>(x0, x1, xib, 0, D0 / 4);         // x0 only
    convert_B12_kernel<<<B1_TILES + B2_TILES, dim3(32, 8)>>>(rw1, rw2);

    // router layer 1 (fp16 HMMA, fp16 out, fused column stats): h1 = x0 @ rw1
    hmma_gemm_kernel<true, false, true, false>
        <<<dim3(H1C / 128, BATCH / 128), 128, HM_SMEM>>>(
        Ab, B1h, h1f, nullptr, st1, H1C, nullptr, nullptr,
        KCAT, D0, H1C, D0 / 64);
    bn_prep_kernel<<<2, 256>>>(rg1, rbt1);

    // router layer 2 (fp16 HMMA, BN+ReLU fused on A frags, fused stats)
    hmma_gemm_kernel<false, false, true, true>
        <<<dim3(H2P / 128, BATCH / 128), 128, HM_SMEM>>>(
        H1u, B2h, h2, nullptr, st2, H2C, bnAa, bnAb,
        H1C, H1C, H2P, H1C / 64);
    router_final_kernel<<<BATCH * 32 / 256, 256>>>(rg2, rbt2, rw3, rb3);

    // join: big GEMM needs full g_A and g_B
    cudaStreamWaitEvent(0, eJoin, 0);

    // big GEMM (plain fp16) with per-row MoE weighting in the epilogue
    hmma_gemm_kernel<false, true, false, false>
        <<<dim3(DOUT / 128, BATCH / 128), 128, HM_SMEM>>>(
        Ab, Bb, out, Wp, nullptr, 0, nullptr, nullptr,
        KCAT, KCAT, DOUT, NC_BIG);

    normalize_rows_kernel<<<BATCH, 256>>>(out);
}

// round 17
// speedup vs baseline: 2.6355x; 1.0008x over previous
#include <cuda_runtime.h>
#include <cuda_bf16.h>
#include <cuda_fp16.h>
#include <cstdint>
#include <math.h>

// ---------------- problem constants ----------------
#define BATCH   8192
#define D0      1024
#define D1      768
#define DIB     1024
#define KCAT    2816        // D0 + D1 + DIB
#define DOUT    1536
#define H1C     512
#define H2C     100
#define H2P     128         // padded N for layer-2 GEMM
#define NEXP    7

#define NC_BIG  (KCAT/64)   // 44 chunks
#define CEND0   15          // last chunk of x0 segment (1024/64 - 1)
#define CEND1   27          // last chunk of x1 segment (+768/64)

// ---------------- device scratch (no allocations allowed) ----------------
__device__ __half g_A  [(size_t)BATCH * KCAT];    // 46 MB  fp16 [x0|x1|xib] UNSCALED
__device__ __half g_B  [(size_t)DOUT  * KCAT];    // 8.7 MB [n][k] K-major, fp16
__device__ __half g_B1 [(size_t)H1C   * D0];      // 1 MB   rw1^T fp16
__device__ __half g_B2 [(size_t)H2P   * H1C];     // 128 KB rw2^T fp16 (padded)
__device__ __half g_h1h[BATCH * H1C];             // fp16 h1 (pre-BN)
__device__ float  g_h2 [BATCH * H2P];
__device__ float  g_stats1[2 * H1C];
__device__ float  g_stats2[2 * H2C];
__device__ float  g_w   [BATCH * 3];
__device__ float  g_bavg[3 * DOUT];
__device__ __half g_bnAa[H1C];                    // fused-BN scale (fp16)
__device__ __half g_bnAb[H1C];                    // fused-BN shift (fp16)

// ---------------- PTX helpers (base-target safe: sm_80+ ISA only) ------------
__device__ __forceinline__ uint32_t smem_u32(const void* p) {
    uint32_t a;
    asm("{ .reg .u64 t; cvta.to.shared.u64 t, %1; cvt.u32.u64 %0, t; }"
        : "=r"(a) : "l"(p));
    return a;
}
__device__ __forceinline__ void cp16(uint32_t saddr, const void* g) {
    asm volatile("cp.async.cg.shared.global [%0], [%1], 16;"
                 :: "r"(saddr), "l"(g));
}
__device__ __forceinline__ void ldsm4(uint32_t* r, uint32_t addr) {
    asm volatile("ldmatrix.sync.aligned.m8n8.x4.shared.b16 {%0,%1,%2,%3}, [%4];"
                 : "=r"(r[0]), "=r"(r[1]), "=r"(r[2]), "=r"(r[3]) : "r"(addr));
}
__device__ __forceinline__ void mma_f16(float* c, const uint32_t* a,
                                        uint32_t b0, uint32_t b1) {
    asm volatile(
        "mma.sync.aligned.m16n8k16.row.col.f32.f16.f16.f32 "
        "{%0,%1,%2,%3}, {%4,%5,%6,%7}, {%8,%9}, {%0,%1,%2,%3};"
        : "+f"(c[0]), "+f"(c[1]), "+f"(c[2]), "+f"(c[3])
        : "r"(a[0]), "r"(a[1]), "r"(a[2]), "r"(a[3]), "r"(b0), "r"(b1));
}

// ---------------- HMMA fp16 GEMM: C[M,N] = A[M,K] @ B[N,K]^T -----------------
// CTA 128x128, BK=64, 3-stage cp.async pipeline (96 KB smem, 2 CTA/SM),
// 4 warps 2(m) x 2(n), warp tile 64x64, mma.sync.m16n8k16.
// WSCALE: per-row MoE weighting via segment-boundary accumulator rescale.
// OUT16 : write __half output.
// STATS : per-column sum/sumsq atomically accumulated into `stats`.
// BNA   : apply per-k affine+ReLU to A fragments after ldmatrix (fused BN).
//         A frag k map (m16n8k16): regs 0,1 -> k=(lane&3)*2+{0,1};
//         regs 2,3 -> k+8; slab base = chunk*64 + ks*16.
#define STAGE_BYTES 32768               // A 16KB + B 16KB
#define HM_SMEM     (3 * STAGE_BYTES)   // 98304

template<bool OUT16, bool WSCALE, bool STATS, bool BNA>
__global__ void __launch_bounds__(128, 2)
hmma_gemm_kernel(const uint16_t* __restrict__ A,
                 const uint16_t* __restrict__ B,
                 float* __restrict__ C,
                 const float* __restrict__ W,
                 float* __restrict__ stats, int statsC,
                 const __half2* __restrict__ bnAa,
                 const __half2* __restrict__ bnAb,
                 int ldA, int ldB, int ldC, int nchunks) {
    extern __shared__ char smem[];
    const uint32_t sbase = smem_u32(smem);
    const int tid  = threadIdx.x;
    const int lane = tid & 31;
    const int wid  = tid >> 5;          // 0..3
    const int wm   = wid & 1;
    const int wn   = wid >> 1;
    const int bm   = blockIdx.y * 128;
    const int bn   = blockIdx.x * 128;
    const int erow = lane >> 2;
    const int ecol = (lane & 3) * 2;

    const int srow = tid >> 3;          // 0..15
    const int scol = tid & 7;           // 16B unit
    const uint32_t stoff = (uint32_t)srow * 128 +
                           (uint32_t)((scol ^ (srow & 7)) << 4);
    const uint16_t* gA0 = A + (size_t)(bm + srow) * ldA + scol * 8;
    const uint16_t* gB0 = B + (size_t)(bn + srow) * ldB + scol * 8;

    // per-row router-weight ratios (WSCALE only)
    float r01[4][2], r12[4][2], wfin[4][2];
    if (WSCALE) {
        #pragma unroll
        for (int mi = 0; mi < 4; mi++)
            #pragma unroll
            for (int h = 0; h < 2; h++) {
                int row = bm + wm * 64 + mi * 16 + erow + h * 8;
                float w0 = W[row * 3 + 0];
                float w1 = W[row * 3 + 1];
                float w2 = W[row * 3 + 2];
                r01[mi][h]  = w0 / w1;
                r12[mi][h]  = w1 / w2;
                wfin[mi][h] = w2;
            }
    }

    float acc[4][8][4];
    #pragma unroll
    for (int i = 0; i < 4; i++)
        #pragma unroll
        for (int j = 0; j < 8; j++)
            #pragma unroll
            for (int r = 0; r < 4; r++) acc[i][j][r] = 0.f;

    const int g  = lane >> 3;
    const int lr = lane & 7;
    const int rA  = wm * 64 + lr + (g & 1) * 8;
    const int chA = g >> 1;
    const int sA7 = rA & 7;
    const int rB  = wn * 64 + lr + (g >> 1) * 8;
    const int chB = g & 1;
    const int sB7 = rB & 7;

#define LOAD_STAGE(s, c_)                                                      \
    do {                                                                       \
        int k0_ = (c_) * 64;                                                   \
        uint32_t dA = sbase + (s) * STAGE_BYTES + stoff;                       \
        const uint16_t* ga = gA0 + k0_;                                        \
        _Pragma("unroll")                                                      \
        for (int i = 0; i < 8; i++)                                            \
            cp16(dA + i * 2048, ga + (size_t)i * 16 * ldA);                    \
        uint32_t dB = sbase + (s) * STAGE_BYTES + 16384 + stoff;               \
        const uint16_t* gb = gB0 + k0_;                                        \
        _Pragma("unroll")                                                      \
        for (int i = 0; i < 8; i++)                                            \
            cp16(dB + i * 2048, gb + (size_t)i * 16 * ldB);                    \
        asm volatile("cp.async.commit_group;" ::: "memory");                   \
    } while (0)

    LOAD_STAGE(0, 0);
    LOAD_STAGE(1, 1);

    for (int c = 0; c < nchunks; c++) {
        if (c + 2 < nchunks) {
            asm volatile("cp.async.wait_group 1;" ::: "memory");
        } else {
            asm volatile("cp.async.wait_group 0;" ::: "memory");
        }
        __syncthreads();
        if (c + 2 < nchunks) {
            int s2 = (c + 2) % 3;
            LOAD_STAGE(s2, c + 2);
        }

        const uint32_t aB = sbase + (c % 3) * STAGE_BYTES;
        const uint32_t bB = aB + 16384;
        #pragma unroll
        for (int ks = 0; ks < 4; ks++) {
            __half2 al_lo, be_lo, al_hi, be_hi;
            if (BNA) {
                int kk = (c * 64 + ks * 16 + (lane & 3) * 2) >> 1;
                al_lo = bnAa[kk];     be_lo = bnAb[kk];
                al_hi = bnAa[kk + 4]; be_hi = bnAb[kk + 4];
            }
            uint32_t a[4][4];
            #pragma unroll
            for (int mi = 0; mi < 4; mi++) {
                uint32_t addr = aB + (uint32_t)(rA + mi * 16) * 128 +
                                (uint32_t)(((2 * ks + chA) ^ sA7) << 4);
                ldsm4(a[mi], addr);
                if (BNA) {
                    const __half2 z = __floats2half2_rn(0.f, 0.f);
                    __half2* ah = reinterpret_cast<__half2*>(a[mi]);
                    ah[0] = __hmax2(__hfma2(ah[0], al_lo, be_lo), z);
                    ah[1] = __hmax2(__hfma2(ah[1], al_lo, be_lo), z);
                    ah[2] = __hmax2(__hfma2(ah[2], al_hi, be_hi), z);
                    ah[3] = __hmax2(__hfma2(ah[3], al_hi, be_hi), z);
                }
            }
            uint32_t b[4][4];
            #pragma unroll
            for (int ng = 0; ng < 4; ng++) {
                uint32_t addr = bB + (uint32_t)(rB + ng * 16) * 128 +
                                (uint32_t)(((2 * ks + chB) ^ sB7) << 4);
                ldsm4(b[ng], addr);
            }
            #pragma unroll
            for (int mi = 0; mi < 4; mi++)
                #pragma unroll
                for (int ni = 0; ni < 8; ni++)
                    mma_f16(acc[mi][ni], a[mi],
                            b[ni >> 1][(ni & 1) * 2],
                            b[ni >> 1][(ni & 1) * 2 + 1]);
        }
        if (WSCALE && (c == CEND0 || c == CEND1)) {
            #pragma unroll
            for (int mi = 0; mi < 4; mi++)
                #pragma unroll
                for (int ni = 0; ni < 8; ni++)
                    #pragma unroll
                    for (int r = 0; r < 4; r++) {
                        float rt = (c == CEND0) ? r01[mi][r >> 1]
                                                : r12[mi][r >> 1];
                        acc[mi][ni][r] *= rt;
                    }
        }
        // no trailing sync: slot (c+2)%3 overwritten only after next-iter sync
    }
#undef LOAD_STAGE

    // fused BN batch-stats: per-column sum/sumsq over this CTA's 128 rows
    if (STATS) {
        #pragma unroll
        for (int ni = 0; ni < 8; ni++) {
            float s0 = 0.f, s1 = 0.f, q0 = 0.f, q1 = 0.f;
            #pragma unroll
            for (int mi = 0; mi < 4; mi++)
                #pragma unroll
                for (int r = 0; r < 4; r++) {
                    float v = acc[mi][ni][r];
                    if (r & 1) { s1 += v; q1 = fmaf(v, v, q1); }
                    else       { s0 += v; q0 = fmaf(v, v, q0); }
                }
            #pragma unroll
            for (int o = 16; o >= 4; o >>= 1) {
                s0 += __shfl_down_sync(0xffffffffu, s0, o);
                s1 += __shfl_down_sync(0xffffffffu, s1, o);
                q0 += __shfl_down_sync(0xffffffffu, q0, o);
                q1 += __shfl_down_sync(0xffffffffu, q1, o);
            }
            if (lane < 4) {
                int col = bn + wn * 64 + ni * 8 + lane * 2;
                if (col < statsC) {
                    atomicAdd(&stats[col], s0);
                    atomicAdd(&stats[statsC + col], q0);
                }
                if (col + 1 < statsC) {
                    atomicAdd(&stats[col + 1], s1);
                    atomicAdd(&stats[statsC + col + 1], q1);
                }
            }
        }
    }

    #pragma unroll
    for (int mi = 0; mi < 4; mi++) {
        int row = bm + wm * 64 + mi * 16 + erow;
        #pragma unroll
        for (int ni = 0; ni < 8; ni++) {
            int col = bn + wn * 64 + ni * 8 + ecol;
            float s0 = WSCALE ? wfin[mi][0] : 1.f;
            float s1 = WSCALE ? wfin[mi][1] : 1.f;
            if (OUT16) {
                __half* C16 = reinterpret_cast<__half*>(C);
                __half2 v0 = __floats2half2_rn(acc[mi][ni][0] * s0,
                                               acc[mi][ni][1] * s0);
                __half2 v1 = __floats2half2_rn(acc[mi][ni][2] * s1,
                                               acc[mi][ni][3] * s1);
                *reinterpret_cast<__half2*>(C16 + (size_t)row * ldC + col) = v0;
                *reinterpret_cast<__half2*>(C16 + (size_t)(row + 8) * ldC + col) = v1;
            } else {
                float2 v0 = make_float2(acc[mi][ni][0] * s0, acc[mi][ni][1] * s0);
                float2 v1 = make_float2(acc[mi][ni][2] * s1, acc[mi][ni][3] * s1);
                *reinterpret_cast<float2*>(C + (size_t)row * ldC + col) = v0;
                *reinterpret_cast<float2*>(C + (size_t)(row + 8) * ldC + col) = v1;
            }
        }
    }
}

// ---------------- conversions ----------------
// A: plain fp16 of columns [c4_begin*4, (c4_begin+c4_count)*4) of [x0|x1|xib]
__global__ void convert_A_kernel(const float* __restrict__ x0,
                                 const float* __restrict__ x1,
                                 const float* __restrict__ xib,
                                 int c4_begin, int c4_count) {
    const int total = BATCH * c4_count;
    for (int idx = blockIdx.x * blockDim.x + threadIdx.x; idx < total;
         idx += gridDim.x * blockDim.x) {
        int b = idx / c4_count;
        int c = (c4_begin + (idx - b * c4_count)) * 4;
        float4 v;
        if (c < D0)
            v = *reinterpret_cast<const float4*>(x0 + (size_t)b * D0 + c);
        else if (c < D0 + D1)
            v = *reinterpret_cast<const float4*>(x1 + (size_t)b * D1 + (c - D0));
        else
            v = *reinterpret_cast<const float4*>(xib + (size_t)b * DIB + (c - D0 - D1));
        __half2 h0 = __floats2half2_rn(v.x, v.y);
        __half2 h1 = __floats2half2_rn(v.z, v.w);
        uint2 u;
        u.x = *reinterpret_cast<uint32_t*>(&h0);
        u.y = *reinterpret_cast<uint32_t*>(&h1);
        *reinterpret_cast<uint2*>(g_A + (size_t)b * KCAT + c) = u;
    }
}

// B for big GEMM: average 7 experts, transpose to [n][k], fp16
__global__ void convert_B_kernel(const float* __restrict__ pW0,
                                 const float* __restrict__ pW1,
                                 const float* __restrict__ pWib) {
    __shared__ float t[32][33];
    const int k0 = blockIdx.x * 32;
    const int n0 = blockIdx.y * 32;
    const int tx = threadIdx.x, ty = threadIdx.y;
    for (int kl = ty; kl < 32; kl += 8) {
        int k = k0 + kl;
        const float* src; int lr, ld;
        if (k < D0)            { src = pW0;  lr = k;            ld = D0;  }
        else if (k < D0 + D1)  { src = pW1;  lr = k - D0;       ld = D1;  }
        else                   { src = pWib; lr = k - D0 - D1;  ld = DIB; }
        const float* p = src + (size_t)lr * DOUT + n0 + tx;
        const size_t es = (size_t)ld * DOUT;
        float s = 0.f;
        #pragma unroll
        for (int e = 0; e < NEXP; e++) s += p[(size_t)e * es];
        t[kl][tx] = s * (1.0f / 7.0f);
    }
    __syncthreads();
    for (int nl = ty; nl < 32; nl += 8)
        g_B[(size_t)(n0 + nl) * KCAT + k0 + tx] = __float2half(t[tx][nl]);
}

// merged: B1 = rw1^T (512 tiles) then B2 = rw2^T padded (64 tiles)
#define B1_TILES ((D0 / 32) * (H1C / 32))   // 512
#define B2_TILES ((H1C / 32) * (H2P / 32))  // 64
__global__ void convert_B12_kernel(const float* __restrict__ rw1,
                                   const float* __restrict__ rw2) {
    __shared__ float t[32][33];
    const int tx = threadIdx.x, ty = threadIdx.y;
    int bx = blockIdx.x;
    if (bx < B1_TILES) {
        const int k0 = (bx % (D0 / 32)) * 32;
        const int n0 = (bx / (D0 / 32)) * 32;
        for (int kl = ty; kl < 32; kl += 8)
            t[kl][tx] = rw1[(size_t)(k0 + kl) * H1C + n0 + tx];
        __syncthreads();
        for (int nl = ty; nl < 32; nl += 8)
            g_B1[(size_t)(n0 + nl) * D0 + k0 + tx] = __float2half(t[tx][nl]);
    } else {
        bx -= B1_TILES;
        const int k0 = (bx % (H1C / 32)) * 32;
        const int n0 = (bx / (H1C / 32)) * 32;
        for (int kl = ty; kl < 32; kl += 8) {
            int n = n0 + tx;
            t[kl][tx] = (n < H2C) ? rw2[(size_t)(k0 + kl) * H2C + n] : 0.f;
        }
        __syncthreads();
        for (int nl = ty; nl < 32; nl += 8)
            g_B2[(size_t)(n0 + nl) * H1C + k0 + tx] = __float2half(t[tx][nl]);
    }
}

// ---------------- misc small kernels ----------------
// merged: zero BN-stat accumulators + average projection biases
__global__ void init_kernel(const float* __restrict__ pb0,
                            const float* __restrict__ pb1,
                            const float* __restrict__ pbib) {
    int i = blockIdx.x * blockDim.x + threadIdx.x;
    if (i < 2 * H1C) g_stats1[i] = 0.0f;
    if (i < 2 * H2C) g_stats2[i] = 0.0f;
    if (i < 3 * DOUT) {
        int s = i / DOUT, n = i - s * DOUT;
        const float* pb = (s == 0) ? pb0 : (s == 1) ? pb1 : pbib;
        float a = 0.f;
        #pragma unroll
        for (int e = 0; e < NEXP; e++) a += pb[e * DOUT + n];
        g_bavg[i] = a * (1.0f / 7.0f);
    }
}

// fold h1 batch stats + gamma/beta into per-column fp16 affine (alpha, beta)
__global__ void bn_prep_kernel(const float* __restrict__ gamma,
                               const float* __restrict__ beta) {
    int c = blockIdx.x * blockDim.x + threadIdx.x;
    if (c >= H1C) return;
    const float invB = 1.0f / (float)BATCH;
    float mean = g_stats1[c] * invB;
    float var  = g_stats1[H1C + c] * invB - mean * mean;
    float a = gamma[c] * rsqrtf(var + 1e-5f);
    float b = beta[c] - a * mean;
    g_bnAa[c] = __float2half(a);
    g_bnAb[c] = __float2half(b);
}

__global__ void router_final_kernel(const float* __restrict__ rg2,
                                    const float* __restrict__ rbt2,
                                    const float* __restrict__ rw3,
                                    const float* __restrict__ rb3) {
    int warp = (blockIdx.x * blockDim.x + threadIdx.x) >> 5;
    int lane = threadIdx.x & 31;
    if (warp >= BATCH) return;
    const float invB = 1.0f / (float)BATCH;
    float d0 = 0.f, d1 = 0.f, d2 = 0.f;
    for (int c = lane; c < H2C; c += 32) {
        float mean = g_stats2[c] * invB;
        float var  = g_stats2[H2C + c] * invB - mean * mean;
        float v = g_h2[(size_t)warp * H2P + c];
        v = rg2[c] * (v - mean) * rsqrtf(var + 1e-5f) + rbt2[c];
        v = tanhf(v);
        d0 = fmaf(v, rw3[c * 3 + 0], d0);
        d1 = fmaf(v, rw3[c * 3 + 1], d1);
        d2 = fmaf(v, rw3[c * 3 + 2], d2);
    }
    #pragma unroll
    for (int o = 16; o > 0; o >>= 1) {
        d0 += __shfl_down_sync(0xffffffffu, d0, o);
        d1 += __shfl_down_sync(0xffffffffu, d1, o);
        d2 += __shfl_down_sync(0xffffffffu, d2, o);
    }
    if (lane == 0) {
        float l0 = 1.f / (1.f + __expf(-(d0 + rb3[0])));
        float l1 = 1.f / (1.f + __expf(-(d1 + rb3[1])));
        float l2 = 1.f / (1.f + __expf(-(d2 + rb3[2])));
        float mx = fmaxf(l0, fmaxf(l1, l2));
        float e0 = __expf(l0 - mx), e1 = __expf(l1 - mx), e2 = __expf(l2 - mx);
        float inv = 1.f / (e0 + e1 + e2);
        g_w[warp * 3 + 0] = e0 * inv;
        g_w[warp * 3 + 1] = e1 * inv;
        g_w[warp * 3 + 2] = e2 * inv;
    }
}

__global__ void normalize_rows_kernel(float* __restrict__ out) {
    int b = blockIdx.x;
    int t = threadIdx.x;
    float w0 = g_w[b * 3 + 0], w1 = g_w[b * 3 + 1], w2 = g_w[b * 3 + 2];
    float vals[6];
    float ss = 0.f;
    #pragma unroll
    for (int j = 0; j < 6; j++) {
        int n = t + j * 256;
        float v = out[(size_t)b * DOUT + n];
        v += w0 * g_bavg[n] + w1 * g_bavg[DOUT + n] + w2 * g_bavg[2 * DOUT + n];
        vals[j] = v;
        ss = fmaf(v, v, ss);
    }
    __shared__ float red[256];
    red[t] = ss;
    __syncthreads();
    #pragma unroll
    for (int s2 = 128; s2 > 0; s2 >>= 1) {
        if (t < s2) red[t] += red[t + s2];
        __syncthreads();
    }
    float inv = 1.f / fmaxf(sqrtf(red[0]), 1e-12f);
    #pragma unroll
    for (int j = 0; j < 6; j++)
        out[(size_t)b * DOUT + t + j * 256] = vals[j] * inv;
}

// ---------------- launch ----------------
extern "C" void kernel_launch(void* const* d_in, const int* in_sizes, int n_in,
                              void* d_out, int out_size) {
    const float* x0   = (const float*)d_in[0];
    const float* x1   = (const float*)d_in[1];
    const float* xib  = (const float*)d_in[2];
    const float* pW0  = (const float*)d_in[3];
    const float* pb0  = (const float*)d_in[4];
    const float* pW1  = (const float*)d_in[5];
    const float* pb1  = (const float*)d_in[6];
    const float* pWib = (const float*)d_in[7];
    const float* pbib = (const float*)d_in[8];
    const float* rw1  = (const float*)d_in[9];
    // rb1 (d_in[10]) cancels exactly under batch-norm — skipped
    const float* rg1  = (const float*)d_in[11];
    const float* rbt1 = (const float*)d_in[12];
    const float* rw2  = (const float*)d_in[13];
    // rb2 (d_in[14]) also cancels under batch-norm — skipped
    const float* rg2  = (const float*)d_in[15];
    const float* rbt2 = (const float*)d_in[16];
    const float* rw3  = (const float*)d_in[17];
    const float* rb3  = (const float*)d_in[18];
    float* out = (float*)d_out;
    (void)in_sizes; (void)n_in; (void)out_size;

    void *a_p, *b_p, *b1_p, *b2_p, *h1h_p, *h2_p, *s1_p, *s2_p, *w_p;
    void *bna_p, *bnb_p;
    cudaGetSymbolAddress(&a_p,   g_A);
    cudaGetSymbolAddress(&b_p,   g_B);
    cudaGetSymbolAddress(&b1_p,  g_B1);
    cudaGetSymbolAddress(&b2_p,  g_B2);
    cudaGetSymbolAddress(&h1h_p, g_h1h);
    cudaGetSymbolAddress(&h2_p,  g_h2);
    cudaGetSymbolAddress(&s1_p,  g_stats1);
    cudaGetSymbolAddress(&s2_p,  g_stats2);
    cudaGetSymbolAddress(&w_p,   g_w);
    cudaGetSymbolAddress(&bna_p, g_bnAa);
    cudaGetSymbolAddress(&bnb_p, g_bnAb);
    const uint16_t* Ab  = (const uint16_t*)a_p;
    const uint16_t* Bb  = (const uint16_t*)b_p;
    const uint16_t* B1h = (const uint16_t*)b1_p;
    const uint16_t* B2h = (const uint16_t*)b2_p;
    const uint16_t* H1u = (const uint16_t*)h1h_p;
    float* h1f = (float*)h1h_p;   // reinterpreted for OUT16 GEMM param
    float* h2  = (float*)h2_p;
    float* st1 = (float*)s1_p;
    float* st2 = (float*)s2_p;
    const float* Wp = (const float*)w_p;
    const __half2* bnAa = (const __half2*)bna_p;
    const __half2* bnAb = (const __half2*)bnb_p;

    cudaFuncSetAttribute((const void*)hmma_gemm_kernel<true, false, true, false>,
                         cudaFuncAttributeMaxDynamicSharedMemorySize, HM_SMEM);
    cudaFuncSetAttribute((const void*)hmma_gemm_kernel<false, false, true, true>,
                         cudaFuncAttributeMaxDynamicSharedMemorySize, HM_SMEM);
    cudaFuncSetAttribute((const void*)hmma_gemm_kernel<false, true, false, false>,
                         cudaFuncAttributeMaxDynamicSharedMemorySize, HM_SMEM);

    // side stream + fork/join events (created once; identical work every call)
    static cudaStream_t sB = nullptr;
    static cudaEvent_t  eFork = nullptr, eJoin = nullptr;
    if (sB == nullptr) {
        cudaStreamCreateWithFlags(&sB, cudaStreamNonBlocking);
        cudaEventCreateWithFlags(&eFork, cudaEventDisableTiming);
        cudaEventCreateWithFlags(&eJoin, cudaEventDisableTiming);
    }

    // fork immediately: side stream handles work not needed until the big GEMM
    cudaEventRecord(eFork, 0);
    cudaStreamWaitEvent(sB, eFork, 0);
    convert_A_kernel<<<8192, 256, 0, sB>>>(x0, x1, xib,
                                           D0 / 4, (KCAT - D0) / 4);  // x1|xib
    convert_B_kernel<<<dim3(KCAT / 32, DOUT / 32), dim3(32, 8), 0, sB>>>(
        pW0, pW1, pWib);
    cudaEventRecord(eJoin, sB);

    // main stream: router-critical work only
    init_kernel<<<(3 * DOUT + 255) / 256, 256>>>(pb0, pb1, pbib);
    convert_A_kernel <<<4096, 256>>>(x0, x1, xib, 0, D0 / 4);         // x0 only
    convert_B12_kernel<<<B1_TILES + B2_TILES, dim3(32, 8)>>>(rw1, rw2);

    // router layer 1 (fp16 HMMA, fp16 out, fused column stats): h1 = x0 @ rw1
    hmma_gemm_kernel<true, false, true, false>
        <<<dim3(H1C / 128, BATCH / 128), 128, HM_SMEM>>>(
        Ab, B1h, h1f, nullptr, st1, H1C, nullptr, nullptr,
        KCAT, D0, H1C, D0 / 64);
    bn_prep_kernel<<<2, 256>>>(rg1, rbt1);

    // router layer 2 (fp16 HMMA, BN+ReLU fused on A frags, fused stats)
    hmma_gemm_kernel<false, false, true, true>
        <<<dim3(H2P / 128, BATCH / 128), 128, HM_SMEM>>>(
        H1u, B2h, h2, nullptr, st2, H2C, bnAa, bnAb,
        H1C, H1C, H2P, H1C / 64);
    router_final_kernel<<<BATCH * 32 / 256, 256>>>(rg2, rbt2, rw3, rb3);

    // join: big GEMM needs full g_A and g_B
    cudaStreamWaitEvent(0, eJoin, 0);

    // big GEMM (plain fp16) with per-row MoE weighting in the epilogue
    hmma_gemm_kernel<false, true, false, false>
        <<<dim3(DOUT / 128, BATCH / 128), 128, HM_SMEM>>>(
        Ab, Bb, out, Wp, nullptr, 0, nullptr, nullptr,
        KCAT, KCAT, DOUT, NC_BIG);

    normalize_rows_kernel<<<BATCH, 256>>>(out);
}